// round 6
// baseline (speedup 1.0000x reference)
#include <cuda_runtime.h>
#include <cuda_bf16.h>
#include <cstdint>

#define BATCH 4
#define CTX   2048
#define NEMB  1024
#define NH    16
#define HS    64
#define DM    1024
#define FF    4096
#define MTOT  (BATCH*CTX)   // 8192

typedef __nv_bfloat16 bf16;

// ================= scratch =================
__device__ bf16 g_qhi[(size_t)BATCH*NH*CTX*HS], g_qlo[(size_t)BATCH*NH*CTX*HS];
__device__ bf16 g_khi[(size_t)BATCH*NH*CTX*HS], g_klo[(size_t)BATCH*NH*CTX*HS];
__device__ bf16 g_vhi[(size_t)BATCH*NH*CTX*HS], g_vlo[(size_t)BATCH*NH*CTX*HS];
__device__ bf16 g_xhi[(size_t)MTOT*NEMB];
__device__ uint8_t g_x8h[(size_t)MTOT*NEMB], g_x8l[(size_t)MTOT*NEMB];
__device__ bf16 g_bqhi[(size_t)3*DM*NEMB];
__device__ uint8_t g_bq8h[(size_t)3*DM*NEMB], g_bq8l[(size_t)3*DM*NEMB];
__device__ bf16 g_ahi[(size_t)MTOT*DM];
__device__ uint8_t g_a8h[(size_t)MTOT*DM], g_a8l[(size_t)MTOT*DM];
__device__ bf16 g_w1hi[(size_t)FF*DM];
__device__ uint8_t g_w18h[(size_t)FF*DM], g_w18l[(size_t)FF*DM];
__device__ bf16 g_hhi[(size_t)MTOT*FF];
__device__ uint8_t g_h8h[(size_t)MTOT*FF], g_h8l[(size_t)MTOT*FF];
__device__ bf16 g_w2hi[(size_t)DM*FF];
__device__ uint8_t g_w28h[(size_t)DM*FF], g_w28l[(size_t)DM*FF];

__device__ __forceinline__ uint32_t pack2bf(float a, float b) {
    __nv_bfloat162 p(__float2bfloat16(a), __float2bfloat16(b));
    return *reinterpret_cast<uint32_t*>(&p);
}
__device__ __forceinline__ uint32_t packlo2(float a, float b) {
    float ra = __bfloat162float(__float2bfloat16(a));
    float rb = __bfloat162float(__float2bfloat16(b));
    return pack2bf(a - ra, b - rb);
}
// low byte = first element
__device__ __forceinline__ uint16_t pack_e4m3x2(float lo_elem, float hi_elem) {
    uint16_t r;
    asm("cvt.rn.satfinite.e4m3x2.f32 %0, %1, %2;" : "=h"(r) : "f"(hi_elem), "f"(lo_elem));
    return r;
}
__device__ __forceinline__ uint8_t e4m3_1(float v) {
    return (uint8_t)(pack_e4m3x2(v, 0.f) & 0xff);
}
__device__ __forceinline__ uint32_t smem_u32(const void* p) {
    uint32_t a;
    asm("{ .reg .u64 t; cvta.to.shared.u64 t, %1; cvt.u32.u64 %0, t; }" : "=r"(a) : "l"(p));
    return a;
}
__device__ __forceinline__ void cp16(uint32_t dst, const void* src) {
    asm volatile("cp.async.cg.shared.global [%0], [%1], 16;" :: "r"(dst), "l"(src));
}
#define CP_COMMIT() asm volatile("cp.async.commit_group;" ::: "memory")
#define CP_WAIT(n)  asm volatile("cp.async.wait_group %0;" :: "n"(n) : "memory")

__device__ __forceinline__ void ldm4(uint32_t* r, uint32_t addr) {
    asm volatile("ldmatrix.sync.aligned.m8n8.x4.shared.b16 {%0,%1,%2,%3}, [%4];"
        : "=r"(r[0]), "=r"(r[1]), "=r"(r[2]), "=r"(r[3]) : "r"(addr));
}
__device__ __forceinline__ void ldm4t(uint32_t* r, uint32_t addr) {
    asm volatile("ldmatrix.sync.aligned.m8n8.x4.trans.shared.b16 {%0,%1,%2,%3}, [%4];"
        : "=r"(r[0]), "=r"(r[1]), "=r"(r[2]), "=r"(r[3]) : "r"(addr));
}
__device__ __forceinline__ void mma_bf16(float* d, const uint32_t* a, const uint32_t* b) {
    asm volatile("mma.sync.aligned.m16n8k16.row.col.f32.bf16.bf16.f32 "
        "{%0,%1,%2,%3}, {%4,%5,%6,%7}, {%8,%9}, {%0,%1,%2,%3};"
        : "+f"(d[0]), "+f"(d[1]), "+f"(d[2]), "+f"(d[3])
        : "r"(a[0]), "r"(a[1]), "r"(a[2]), "r"(a[3]), "r"(b[0]), "r"(b[1]));
}
__device__ __forceinline__ void mma_fp8(float* d, const uint32_t* a, uint32_t b0, uint32_t b1) {
    asm volatile("mma.sync.aligned.m16n8k32.row.col.f32.e4m3.e4m3.f32 "
        "{%0,%1,%2,%3}, {%4,%5,%6,%7}, {%8,%9}, {%0,%1,%2,%3};"
        : "+f"(d[0]), "+f"(d[1]), "+f"(d[2]), "+f"(d[3])
        : "r"(a[0]), "r"(a[1]), "r"(a[2]), "r"(a[3]), "r"(b0), "r"(b1));
}

// ================= split / transpose kernels =================
__global__ __launch_bounds__(256) void split_x_kernel(const float* __restrict__ x,
                                                      bf16* __restrict__ hi,
                                                      uint8_t* __restrict__ f8h,
                                                      uint8_t* __restrict__ f8l)
{
    size_t i = (size_t)blockIdx.x * 256 + threadIdx.x;
    float4 v = ((const float4*)x)[i];
    float h0 = __bfloat162float(__float2bfloat16(v.x));
    float h1 = __bfloat162float(__float2bfloat16(v.y));
    float h2 = __bfloat162float(__float2bfloat16(v.z));
    float h3 = __bfloat162float(__float2bfloat16(v.w));
    ((uint2*)hi)[i] = make_uint2(pack2bf(v.x, v.y), pack2bf(v.z, v.w));
    uint32_t uh = (uint32_t)pack_e4m3x2(h0, h1) | ((uint32_t)pack_e4m3x2(h2, h3) << 16);
    uint32_t ul = (uint32_t)pack_e4m3x2((v.x - h0) * 256.f, (v.y - h1) * 256.f)
                | ((uint32_t)pack_e4m3x2((v.z - h2) * 256.f, (v.w - h3) * 256.f) << 16);
    ((uint32_t*)f8h)[i] = uh;
    ((uint32_t*)f8l)[i] = ul;
}

// W [K,N] row-major -> out [N,K] bf16 hi + fp8 hi/lo
__global__ __launch_bounds__(256) void transpose_split(const float* __restrict__ W,
                                                       bf16* __restrict__ hi,
                                                       uint8_t* __restrict__ f8h,
                                                       uint8_t* __restrict__ f8l,
                                                       int K, int N)
{
    __shared__ float t[32][33];
    int n0 = blockIdx.x * 32, k0 = blockIdx.y * 32;
    int tx = threadIdx.x, ty = threadIdx.y;
#pragma unroll
    for (int i = ty; i < 32; i += 8)
        t[i][tx] = W[(size_t)(k0 + i) * N + n0 + tx];
    __syncthreads();
#pragma unroll
    for (int i = ty; i < 32; i += 8) {
        float v = t[tx][i];
        bf16 h = __float2bfloat16(v);
        float hf = __bfloat162float(h);
        size_t o = (size_t)(n0 + i) * K + k0 + tx;
        hi[o] = h;
        f8h[o] = e4m3_1(hf);
        f8l[o] = e4m3_1((v - hf) * 256.f);
    }
}

// Wq/Wk/Wv [H,C,D] -> bqkv[n = sel*1024 + h*64 + d][k = c]
__global__ __launch_bounds__(256) void qkv_transpose_split(const float* __restrict__ Wq,
                                                           const float* __restrict__ Wk,
                                                           const float* __restrict__ Wv,
                                                           bf16* __restrict__ hi,
                                                           uint8_t* __restrict__ f8h,
                                                           uint8_t* __restrict__ f8l)
{
    __shared__ float t[32][33];
    int sel = blockIdx.z >> 4, h = blockIdx.z & 15;
    const float* W = (sel == 0 ? Wq : sel == 1 ? Wk : Wv) + (size_t)h * NEMB * HS;
    int c0 = blockIdx.x * 32, d0 = blockIdx.y * 32;
    int tx = threadIdx.x, ty = threadIdx.y;
#pragma unroll
    for (int i = ty; i < 32; i += 8)
        t[i][tx] = W[(size_t)(c0 + i) * HS + d0 + tx];
    __syncthreads();
    int nbase = sel * DM + h * HS + d0;
#pragma unroll
    for (int i = ty; i < 32; i += 8) {
        float v = t[tx][i];
        bf16 hh = __float2bfloat16(v);
        float hf = __bfloat162float(hh);
        size_t o = (size_t)(nbase + i) * NEMB + c0 + tx;
        hi[o] = hh;
        f8h[o] = e4m3_1(hf);
        f8l[o] = e4m3_1((v - hf) * 256.f);
    }
}

// ================= mixed bf16/fp8 split GEMM =================
// D = Ahi*Bhi (bf16 mma) + [A8h*B8l' + A8l'*B8h]/256 (fp8 mma, lo pre-scaled x256)
// MODE 0: scatter split bf16 -> q/k/v [B,H,T,D] hi/lo
// MODE 1: +bias, write bf16 hi + fp8 hi/lo (FFN1 -> h)
// MODE 2: +bias, relu, write fp32 (FFN2 -> out)
#define ROWB    80
#define ROW8    48
#define TB_BF   (128*ROWB)  // 10240
#define TB_F8   (128*ROW8)  // 6144
#define OFF_AH  0
#define OFF_BH  (TB_BF)
#define OFF_A8H (2*TB_BF)
#define OFF_A8L (2*TB_BF + TB_F8)
#define OFF_B8H (2*TB_BF + 2*TB_F8)
#define OFF_B8L (2*TB_BF + 3*TB_F8)
#define STAGE_B (2*TB_BF + 4*TB_F8)   // 45056
#define NSTAGE  3
#define GEMM_SMEM (NSTAGE*STAGE_B)    // 135168

template <int MODE>
__global__ __launch_bounds__(256, 1)
void gemm_split(const bf16* __restrict__ Ahi,
                const uint8_t* __restrict__ A8h, const uint8_t* __restrict__ A8l,
                const bf16* __restrict__ Bhi,
                const uint8_t* __restrict__ B8h, const uint8_t* __restrict__ B8l,
                const float* __restrict__ bias,
                float* __restrict__ out_f, bf16* __restrict__ out_hi,
                uint8_t* __restrict__ o8h, uint8_t* __restrict__ o8l,
                bf16* __restrict__ qhi, bf16* __restrict__ qlo,
                bf16* __restrict__ khi, bf16* __restrict__ klo,
                bf16* __restrict__ vhi, bf16* __restrict__ vlo,
                int N, int K)
{
    extern __shared__ char smem[];
    uint32_t sb = smem_u32(smem);

    int tid = threadIdx.x, wid = tid >> 5, lid = tid & 31;
    int wm = wid >> 2, wn = wid & 3;          // warp tile 64(M) x 32(N)
    int bx = blockIdx.x, by = blockIdx.y;

    const bf16* aH = Ahi + (size_t)by * 128 * K;
    const bf16* bH = Bhi + (size_t)bx * 128 * K;
    const uint8_t* a8H = A8h + (size_t)by * 128 * K;
    const uint8_t* a8L = A8l + (size_t)by * 128 * K;
    const uint8_t* b8H = B8h + (size_t)bx * 128 * K;
    const uint8_t* b8L = B8l + (size_t)bx * 128 * K;

    float acc[4][4][4], acc2[4][4][4];
#pragma unroll
    for (int i = 0; i < 4; i++)
#pragma unroll
        for (int j = 0; j < 4; j++)
#pragma unroll
            for (int l = 0; l < 4; l++) { acc[i][j][l] = 0.f; acc2[i][j][l] = 0.f; }

    int ITERS = K >> 5;

#define ISSUE(st, k0) do {                                                        \
        uint32_t _b = sb + (st) * STAGE_B;                                        \
        { int _c = tid; int _r = _c >> 2, _q = _c & 3;                            \
          cp16(_b + OFF_AH + _r * ROWB + _q * 16, aH + (size_t)_r * K + (k0) + _q * 8); \
          cp16(_b + OFF_BH + _r * ROWB + _q * 16, bH + (size_t)_r * K + (k0) + _q * 8); } \
        { int _c = tid + 256; int _r = _c >> 2, _q = _c & 3;                      \
          cp16(_b + OFF_AH + _r * ROWB + _q * 16, aH + (size_t)_r * K + (k0) + _q * 8); \
          cp16(_b + OFF_BH + _r * ROWB + _q * 16, bH + (size_t)_r * K + (k0) + _q * 8); } \
        { int _r = tid >> 1, _hf = tid & 1;                                       \
          uint32_t _so = _r * ROW8 + _hf * 16;                                    \
          size_t _go = (size_t)_r * K + (k0) + _hf * 16;                          \
          cp16(_b + OFF_A8H + _so, a8H + _go);                                    \
          cp16(_b + OFF_A8L + _so, a8L + _go);                                    \
          cp16(_b + OFF_B8H + _so, b8H + _go);                                    \
          cp16(_b + OFF_B8L + _so, b8L + _go); }                                  \
    } while (0)

    ISSUE(0, 0);  CP_COMMIT();
    ISSUE(1, 32); CP_COMMIT();

    int g = lid >> 3, rr = lid & 7;
    uint32_t a_row_off = (uint32_t)(((g & 1) * 8 + rr) * ROWB + (g >> 1) * 16);
    uint32_t b_row_off = (uint32_t)(((g >> 1) * 8 + rr) * ROWB + (g & 1) * 16);
    uint32_t a8_off    = (uint32_t)(((g & 1) * 8 + rr) * ROW8 + (g >> 1) * 16);
    uint32_t b8_off    = (uint32_t)(((g >> 1) * 8 + rr) * ROW8 + (g & 1) * 16);

    for (int it = 0; it < ITERS; it++) {
        int pre = it + NSTAGE - 1;
        if (pre < ITERS) { ISSUE(pre % NSTAGE, pre * 32); }
        CP_COMMIT();
        CP_WAIT(NSTAGE - 2);
        __syncthreads();

        uint32_t base = sb + (it % NSTAGE) * STAGE_B;
        // bf16 main: Ahi * Bhi
#pragma unroll
        for (int ks = 0; ks < 2; ks++) {
            uint32_t ah[4][4], bh2[2][4];
#pragma unroll
            for (int mi = 0; mi < 4; mi++)
                ldm4(ah[mi], base + OFF_AH + (uint32_t)((wm * 64 + mi * 16) * ROWB + ks * 32) + a_row_off);
#pragma unroll
            for (int p = 0; p < 2; p++)
                ldm4(bh2[p], base + OFF_BH + (uint32_t)((wn * 32 + p * 16) * ROWB + ks * 32) + b_row_off);
#pragma unroll
            for (int mi = 0; mi < 4; mi++)
#pragma unroll
                for (int ni = 0; ni < 4; ni++)
                    mma_bf16(acc[mi][ni], ah[mi], &bh2[ni >> 1][(ni & 1) * 2]);
        }
        // fp8 cross: A8h*B8l + A8l*B8h  (k32)
        {
            uint32_t a8h[4][4], a8l[4][4], b8h2[2][4], b8l2[2][4];
#pragma unroll
            for (int mi = 0; mi < 4; mi++) {
                uint32_t off = (uint32_t)((wm * 64 + mi * 16) * ROW8) + a8_off;
                ldm4(a8h[mi], base + OFF_A8H + off);
                ldm4(a8l[mi], base + OFF_A8L + off);
            }
#pragma unroll
            for (int p = 0; p < 2; p++) {
                uint32_t off = (uint32_t)((wn * 32 + p * 16) * ROW8) + b8_off;
                ldm4(b8h2[p], base + OFF_B8H + off);
                ldm4(b8l2[p], base + OFF_B8L + off);
            }
#pragma unroll
            for (int mi = 0; mi < 4; mi++)
#pragma unroll
                for (int ni = 0; ni < 4; ni++) {
                    int p = ni >> 1, o = (ni & 1) * 2;
                    mma_fp8(acc2[mi][ni], a8h[mi], b8l2[p][o], b8l2[p][o + 1]);
                    mma_fp8(acc2[mi][ni], a8l[mi], b8h2[p][o], b8h2[p][o + 1]);
                }
        }
        __syncthreads();
    }
#undef ISSUE

    // ---------------- epilogue ----------------
    const float SC = 1.f / 256.f;
    int t4 = lid >> 2, t2 = (lid & 3) * 2;
#pragma unroll
    for (int mi = 0; mi < 4; mi++) {
#pragma unroll
        for (int ni = 0; ni < 4; ni++) {
            int n = bx * 128 + wn * 32 + ni * 8 + t2;
            int m0 = by * 128 + wm * 64 + mi * 16 + t4;
            float bn0 = 0.f, bn1 = 0.f;
            if (MODE != 0) { bn0 = bias[n]; bn1 = bias[n + 1]; }
#pragma unroll
            for (int half = 0; half < 2; half++) {
                int m = m0 + half * 8;
                float v0 = acc[mi][ni][half * 2]     + SC * acc2[mi][ni][half * 2];
                float v1 = acc[mi][ni][half * 2 + 1] + SC * acc2[mi][ni][half * 2 + 1];
                if (MODE == 0) {
                    int b = m >> 11, t = m & (CTX - 1);
                    int sel = n >> 10, hh = (n & 1023) >> 6, d0 = n & 63;
                    bf16* hi = (sel == 0) ? qhi : (sel == 1 ? khi : vhi);
                    bf16* lo = (sel == 0) ? qlo : (sel == 1 ? klo : vlo);
                    size_t o = ((size_t)(b * NH + hh) * CTX + t) * HS + d0;
                    *(uint32_t*)(hi + o) = pack2bf(v0, v1);
                    *(uint32_t*)(lo + o) = packlo2(v0, v1);
                } else if (MODE == 1) {
                    v0 += bn0; v1 += bn1;
                    float h0 = __bfloat162float(__float2bfloat16(v0));
                    float h1 = __bfloat162float(__float2bfloat16(v1));
                    size_t o = (size_t)m * N + n;
                    *(uint32_t*)(out_hi + o) = pack2bf(v0, v1);
                    *(uint16_t*)(o8h + o) = pack_e4m3x2(h0, h1);
                    *(uint16_t*)(o8l + o) = pack_e4m3x2((v0 - h0) * 256.f, (v1 - h1) * 256.f);
                } else {
                    v0 = fmaxf(v0 + bn0, 0.f);
                    v1 = fmaxf(v1 + bn1, 0.f);
                    *(float2*)(out_f + (size_t)m * N + n) = make_float2(v0, v1);
                }
            }
        }
    }
}

// ================= mma.sync causal flash attention =================
// 128 queries/CTA, 8 warps x 16 rows; Bc=64 key tile; double-buffered K/V.
// V stored [T,D]; PV B-fragments via ldmatrix.trans.
#define PADB   144
#define QTILE  (128*PADB)       // 18432
#define KVTILE (64*PADB)        // 9216
#define ASTAGE (4*KVTILE)       // 36864
#define ATTN_SMEM (2*QTILE + 2*ASTAGE)   // 110592

__global__ __launch_bounds__(256, 1)
void attn_mma()
{
    extern __shared__ char smem[];
    uint32_t sb = smem_u32(smem);
    int tid = threadIdx.x, wid = tid >> 5, lid = tid & 31;
    int qt = blockIdx.x, h = blockIdx.y, b = blockIdx.z;
    int q0 = qt * 128;
    int wm = wid;
    int g = lid >> 3, rr = lid & 7;
    uint32_t a_off = (uint32_t)(((g & 1) * 8 + rr) * PADB + (g >> 1) * 16);
    uint32_t b_off = (uint32_t)(((g >> 1) * 8 + rr) * PADB + (g & 1) * 16);
    int t4 = lid >> 2, t2 = lid & 3;

    size_t hb = (size_t)(b * NH + h);
    const bf16* qhB = g_qhi + hb * CTX * HS;
    const bf16* qlB = g_qlo + hb * CTX * HS;
    const bf16* khB = g_khi + hb * CTX * HS;
    const bf16* klB = g_klo + hb * CTX * HS;
    const bf16* vhB = g_vhi + hb * CTX * HS;
    const bf16* vlB = g_vlo + hb * CTX * HS;

    // Q tile (128 x 64) hi/lo
#pragma unroll
    for (int i = 0; i < 4; i++) {
        int idx = tid + i * 256;
        int r = idx >> 3, ch = idx & 7;
        uint32_t so = (uint32_t)(r * PADB + ch * 16);
        size_t gg = (size_t)(q0 + r) * HS + ch * 8;
        cp16(sb + so, qhB + gg);
        cp16(sb + QTILE + so, qlB + gg);
    }
    CP_COMMIT();

#define LOAD_TILE(st, kb_) do {                                            \
        uint32_t bs = sb + 2 * QTILE + (st) * ASTAGE;                      \
        for (int i_ = 0; i_ < 2; i_++) {                                   \
            int idx_ = tid + i_ * 256;                                     \
            int r_ = idx_ >> 3, ch_ = idx_ & 7;                            \
            uint32_t so_ = (uint32_t)(r_ * PADB + ch_ * 16);               \
            size_t kg_ = (size_t)((kb_) + r_) * HS + ch_ * 8;              \
            cp16(bs + so_, khB + kg_);                                     \
            cp16(bs + KVTILE + so_, klB + kg_);                            \
            cp16(bs + 2 * KVTILE + so_, vhB + kg_);                        \
            cp16(bs + 3 * KVTILE + so_, vlB + kg_);                        \
        } } while (0)

    LOAD_TILE(0, 0);
    CP_COMMIT();

    uint32_t qfh[4][4], qfl[4][4];
    float of[8][4];
#pragma unroll
    for (int i = 0; i < 8; i++)
#pragma unroll
        for (int j = 0; j < 4; j++) of[i][j] = 0.f;
    float m0 = -1e30f, m1 = -1e30f, l0 = 0.f, l1 = 0.f;
    bool qload = false;

    int nkt = 2 * qt + 2;
    for (int kt = 0; kt < nkt; kt++) {
        int kb = kt * 64;
        if (kt + 1 < nkt) { LOAD_TILE((kt + 1) & 1, kb + 64); CP_COMMIT(); CP_WAIT(1); }
        else { CP_WAIT(0); }
        __syncthreads();
        if (!qload) {
#pragma unroll
            for (int ks = 0; ks < 4; ks++) {
                uint32_t qo = (uint32_t)((wm * 16) * PADB + ks * 32) + a_off;
                ldm4(qfh[ks], sb + qo);
                ldm4(qfl[ks], sb + QTILE + qo);
            }
            qload = true;
        }
        if (q0 + wm * 16 + 15 >= kb) {
            uint32_t base = sb + 2 * QTILE + (kt & 1) * ASTAGE;
            float sf[8][4];
#pragma unroll
            for (int i = 0; i < 8; i++)
#pragma unroll
                for (int j = 0; j < 4; j++) sf[i][j] = 0.f;

#pragma unroll
            for (int ks = 0; ks < 4; ks++) {
                uint32_t bh[4][4], bl[4][4];
#pragma unroll
                for (int p = 0; p < 4; p++) {
                    uint32_t off = (uint32_t)((p * 16) * PADB + ks * 32) + b_off;
                    ldm4(bh[p], base + off);
                    ldm4(bl[p], base + KVTILE + off);
                }
#pragma unroll
                for (int ni = 0; ni < 8; ni++) {
                    int p = ni >> 1, o = (ni & 1) * 2;
                    mma_bf16(sf[ni], qfh[ks], &bh[p][o]);
                    mma_bf16(sf[ni], qfh[ks], &bl[p][o]);
                    mma_bf16(sf[ni], qfl[ks], &bh[p][o]);
                }
            }

            int row0 = q0 + wm * 16 + t4, row1 = row0 + 8;
            bool needm = (kb + 63 > q0 + wm * 16);
            float mx0 = -1e30f, mx1 = -1e30f;
#pragma unroll
            for (int ni = 0; ni < 8; ni++) {
                int c = kb + ni * 8 + t2 * 2;
                float s0 = sf[ni][0] * 0.125f, s1 = sf[ni][1] * 0.125f;
                float s2 = sf[ni][2] * 0.125f, s3 = sf[ni][3] * 0.125f;
                if (needm) {
                    if (c > row0)     s0 = -1e30f;
                    if (c + 1 > row0) s1 = -1e30f;
                    if (c > row1)     s2 = -1e30f;
                    if (c + 1 > row1) s3 = -1e30f;
                }
                sf[ni][0] = s0; sf[ni][1] = s1; sf[ni][2] = s2; sf[ni][3] = s3;
                mx0 = fmaxf(mx0, fmaxf(s0, s1));
                mx1 = fmaxf(mx1, fmaxf(s2, s3));
            }
            mx0 = fmaxf(mx0, __shfl_xor_sync(0xffffffffu, mx0, 1));
            mx0 = fmaxf(mx0, __shfl_xor_sync(0xffffffffu, mx0, 2));
            mx1 = fmaxf(mx1, __shfl_xor_sync(0xffffffffu, mx1, 1));
            mx1 = fmaxf(mx1, __shfl_xor_sync(0xffffffffu, mx1, 2));
            float nm0 = fmaxf(m0, mx0), nm1 = fmaxf(m1, mx1);
            float cr0 = __expf(m0 - nm0), cr1 = __expf(m1 - nm1);
            m0 = nm0; m1 = nm1;
            l0 *= cr0; l1 *= cr1;
#pragma unroll
            for (int ni = 0; ni < 8; ni++) {
                float p0 = __expf(sf[ni][0] - m0), p1 = __expf(sf[ni][1] - m0);
                float p2 = __expf(sf[ni][2] - m1), p3 = __expf(sf[ni][3] - m1);
                sf[ni][0] = p0; sf[ni][1] = p1; sf[ni][2] = p2; sf[ni][3] = p3;
                l0 += p0 + p1; l1 += p2 + p3;
                of[ni][0] *= cr0; of[ni][1] *= cr0; of[ni][2] *= cr1; of[ni][3] *= cr1;
            }

#pragma unroll
            for (int ks2 = 0; ks2 < 4; ks2++) {
                int n0b = 2 * ks2, n1b = n0b + 1;
                uint32_t pah[4], pal[4];
                pah[0] = pack2bf(sf[n0b][0], sf[n0b][1]);
                pah[1] = pack2bf(sf[n0b][2], sf[n0b][3]);
                pah[2] = pack2bf(sf[n1b][0], sf[n1b][1]);
                pah[3] = pack2bf(sf[n1b][2], sf[n1b][3]);
                pal[0] = packlo2(sf[n0b][0], sf[n0b][1]);
                pal[1] = packlo2(sf[n0b][2], sf[n0b][3]);
                pal[2] = packlo2(sf[n1b][0], sf[n1b][1]);
                pal[3] = packlo2(sf[n1b][2], sf[n1b][3]);
                uint32_t vh[4][4], vl[4][4];
#pragma unroll
                for (int p = 0; p < 4; p++) {
                    uint32_t off = (uint32_t)((ks2 * 16) * PADB + p * 32) + a_off;
                    ldm4t(vh[p], base + 2 * KVTILE + off);
                    ldm4t(vl[p], base + 3 * KVTILE + off);
                }
#pragma unroll
                for (int ni = 0; ni < 8; ni++) {
                    int p = ni >> 1, o = (ni & 1) * 2;
                    mma_bf16(of[ni], pah, &vh[p][o]);
                    mma_bf16(of[ni], pah, &vl[p][o]);
                    mma_bf16(of[ni], pal, &vh[p][o]);
                }
            }
        }
        __syncthreads();
    }
#undef LOAD_TILE

    l0 += __shfl_xor_sync(0xffffffffu, l0, 1);
    l0 += __shfl_xor_sync(0xffffffffu, l0, 2);
    l1 += __shfl_xor_sync(0xffffffffu, l1, 1);
    l1 += __shfl_xor_sync(0xffffffffu, l1, 2);
    float inv0 = 1.f / l0, inv1 = 1.f / l1;

    int row0 = q0 + wm * 16 + t4;
#pragma unroll
    for (int ni = 0; ni < 8; ni++) {
        int col = h * HS + ni * 8 + t2 * 2;
        float v0 = of[ni][0] * inv0, v1 = of[ni][1] * inv0;
        float v2 = of[ni][2] * inv1, v3 = of[ni][3] * inv1;
        size_t o0 = ((size_t)(b * CTX) + row0) * DM + col;
        size_t o1 = o0 + (size_t)8 * DM;
        float h0 = __bfloat162float(__float2bfloat16(v0));
        float h1 = __bfloat162float(__float2bfloat16(v1));
        float h2 = __bfloat162float(__float2bfloat16(v2));
        float h3 = __bfloat162float(__float2bfloat16(v3));
        *(uint32_t*)(g_ahi + o0) = pack2bf(v0, v1);
        *(uint32_t*)(g_ahi + o1) = pack2bf(v2, v3);
        *(uint16_t*)(g_a8h + o0) = pack_e4m3x2(h0, h1);
        *(uint16_t*)(g_a8h + o1) = pack_e4m3x2(h2, h3);
        *(uint16_t*)(g_a8l + o0) = pack_e4m3x2((v0 - h0) * 256.f, (v1 - h1) * 256.f);
        *(uint16_t*)(g_a8l + o1) = pack_e4m3x2((v2 - h2) * 256.f, (v3 - h3) * 256.f);
    }
}

// ================= launch =================
extern "C" void kernel_launch(void* const* d_in, const int* in_sizes, int n_in,
                              void* d_out, int out_size)
{
    const float* x  = (const float*)d_in[0];
    const float* Wq = (const float*)d_in[1];
    const float* Wk = (const float*)d_in[2];
    const float* Wv = (const float*)d_in[3];
    const float* W1 = (const float*)d_in[4];
    const float* b1 = (const float*)d_in[5];
    const float* W2 = (const float*)d_in[6];
    const float* b2 = (const float*)d_in[7];
    float* out = (float*)d_out;

    bf16 *qhi, *qlo, *khi, *klo, *vhi, *vlo;
    bf16 *xhi, *bqhi, *ahi, *w1hi, *hhi, *w2hi;
    uint8_t *x8h, *x8l, *bq8h, *bq8l, *a8h, *a8l, *w18h, *w18l, *h8h, *h8l, *w28h, *w28l;
    cudaGetSymbolAddress((void**)&qhi, g_qhi);
    cudaGetSymbolAddress((void**)&qlo, g_qlo);
    cudaGetSymbolAddress((void**)&khi, g_khi);
    cudaGetSymbolAddress((void**)&klo, g_klo);
    cudaGetSymbolAddress((void**)&vhi, g_vhi);
    cudaGetSymbolAddress((void**)&vlo, g_vlo);
    cudaGetSymbolAddress((void**)&xhi, g_xhi);
    cudaGetSymbolAddress((void**)&x8h, g_x8h);
    cudaGetSymbolAddress((void**)&x8l, g_x8l);
    cudaGetSymbolAddress((void**)&bqhi, g_bqhi);
    cudaGetSymbolAddress((void**)&bq8h, g_bq8h);
    cudaGetSymbolAddress((void**)&bq8l, g_bq8l);
    cudaGetSymbolAddress((void**)&ahi, g_ahi);
    cudaGetSymbolAddress((void**)&a8h, g_a8h);
    cudaGetSymbolAddress((void**)&a8l, g_a8l);
    cudaGetSymbolAddress((void**)&w1hi, g_w1hi);
    cudaGetSymbolAddress((void**)&w18h, g_w18h);
    cudaGetSymbolAddress((void**)&w18l, g_w18l);
    cudaGetSymbolAddress((void**)&hhi, g_hhi);
    cudaGetSymbolAddress((void**)&h8h, g_h8h);
    cudaGetSymbolAddress((void**)&h8l, g_h8l);
    cudaGetSymbolAddress((void**)&w2hi, g_w2hi);
    cudaGetSymbolAddress((void**)&w28h, g_w28h);
    cudaGetSymbolAddress((void**)&w28l, g_w28l);

    cudaFuncSetAttribute(gemm_split<0>, cudaFuncAttributeMaxDynamicSharedMemorySize, GEMM_SMEM);
    cudaFuncSetAttribute(gemm_split<1>, cudaFuncAttributeMaxDynamicSharedMemorySize, GEMM_SMEM);
    cudaFuncSetAttribute(gemm_split<2>, cudaFuncAttributeMaxDynamicSharedMemorySize, GEMM_SMEM);
    cudaFuncSetAttribute(attn_mma, cudaFuncAttributeMaxDynamicSharedMemorySize, ATTN_SMEM);

    // input conversions
    split_x_kernel<<<(size_t)MTOT * NEMB / 1024, 256>>>(x, xhi, x8h, x8l);
    qkv_transpose_split<<<dim3(NEMB / 32, HS / 32, 48), dim3(32, 8)>>>(Wq, Wk, Wv, bqhi, bq8h, bq8l);
    transpose_split<<<dim3(FF / 32, DM / 32), dim3(32, 8)>>>(W1, w1hi, w18h, w18l, DM, FF);
    transpose_split<<<dim3(DM / 32, FF / 32), dim3(32, 8)>>>(W2, w2hi, w28h, w28l, FF, DM);

    // QKV: [8192,1024] @ [1024,3072] -> split bf16 q/k/v [B,H,T,D]
    gemm_split<0><<<dim3(3 * DM / 128, MTOT / 128), 256, GEMM_SMEM>>>(
        xhi, x8h, x8l, bqhi, bq8h, bq8l, nullptr,
        nullptr, nullptr, nullptr, nullptr,
        qhi, qlo, khi, klo, vhi, vlo, 3 * DM, NEMB);

    // attention -> att hi bf16 + fp8 hi/lo
    attn_mma<<<dim3(CTX / 128, NH, BATCH), 256, ATTN_SMEM>>>();

    // FFN1: [8192,1024] @ [1024,4096] + b1 -> h
    gemm_split<1><<<dim3(FF / 128, MTOT / 128), 256, GEMM_SMEM>>>(
        ahi, a8h, a8l, w1hi, w18h, w18l, b1,
        nullptr, hhi, h8h, h8l,
        nullptr, nullptr, nullptr, nullptr, nullptr, nullptr, FF, DM);

    // FFN2: [8192,4096] @ [4096,1024] + b2, relu -> out
    gemm_split<2><<<dim3(DM / 128, MTOT / 128), 256, GEMM_SMEM>>>(
        hhi, h8h, h8l, w2hi, w28h, w28l, b2,
        out, nullptr, nullptr, nullptr,
        nullptr, nullptr, nullptr, nullptr, nullptr, nullptr, DM, FF);
}

// round 7
// speedup vs baseline: 1.3024x; 1.3024x over previous
#include <cuda_runtime.h>
#include <cuda_bf16.h>
#include <cstdint>

#define BATCH 4
#define CTX   2048
#define NEMB  1024
#define NH    16
#define HS    64
#define DM    1024
#define FF    4096
#define MTOT  (BATCH*CTX)   // 8192

typedef __nv_bfloat16 bf16;

// ================= scratch =================
__device__ bf16 g_qhi[(size_t)BATCH*NH*CTX*HS], g_qlo[(size_t)BATCH*NH*CTX*HS];
__device__ bf16 g_khi[(size_t)BATCH*NH*CTX*HS], g_klo[(size_t)BATCH*NH*CTX*HS];
__device__ bf16 g_vhi[(size_t)BATCH*NH*CTX*HS], g_vlo[(size_t)BATCH*NH*CTX*HS];
__device__ bf16 g_xhi[(size_t)MTOT*NEMB],  g_xlo[(size_t)MTOT*NEMB];
__device__ bf16 g_bqhi[(size_t)3*DM*NEMB], g_bqlo[(size_t)3*DM*NEMB];
__device__ bf16 g_ahi[(size_t)MTOT*DM],    g_alo[(size_t)MTOT*DM];
__device__ bf16 g_w1hi[(size_t)FF*DM],     g_w1lo[(size_t)FF*DM];
__device__ bf16 g_hhi[(size_t)MTOT*FF],    g_hlo[(size_t)MTOT*FF];
__device__ bf16 g_w2hi[(size_t)DM*FF],     g_w2lo[(size_t)DM*FF];

__device__ __forceinline__ uint32_t pack2bf(float a, float b) {
    __nv_bfloat162 p(__float2bfloat16(a), __float2bfloat16(b));
    return *reinterpret_cast<uint32_t*>(&p);
}
__device__ __forceinline__ uint32_t packlo2(float a, float b) {
    float ra = __bfloat162float(__float2bfloat16(a));
    float rb = __bfloat162float(__float2bfloat16(b));
    return pack2bf(a - ra, b - rb);
}
__device__ __forceinline__ uint32_t smem_u32(const void* p) {
    uint32_t a;
    asm("{ .reg .u64 t; cvta.to.shared.u64 t, %1; cvt.u32.u64 %0, t; }" : "=r"(a) : "l"(p));
    return a;
}
__device__ __forceinline__ void cp16(uint32_t dst, const void* src) {
    asm volatile("cp.async.cg.shared.global [%0], [%1], 16;" :: "r"(dst), "l"(src));
}
#define CP_COMMIT() asm volatile("cp.async.commit_group;" ::: "memory")
#define CP_WAIT(n)  asm volatile("cp.async.wait_group %0;" :: "n"(n) : "memory")

__device__ __forceinline__ void ldm4(uint32_t* r, uint32_t addr) {
    asm volatile("ldmatrix.sync.aligned.m8n8.x4.shared.b16 {%0,%1,%2,%3}, [%4];"
        : "=r"(r[0]), "=r"(r[1]), "=r"(r[2]), "=r"(r[3]) : "r"(addr));
}
__device__ __forceinline__ void ldm4t(uint32_t* r, uint32_t addr) {
    asm volatile("ldmatrix.sync.aligned.m8n8.x4.trans.shared.b16 {%0,%1,%2,%3}, [%4];"
        : "=r"(r[0]), "=r"(r[1]), "=r"(r[2]), "=r"(r[3]) : "r"(addr));
}
__device__ __forceinline__ void mma_bf16(float* d, const uint32_t* a, const uint32_t* b) {
    asm volatile("mma.sync.aligned.m16n8k16.row.col.f32.bf16.bf16.f32 "
        "{%0,%1,%2,%3}, {%4,%5,%6,%7}, {%8,%9}, {%0,%1,%2,%3};"
        : "+f"(d[0]), "+f"(d[1]), "+f"(d[2]), "+f"(d[3])
        : "r"(a[0]), "r"(a[1]), "r"(a[2]), "r"(a[3]), "r"(b[0]), "r"(b[1]));
}

// ================= split / transpose kernels =================
__global__ __launch_bounds__(256) void split_x_kernel(const float* __restrict__ x,
                                                      bf16* __restrict__ hi, bf16* __restrict__ lo)
{
    size_t i = (size_t)blockIdx.x * 256 + threadIdx.x;
    float4 v = ((const float4*)x)[i];
    ((uint2*)hi)[i] = make_uint2(pack2bf(v.x, v.y), pack2bf(v.z, v.w));
    ((uint2*)lo)[i] = make_uint2(packlo2(v.x, v.y), packlo2(v.z, v.w));
}

// W [K,N] row-major -> out [N,K] bf16 hi/lo
__global__ __launch_bounds__(256) void transpose_split(const float* __restrict__ W,
                                                       bf16* __restrict__ hi, bf16* __restrict__ lo,
                                                       int K, int N)
{
    __shared__ float t[32][33];
    int n0 = blockIdx.x * 32, k0 = blockIdx.y * 32;
    int tx = threadIdx.x, ty = threadIdx.y;
#pragma unroll
    for (int i = ty; i < 32; i += 8)
        t[i][tx] = W[(size_t)(k0 + i) * N + n0 + tx];
    __syncthreads();
#pragma unroll
    for (int i = ty; i < 32; i += 8) {
        float v = t[tx][i];
        bf16 h = __float2bfloat16(v);
        size_t o = (size_t)(n0 + i) * K + k0 + tx;
        hi[o] = h;
        lo[o] = __float2bfloat16(v - __bfloat162float(h));
    }
}

// Wq/Wk/Wv [H,C,D] -> bqkv[n = sel*1024 + h*64 + d][k = c]
__global__ __launch_bounds__(256) void qkv_transpose_split(const float* __restrict__ Wq,
                                                           const float* __restrict__ Wk,
                                                           const float* __restrict__ Wv,
                                                           bf16* __restrict__ hi, bf16* __restrict__ lo)
{
    __shared__ float t[32][33];
    int sel = blockIdx.z >> 4, h = blockIdx.z & 15;
    const float* W = (sel == 0 ? Wq : sel == 1 ? Wk : Wv) + (size_t)h * NEMB * HS;
    int c0 = blockIdx.x * 32, d0 = blockIdx.y * 32;
    int tx = threadIdx.x, ty = threadIdx.y;
#pragma unroll
    for (int i = ty; i < 32; i += 8)
        t[i][tx] = W[(size_t)(c0 + i) * HS + d0 + tx];
    __syncthreads();
    int nbase = sel * DM + h * HS + d0;
#pragma unroll
    for (int i = ty; i < 32; i += 8) {
        float v = t[tx][i];
        bf16 hh = __float2bfloat16(v);
        size_t o = (size_t)(nbase + i) * NEMB + c0 + tx;
        hi[o] = hh;
        lo[o] = __float2bfloat16(v - __bfloat162float(hh));
    }
}

// ================= mma.sync split-bf16 GEMM, 128x256 CTA tile =================
// D[m,n] = sum_k A[m,k]*B[n,k] via AhiBhi + AhiBlo + AloBhi
// MODE 0: scatter split bf16 -> q/k/v [B,H,T,D] hi/lo
// MODE 1: +bias, write split bf16 (FFN1 -> h)
// MODE 2: +bias, relu, write fp32 (FFN2 -> out)
#define ROWB    80
#define TA      (128*ROWB)   // 10240
#define TBL     (256*ROWB)   // 20480
#define OFF_AH  0
#define OFF_AL  (TA)
#define OFF_BH  (2*TA)
#define OFF_BL  (2*TA + TBL)
#define STAGE_B (2*TA + 2*TBL)   // 61440
#define NSTAGE  3
#define GEMM_SMEM (NSTAGE*STAGE_B)   // 184320

template <int MODE>
__global__ __launch_bounds__(256, 1)
void gemm_split(const bf16* __restrict__ Ahi, const bf16* __restrict__ Alo,
                const bf16* __restrict__ Bhi, const bf16* __restrict__ Blo,
                const float* __restrict__ bias,
                float* __restrict__ out_f, bf16* __restrict__ out_hi, bf16* __restrict__ out_lo,
                bf16* __restrict__ qhi, bf16* __restrict__ qlo,
                bf16* __restrict__ khi, bf16* __restrict__ klo,
                bf16* __restrict__ vhi, bf16* __restrict__ vlo,
                int N, int K)
{
    extern __shared__ char smem[];
    uint32_t sb = smem_u32(smem);

    int tid = threadIdx.x, wid = tid >> 5, lid = tid & 31;
    int wm = wid >> 2, wn = wid & 3;          // warp tile 64(M) x 64(N)
    int bx = blockIdx.x, by = blockIdx.y;

    const bf16* aH = Ahi + (size_t)by * 128 * K;
    const bf16* aL = Alo + (size_t)by * 128 * K;
    const bf16* bH = Bhi + (size_t)bx * 256 * K;
    const bf16* bL = Blo + (size_t)bx * 256 * K;

    float acc[4][8][4];
#pragma unroll
    for (int i = 0; i < 4; i++)
#pragma unroll
        for (int j = 0; j < 8; j++)
#pragma unroll
            for (int l = 0; l < 4; l++) acc[i][j][l] = 0.f;

    int ITERS = K >> 5;

#define ISSUE(st, k0) do {                                                         \
        uint32_t _b = sb + (st) * STAGE_B;                                         \
        _Pragma("unroll")                                                          \
        for (int _i = 0; _i < 2; _i++) {                                           \
            int _c = tid + _i * 256; int _r = _c >> 2, _q = _c & 3;                \
            uint32_t _so = (uint32_t)(_r * ROWB + _q * 16);                        \
            size_t _g = (size_t)_r * K + (k0) + _q * 8;                            \
            cp16(_b + OFF_AH + _so, aH + _g);                                      \
            cp16(_b + OFF_AL + _so, aL + _g);                                      \
        }                                                                          \
        _Pragma("unroll")                                                          \
        for (int _i = 0; _i < 4; _i++) {                                           \
            int _c = tid + _i * 256; int _r = _c >> 2, _q = _c & 3;                \
            uint32_t _so = (uint32_t)(_r * ROWB + _q * 16);                        \
            size_t _g = (size_t)_r * K + (k0) + _q * 8;                            \
            cp16(_b + OFF_BH + _so, bH + _g);                                      \
            cp16(_b + OFF_BL + _so, bL + _g);                                      \
        }                                                                          \
    } while (0)

    ISSUE(0, 0);  CP_COMMIT();
    ISSUE(1, 32); CP_COMMIT();

    int g = lid >> 3, rr = lid & 7;
    uint32_t a_row_off = (uint32_t)(((g & 1) * 8 + rr) * ROWB + (g >> 1) * 16);
    uint32_t b_row_off = (uint32_t)(((g >> 1) * 8 + rr) * ROWB + (g & 1) * 16);

    for (int it = 0; it < ITERS; it++) {
        int pre = it + NSTAGE - 1;
        if (pre < ITERS) { ISSUE(pre % NSTAGE, pre * 32); }
        CP_COMMIT();
        CP_WAIT(NSTAGE - 2);
        __syncthreads();

        uint32_t base = sb + (it % NSTAGE) * STAGE_B;
#pragma unroll
        for (int ks = 0; ks < 2; ks++) {
            uint32_t ah[4][4], al[4][4], bh[4][4], bl[4][4];
#pragma unroll
            for (int mi = 0; mi < 4; mi++) {
                uint32_t off = (uint32_t)((wm * 64 + mi * 16) * ROWB + ks * 32) + a_row_off;
                ldm4(ah[mi], base + OFF_AH + off);
                ldm4(al[mi], base + OFF_AL + off);
            }
#pragma unroll
            for (int p = 0; p < 4; p++) {
                uint32_t off = (uint32_t)((wn * 64 + p * 16) * ROWB + ks * 32) + b_row_off;
                ldm4(bh[p], base + OFF_BH + off);
                ldm4(bl[p], base + OFF_BL + off);
            }
#pragma unroll
            for (int mi = 0; mi < 4; mi++)
#pragma unroll
                for (int ni = 0; ni < 8; ni++) {
                    int p = ni >> 1, o = (ni & 1) * 2;
                    mma_bf16(acc[mi][ni], ah[mi], &bh[p][o]);
                    mma_bf16(acc[mi][ni], ah[mi], &bl[p][o]);
                    mma_bf16(acc[mi][ni], al[mi], &bh[p][o]);
                }
        }
        __syncthreads();
    }
#undef ISSUE

    // ---------------- epilogue ----------------
    int t4 = lid >> 2, t2 = (lid & 3) * 2;
#pragma unroll
    for (int mi = 0; mi < 4; mi++) {
#pragma unroll
        for (int ni = 0; ni < 8; ni++) {
            int n = bx * 256 + wn * 64 + ni * 8 + t2;
            int m0 = by * 128 + wm * 64 + mi * 16 + t4;
            float bn0 = 0.f, bn1 = 0.f;
            if (MODE != 0) { bn0 = bias[n]; bn1 = bias[n + 1]; }
#pragma unroll
            for (int half = 0; half < 2; half++) {
                int m = m0 + half * 8;
                float v0 = acc[mi][ni][half * 2];
                float v1 = acc[mi][ni][half * 2 + 1];
                if (MODE == 0) {
                    int b = m >> 11, t = m & (CTX - 1);
                    int sel = n >> 10, hh = (n & 1023) >> 6, d0 = n & 63;
                    bf16* hi = (sel == 0) ? qhi : (sel == 1 ? khi : vhi);
                    bf16* lo = (sel == 0) ? qlo : (sel == 1 ? klo : vlo);
                    size_t o = ((size_t)(b * NH + hh) * CTX + t) * HS + d0;
                    *(uint32_t*)(hi + o) = pack2bf(v0, v1);
                    *(uint32_t*)(lo + o) = packlo2(v0, v1);
                } else if (MODE == 1) {
                    v0 += bn0; v1 += bn1;
                    size_t o = (size_t)m * N + n;
                    *(uint32_t*)(out_hi + o) = pack2bf(v0, v1);
                    *(uint32_t*)(out_lo + o) = packlo2(v0, v1);
                } else {
                    v0 = fmaxf(v0 + bn0, 0.f);
                    v1 = fmaxf(v1 + bn1, 0.f);
                    *(float2*)(out_f + (size_t)m * N + n) = make_float2(v0, v1);
                }
            }
        }
    }
}

// ================= mma.sync causal flash attention =================
// 128 queries/CTA, 8 warps x 16 rows; Bc=64 key tile; double-buffered K/V.
// V stored [T,D]; PV B-fragments via ldmatrix.trans.
#define PADB   144
#define QTILE  (128*PADB)       // 18432
#define KVTILE (64*PADB)        // 9216
#define ASTAGE (4*KVTILE)       // 36864
#define ATTN_SMEM (2*QTILE + 2*ASTAGE)   // 110592

__global__ __launch_bounds__(256, 1)
void attn_mma()
{
    extern __shared__ char smem[];
    uint32_t sb = smem_u32(smem);
    int tid = threadIdx.x, wid = tid >> 5, lid = tid & 31;
    int qt = blockIdx.x, h = blockIdx.y, b = blockIdx.z;
    int q0 = qt * 128;
    int wm = wid;
    int g = lid >> 3, rr = lid & 7;
    uint32_t a_off = (uint32_t)(((g & 1) * 8 + rr) * PADB + (g >> 1) * 16);
    uint32_t b_off = (uint32_t)(((g >> 1) * 8 + rr) * PADB + (g & 1) * 16);
    int t4 = lid >> 2, t2 = lid & 3;

    size_t hb = (size_t)(b * NH + h);
    const bf16* qhB = g_qhi + hb * CTX * HS;
    const bf16* qlB = g_qlo + hb * CTX * HS;
    const bf16* khB = g_khi + hb * CTX * HS;
    const bf16* klB = g_klo + hb * CTX * HS;
    const bf16* vhB = g_vhi + hb * CTX * HS;
    const bf16* vlB = g_vlo + hb * CTX * HS;

    // Q tile (128 x 64) hi/lo
#pragma unroll
    for (int i = 0; i < 4; i++) {
        int idx = tid + i * 256;
        int r = idx >> 3, ch = idx & 7;
        uint32_t so = (uint32_t)(r * PADB + ch * 16);
        size_t gg = (size_t)(q0 + r) * HS + ch * 8;
        cp16(sb + so, qhB + gg);
        cp16(sb + QTILE + so, qlB + gg);
    }
    CP_COMMIT();

#define LOAD_TILE(st, kb_) do {                                            \
        uint32_t bs = sb + 2 * QTILE + (st) * ASTAGE;                      \
        for (int i_ = 0; i_ < 2; i_++) {                                   \
            int idx_ = tid + i_ * 256;                                     \
            int r_ = idx_ >> 3, ch_ = idx_ & 7;                            \
            uint32_t so_ = (uint32_t)(r_ * PADB + ch_ * 16);               \
            size_t kg_ = (size_t)((kb_) + r_) * HS + ch_ * 8;              \
            cp16(bs + so_, khB + kg_);                                     \
            cp16(bs + KVTILE + so_, klB + kg_);                            \
            cp16(bs + 2 * KVTILE + so_, vhB + kg_);                        \
            cp16(bs + 3 * KVTILE + so_, vlB + kg_);                        \
        } } while (0)

    LOAD_TILE(0, 0);
    CP_COMMIT();

    uint32_t qfh[4][4], qfl[4][4];
    float of[8][4];
#pragma unroll
    for (int i = 0; i < 8; i++)
#pragma unroll
        for (int j = 0; j < 4; j++) of[i][j] = 0.f;
    float m0 = -1e30f, m1 = -1e30f, l0 = 0.f, l1 = 0.f;
    bool qload = false;

    int nkt = 2 * qt + 2;
    for (int kt = 0; kt < nkt; kt++) {
        int kb = kt * 64;
        if (kt + 1 < nkt) { LOAD_TILE((kt + 1) & 1, kb + 64); CP_COMMIT(); CP_WAIT(1); }
        else { CP_WAIT(0); }
        __syncthreads();
        if (!qload) {
#pragma unroll
            for (int ks = 0; ks < 4; ks++) {
                uint32_t qo = (uint32_t)((wm * 16) * PADB + ks * 32) + a_off;
                ldm4(qfh[ks], sb + qo);
                ldm4(qfl[ks], sb + QTILE + qo);
            }
            qload = true;
        }
        if (q0 + wm * 16 + 15 >= kb) {
            uint32_t base = sb + 2 * QTILE + (kt & 1) * ASTAGE;
            float sf[8][4];
#pragma unroll
            for (int i = 0; i < 8; i++)
#pragma unroll
                for (int j = 0; j < 4; j++) sf[i][j] = 0.f;

#pragma unroll
            for (int ks = 0; ks < 4; ks++) {
                uint32_t bh[4][4], bl[4][4];
#pragma unroll
                for (int p = 0; p < 4; p++) {
                    uint32_t off = (uint32_t)((p * 16) * PADB + ks * 32) + b_off;
                    ldm4(bh[p], base + off);
                    ldm4(bl[p], base + KVTILE + off);
                }
#pragma unroll
                for (int ni = 0; ni < 8; ni++) {
                    int p = ni >> 1, o = (ni & 1) * 2;
                    mma_bf16(sf[ni], qfh[ks], &bh[p][o]);
                    mma_bf16(sf[ni], qfh[ks], &bl[p][o]);
                    mma_bf16(sf[ni], qfl[ks], &bh[p][o]);
                }
            }

            int row0 = q0 + wm * 16 + t4, row1 = row0 + 8;
            bool needm = (kb + 63 > q0 + wm * 16);
            float mx0 = -1e30f, mx1 = -1e30f;
#pragma unroll
            for (int ni = 0; ni < 8; ni++) {
                int c = kb + ni * 8 + t2 * 2;
                float s0 = sf[ni][0] * 0.125f, s1 = sf[ni][1] * 0.125f;
                float s2 = sf[ni][2] * 0.125f, s3 = sf[ni][3] * 0.125f;
                if (needm) {
                    if (c > row0)     s0 = -1e30f;
                    if (c + 1 > row0) s1 = -1e30f;
                    if (c > row1)     s2 = -1e30f;
                    if (c + 1 > row1) s3 = -1e30f;
                }
                sf[ni][0] = s0; sf[ni][1] = s1; sf[ni][2] = s2; sf[ni][3] = s3;
                mx0 = fmaxf(mx0, fmaxf(s0, s1));
                mx1 = fmaxf(mx1, fmaxf(s2, s3));
            }
            mx0 = fmaxf(mx0, __shfl_xor_sync(0xffffffffu, mx0, 1));
            mx0 = fmaxf(mx0, __shfl_xor_sync(0xffffffffu, mx0, 2));
            mx1 = fmaxf(mx1, __shfl_xor_sync(0xffffffffu, mx1, 1));
            mx1 = fmaxf(mx1, __shfl_xor_sync(0xffffffffu, mx1, 2));
            float nm0 = fmaxf(m0, mx0), nm1 = fmaxf(m1, mx1);
            float cr0 = __expf(m0 - nm0), cr1 = __expf(m1 - nm1);
            m0 = nm0; m1 = nm1;
            l0 *= cr0; l1 *= cr1;
#pragma unroll
            for (int ni = 0; ni < 8; ni++) {
                float p0 = __expf(sf[ni][0] - m0), p1 = __expf(sf[ni][1] - m0);
                float p2 = __expf(sf[ni][2] - m1), p3 = __expf(sf[ni][3] - m1);
                sf[ni][0] = p0; sf[ni][1] = p1; sf[ni][2] = p2; sf[ni][3] = p3;
                l0 += p0 + p1; l1 += p2 + p3;
                of[ni][0] *= cr0; of[ni][1] *= cr0; of[ni][2] *= cr1; of[ni][3] *= cr1;
            }

#pragma unroll
            for (int ks2 = 0; ks2 < 4; ks2++) {
                int n0b = 2 * ks2, n1b = n0b + 1;
                uint32_t pah[4], pal[4];
                pah[0] = pack2bf(sf[n0b][0], sf[n0b][1]);
                pah[1] = pack2bf(sf[n0b][2], sf[n0b][3]);
                pah[2] = pack2bf(sf[n1b][0], sf[n1b][1]);
                pah[3] = pack2bf(sf[n1b][2], sf[n1b][3]);
                pal[0] = packlo2(sf[n0b][0], sf[n0b][1]);
                pal[1] = packlo2(sf[n0b][2], sf[n0b][3]);
                pal[2] = packlo2(sf[n1b][0], sf[n1b][1]);
                pal[3] = packlo2(sf[n1b][2], sf[n1b][3]);
                uint32_t vh[4][4], vl[4][4];
#pragma unroll
                for (int p = 0; p < 4; p++) {
                    uint32_t off = (uint32_t)((ks2 * 16) * PADB + p * 32) + a_off;
                    ldm4t(vh[p], base + 2 * KVTILE + off);
                    ldm4t(vl[p], base + 3 * KVTILE + off);
                }
#pragma unroll
                for (int ni = 0; ni < 8; ni++) {
                    int p = ni >> 1, o = (ni & 1) * 2;
                    mma_bf16(of[ni], pah, &vh[p][o]);
                    mma_bf16(of[ni], pah, &vl[p][o]);
                    mma_bf16(of[ni], pal, &vh[p][o]);
                }
            }
        }
        __syncthreads();
    }
#undef LOAD_TILE

    l0 += __shfl_xor_sync(0xffffffffu, l0, 1);
    l0 += __shfl_xor_sync(0xffffffffu, l0, 2);
    l1 += __shfl_xor_sync(0xffffffffu, l1, 1);
    l1 += __shfl_xor_sync(0xffffffffu, l1, 2);
    float inv0 = 1.f / l0, inv1 = 1.f / l1;

    int row0 = q0 + wm * 16 + t4;
#pragma unroll
    for (int ni = 0; ni < 8; ni++) {
        int col = h * HS + ni * 8 + t2 * 2;
        float v0 = of[ni][0] * inv0, v1 = of[ni][1] * inv0;
        float v2 = of[ni][2] * inv1, v3 = of[ni][3] * inv1;
        size_t o0 = ((size_t)(b * CTX) + row0) * DM + col;
        size_t o1 = o0 + (size_t)8 * DM;
        *(uint32_t*)(g_ahi + o0) = pack2bf(v0, v1);
        *(uint32_t*)(g_alo + o0) = packlo2(v0, v1);
        *(uint32_t*)(g_ahi + o1) = pack2bf(v2, v3);
        *(uint32_t*)(g_alo + o1) = packlo2(v2, v3);
    }
}

// ================= launch =================
extern "C" void kernel_launch(void* const* d_in, const int* in_sizes, int n_in,
                              void* d_out, int out_size)
{
    const float* x  = (const float*)d_in[0];
    const float* Wq = (const float*)d_in[1];
    const float* Wk = (const float*)d_in[2];
    const float* Wv = (const float*)d_in[3];
    const float* W1 = (const float*)d_in[4];
    const float* b1 = (const float*)d_in[5];
    const float* W2 = (const float*)d_in[6];
    const float* b2 = (const float*)d_in[7];
    float* out = (float*)d_out;

    bf16 *qhi, *qlo, *khi, *klo, *vhi, *vlo;
    bf16 *xhi, *xlo, *bqhi, *bqlo, *ahi, *alo, *w1hi, *w1lo, *hhi, *hlo, *w2hi, *w2lo;
    cudaGetSymbolAddress((void**)&qhi, g_qhi);
    cudaGetSymbolAddress((void**)&qlo, g_qlo);
    cudaGetSymbolAddress((void**)&khi, g_khi);
    cudaGetSymbolAddress((void**)&klo, g_klo);
    cudaGetSymbolAddress((void**)&vhi, g_vhi);
    cudaGetSymbolAddress((void**)&vlo, g_vlo);
    cudaGetSymbolAddress((void**)&xhi, g_xhi);
    cudaGetSymbolAddress((void**)&xlo, g_xlo);
    cudaGetSymbolAddress((void**)&bqhi, g_bqhi);
    cudaGetSymbolAddress((void**)&bqlo, g_bqlo);
    cudaGetSymbolAddress((void**)&ahi, g_ahi);
    cudaGetSymbolAddress((void**)&alo, g_alo);
    cudaGetSymbolAddress((void**)&w1hi, g_w1hi);
    cudaGetSymbolAddress((void**)&w1lo, g_w1lo);
    cudaGetSymbolAddress((void**)&hhi, g_hhi);
    cudaGetSymbolAddress((void**)&hlo, g_hlo);
    cudaGetSymbolAddress((void**)&w2hi, g_w2hi);
    cudaGetSymbolAddress((void**)&w2lo, g_w2lo);

    cudaFuncSetAttribute(gemm_split<0>, cudaFuncAttributeMaxDynamicSharedMemorySize, GEMM_SMEM);
    cudaFuncSetAttribute(gemm_split<1>, cudaFuncAttributeMaxDynamicSharedMemorySize, GEMM_SMEM);
    cudaFuncSetAttribute(gemm_split<2>, cudaFuncAttributeMaxDynamicSharedMemorySize, GEMM_SMEM);
    cudaFuncSetAttribute(attn_mma, cudaFuncAttributeMaxDynamicSharedMemorySize, ATTN_SMEM);

    // input conversions
    split_x_kernel<<<(size_t)MTOT * NEMB / 1024, 256>>>(x, xhi, xlo);
    qkv_transpose_split<<<dim3(NEMB / 32, HS / 32, 48), dim3(32, 8)>>>(Wq, Wk, Wv, bqhi, bqlo);
    transpose_split<<<dim3(FF / 32, DM / 32), dim3(32, 8)>>>(W1, w1hi, w1lo, DM, FF);
    transpose_split<<<dim3(DM / 32, FF / 32), dim3(32, 8)>>>(W2, w2hi, w2lo, FF, DM);

    // QKV: [8192,1024] @ [1024,3072] -> split bf16 q/k/v [B,H,T,D]
    gemm_split<0><<<dim3(3 * DM / 256, MTOT / 128), 256, GEMM_SMEM>>>(
        xhi, xlo, bqhi, bqlo, nullptr,
        nullptr, nullptr, nullptr,
        qhi, qlo, khi, klo, vhi, vlo, 3 * DM, NEMB);

    // attention -> att hi/lo
    attn_mma<<<dim3(CTX / 128, NH, BATCH), 256, ATTN_SMEM>>>();

    // FFN1: [8192,1024] @ [1024,4096] + b1 -> h hi/lo
    gemm_split<1><<<dim3(FF / 256, MTOT / 128), 256, GEMM_SMEM>>>(
        ahi, alo, w1hi, w1lo, b1,
        nullptr, hhi, hlo,
        nullptr, nullptr, nullptr, nullptr, nullptr, nullptr, FF, DM);

    // FFN2: [8192,4096] @ [4096,1024] + b2, relu -> out
    gemm_split<2><<<dim3(DM / 256, MTOT / 128), 256, GEMM_SMEM>>>(
        hhi, hlo, w2hi, w2lo, b2,
        out, nullptr, nullptr,
        nullptr, nullptr, nullptr, nullptr, nullptr, nullptr, DM, FF);
}

// round 8
// speedup vs baseline: 1.3335x; 1.0239x over previous
#include <cuda_runtime.h>
#include <cuda_bf16.h>
#include <cstdint>

#define BATCH 4
#define CTX   2048
#define NEMB  1024
#define NH    16
#define HS    64
#define DM    1024
#define FF    4096
#define MTOT  (BATCH*CTX)   // 8192

typedef __nv_bfloat16 bf16;

// ================= scratch =================
__device__ bf16 g_qhi[(size_t)BATCH*NH*CTX*HS], g_qlo[(size_t)BATCH*NH*CTX*HS];
__device__ bf16 g_khi[(size_t)BATCH*NH*CTX*HS], g_klo[(size_t)BATCH*NH*CTX*HS];
__device__ bf16 g_vhi[(size_t)BATCH*NH*CTX*HS], g_vlo[(size_t)BATCH*NH*CTX*HS];
__device__ bf16 g_xhi[(size_t)MTOT*NEMB],  g_xlo[(size_t)MTOT*NEMB];
__device__ bf16 g_bqhi[(size_t)3*DM*NEMB], g_bqlo[(size_t)3*DM*NEMB];
__device__ bf16 g_ahi[(size_t)MTOT*DM],    g_alo[(size_t)MTOT*DM];
__device__ bf16 g_w1hi[(size_t)FF*DM],     g_w1lo[(size_t)FF*DM];
__device__ bf16 g_hhi[(size_t)MTOT*FF],    g_hlo[(size_t)MTOT*FF];
__device__ bf16 g_w2hi[(size_t)DM*FF],     g_w2lo[(size_t)DM*FF];

__device__ __forceinline__ uint32_t pack2bf(float a, float b) {
    __nv_bfloat162 p(__float2bfloat16(a), __float2bfloat16(b));
    return *reinterpret_cast<uint32_t*>(&p);
}
__device__ __forceinline__ uint32_t packlo2(float a, float b) {
    float ra = __bfloat162float(__float2bfloat16(a));
    float rb = __bfloat162float(__float2bfloat16(b));
    return pack2bf(a - ra, b - rb);
}
__device__ __forceinline__ uint32_t smem_u32(const void* p) {
    uint32_t a;
    asm("{ .reg .u64 t; cvta.to.shared.u64 t, %1; cvt.u32.u64 %0, t; }" : "=r"(a) : "l"(p));
    return a;
}
__device__ __forceinline__ void cp16(uint32_t dst, const void* src) {
    asm volatile("cp.async.cg.shared.global [%0], [%1], 16;" :: "r"(dst), "l"(src));
}
#define CP_COMMIT() asm volatile("cp.async.commit_group;" ::: "memory")
#define CP_WAIT(n)  asm volatile("cp.async.wait_group %0;" :: "n"(n) : "memory")

__device__ __forceinline__ void ldm4(uint32_t* r, uint32_t addr) {
    asm volatile("ldmatrix.sync.aligned.m8n8.x4.shared.b16 {%0,%1,%2,%3}, [%4];"
        : "=r"(r[0]), "=r"(r[1]), "=r"(r[2]), "=r"(r[3]) : "r"(addr));
}
__device__ __forceinline__ void ldm4t(uint32_t* r, uint32_t addr) {
    asm volatile("ldmatrix.sync.aligned.m8n8.x4.trans.shared.b16 {%0,%1,%2,%3}, [%4];"
        : "=r"(r[0]), "=r"(r[1]), "=r"(r[2]), "=r"(r[3]) : "r"(addr));
}
__device__ __forceinline__ void mma_bf16(float* d, const uint32_t* a, const uint32_t* b) {
    asm volatile("mma.sync.aligned.m16n8k16.row.col.f32.bf16.bf16.f32 "
        "{%0,%1,%2,%3}, {%4,%5,%6,%7}, {%8,%9}, {%0,%1,%2,%3};"
        : "+f"(d[0]), "+f"(d[1]), "+f"(d[2]), "+f"(d[3])
        : "r"(a[0]), "r"(a[1]), "r"(a[2]), "r"(a[3]), "r"(b[0]), "r"(b[1]));
}

// ================= split / transpose kernels =================
__global__ __launch_bounds__(256) void split_x_kernel(const float* __restrict__ x,
                                                      bf16* __restrict__ hi, bf16* __restrict__ lo)
{
    size_t i = (size_t)blockIdx.x * 256 + threadIdx.x;
    float4 v = ((const float4*)x)[i];
    ((uint2*)hi)[i] = make_uint2(pack2bf(v.x, v.y), pack2bf(v.z, v.w));
    ((uint2*)lo)[i] = make_uint2(packlo2(v.x, v.y), packlo2(v.z, v.w));
}

// W [K,N] row-major -> out [N,K] bf16 hi/lo
__global__ __launch_bounds__(256) void transpose_split(const float* __restrict__ W,
                                                       bf16* __restrict__ hi, bf16* __restrict__ lo,
                                                       int K, int N)
{
    __shared__ float t[32][33];
    int n0 = blockIdx.x * 32, k0 = blockIdx.y * 32;
    int tx = threadIdx.x, ty = threadIdx.y;
#pragma unroll
    for (int i = ty; i < 32; i += 8)
        t[i][tx] = W[(size_t)(k0 + i) * N + n0 + tx];
    __syncthreads();
#pragma unroll
    for (int i = ty; i < 32; i += 8) {
        float v = t[tx][i];
        bf16 h = __float2bfloat16(v);
        size_t o = (size_t)(n0 + i) * K + k0 + tx;
        hi[o] = h;
        lo[o] = __float2bfloat16(v - __bfloat162float(h));
    }
}

// Wq/Wk/Wv [H,C,D] -> bqkv[n = sel*1024 + h*64 + d][k = c]
__global__ __launch_bounds__(256) void qkv_transpose_split(const float* __restrict__ Wq,
                                                           const float* __restrict__ Wk,
                                                           const float* __restrict__ Wv,
                                                           bf16* __restrict__ hi, bf16* __restrict__ lo)
{
    __shared__ float t[32][33];
    int sel = blockIdx.z >> 4, h = blockIdx.z & 15;
    const float* W = (sel == 0 ? Wq : sel == 1 ? Wk : Wv) + (size_t)h * NEMB * HS;
    int c0 = blockIdx.x * 32, d0 = blockIdx.y * 32;
    int tx = threadIdx.x, ty = threadIdx.y;
#pragma unroll
    for (int i = ty; i < 32; i += 8)
        t[i][tx] = W[(size_t)(c0 + i) * HS + d0 + tx];
    __syncthreads();
    int nbase = sel * DM + h * HS + d0;
#pragma unroll
    for (int i = ty; i < 32; i += 8) {
        float v = t[tx][i];
        bf16 hh = __float2bfloat16(v);
        size_t o = (size_t)(nbase + i) * NEMB + c0 + tx;
        hi[o] = hh;
        lo[o] = __float2bfloat16(v - __bfloat162float(hh));
    }
}

// ================= mma.sync split-bf16 GEMM, 128x256 CTA tile =================
// D[m,n] = sum_k A[m,k]*B[n,k] via AhiBhi + AhiBlo + AloBhi
// Single barrier per K-iter; 3-pass MMA ordering for acc-chain ILP.
// MODE 0: scatter split bf16 -> q/k/v [B,H,T,D] hi/lo
// MODE 1: +bias, write split bf16 (FFN1 -> h)
// MODE 2: +bias, relu, write fp32 (FFN2 -> out)
#define ROWB    80
#define TA      (128*ROWB)   // 10240
#define TBL     (256*ROWB)   // 20480
#define OFF_AH  0
#define OFF_AL  (TA)
#define OFF_BH  (2*TA)
#define OFF_BL  (2*TA + TBL)
#define STAGE_B (2*TA + 2*TBL)   // 61440
#define NSTAGE  3
#define GEMM_SMEM (NSTAGE*STAGE_B)   // 184320

template <int MODE>
__global__ __launch_bounds__(256, 1)
void gemm_split(const bf16* __restrict__ Ahi, const bf16* __restrict__ Alo,
                const bf16* __restrict__ Bhi, const bf16* __restrict__ Blo,
                const float* __restrict__ bias,
                float* __restrict__ out_f, bf16* __restrict__ out_hi, bf16* __restrict__ out_lo,
                bf16* __restrict__ qhi, bf16* __restrict__ qlo,
                bf16* __restrict__ khi, bf16* __restrict__ klo,
                bf16* __restrict__ vhi, bf16* __restrict__ vlo,
                int N, int K)
{
    extern __shared__ char smem[];
    uint32_t sb = smem_u32(smem);

    int tid = threadIdx.x, wid = tid >> 5, lid = tid & 31;
    int wm = wid >> 2, wn = wid & 3;          // warp tile 64(M) x 64(N)
    int bx = blockIdx.x, by = blockIdx.y;

    const bf16* aH = Ahi + (size_t)by * 128 * K;
    const bf16* aL = Alo + (size_t)by * 128 * K;
    const bf16* bH = Bhi + (size_t)bx * 256 * K;
    const bf16* bL = Blo + (size_t)bx * 256 * K;

    float acc[4][8][4];
#pragma unroll
    for (int i = 0; i < 4; i++)
#pragma unroll
        for (int j = 0; j < 8; j++)
#pragma unroll
            for (int l = 0; l < 4; l++) acc[i][j][l] = 0.f;

    int ITERS = K >> 5;

#define ISSUE(st, k0) do {                                                         \
        uint32_t _b = sb + (st) * STAGE_B;                                         \
        _Pragma("unroll")                                                          \
        for (int _i = 0; _i < 2; _i++) {                                           \
            int _c = tid + _i * 256; int _r = _c >> 2, _q = _c & 3;                \
            uint32_t _so = (uint32_t)(_r * ROWB + _q * 16);                        \
            size_t _g = (size_t)_r * K + (k0) + _q * 8;                            \
            cp16(_b + OFF_AH + _so, aH + _g);                                      \
            cp16(_b + OFF_AL + _so, aL + _g);                                      \
        }                                                                          \
        _Pragma("unroll")                                                          \
        for (int _i = 0; _i < 4; _i++) {                                           \
            int _c = tid + _i * 256; int _r = _c >> 2, _q = _c & 3;                \
            uint32_t _so = (uint32_t)(_r * ROWB + _q * 16);                        \
            size_t _g = (size_t)_r * K + (k0) + _q * 8;                            \
            cp16(_b + OFF_BH + _so, bH + _g);                                      \
            cp16(_b + OFF_BL + _so, bL + _g);                                      \
        }                                                                          \
    } while (0)

    ISSUE(0, 0);  CP_COMMIT();
    ISSUE(1, 32); CP_COMMIT();

    int g = lid >> 3, rr = lid & 7;
    uint32_t a_row_off = (uint32_t)(((g & 1) * 8 + rr) * ROWB + (g >> 1) * 16);
    uint32_t b_row_off = (uint32_t)(((g >> 1) * 8 + rr) * ROWB + (g & 1) * 16);

    for (int it = 0; it < ITERS; it++) {
        CP_WAIT(NSTAGE - 2);        // stage it resident
        __syncthreads();            // all warps done with stage it-1 (which it+2 aliases)
        int pre = it + NSTAGE - 1;
        if (pre < ITERS) { ISSUE(pre % NSTAGE, pre * 32); }
        CP_COMMIT();

        uint32_t base = sb + (it % NSTAGE) * STAGE_B;
#pragma unroll
        for (int ks = 0; ks < 2; ks++) {
            uint32_t ah[4][4], al[4][4], bh[4][4], bl[4][4];
#pragma unroll
            for (int mi = 0; mi < 4; mi++) {
                uint32_t off = (uint32_t)((wm * 64 + mi * 16) * ROWB + ks * 32) + a_row_off;
                ldm4(ah[mi], base + OFF_AH + off);
                ldm4(al[mi], base + OFF_AL + off);
            }
#pragma unroll
            for (int p = 0; p < 4; p++) {
                uint32_t off = (uint32_t)((wn * 64 + p * 16) * ROWB + ks * 32) + b_row_off;
                ldm4(bh[p], base + OFF_BH + off);
                ldm4(bl[p], base + OFF_BL + off);
            }
            // 3 passes: dependent MMAs on the same acc are 32 issues apart
#pragma unroll
            for (int mi = 0; mi < 4; mi++)
#pragma unroll
                for (int ni = 0; ni < 8; ni++)
                    mma_bf16(acc[mi][ni], ah[mi], &bh[ni >> 1][(ni & 1) * 2]);
#pragma unroll
            for (int mi = 0; mi < 4; mi++)
#pragma unroll
                for (int ni = 0; ni < 8; ni++)
                    mma_bf16(acc[mi][ni], ah[mi], &bl[ni >> 1][(ni & 1) * 2]);
#pragma unroll
            for (int mi = 0; mi < 4; mi++)
#pragma unroll
                for (int ni = 0; ni < 8; ni++)
                    mma_bf16(acc[mi][ni], al[mi], &bh[ni >> 1][(ni & 1) * 2]);
        }
    }
#undef ISSUE

    // ---------------- epilogue ----------------
    int t4 = lid >> 2, t2 = (lid & 3) * 2;
#pragma unroll
    for (int mi = 0; mi < 4; mi++) {
#pragma unroll
        for (int ni = 0; ni < 8; ni++) {
            int n = bx * 256 + wn * 64 + ni * 8 + t2;
            int m0 = by * 128 + wm * 64 + mi * 16 + t4;
            float bn0 = 0.f, bn1 = 0.f;
            if (MODE != 0) { bn0 = bias[n]; bn1 = bias[n + 1]; }
#pragma unroll
            for (int half = 0; half < 2; half++) {
                int m = m0 + half * 8;
                float v0 = acc[mi][ni][half * 2];
                float v1 = acc[mi][ni][half * 2 + 1];
                if (MODE == 0) {
                    int b = m >> 11, t = m & (CTX - 1);
                    int sel = n >> 10, hh = (n & 1023) >> 6, d0 = n & 63;
                    bf16* hi = (sel == 0) ? qhi : (sel == 1 ? khi : vhi);
                    bf16* lo = (sel == 0) ? qlo : (sel == 1 ? klo : vlo);
                    size_t o = ((size_t)(b * NH + hh) * CTX + t) * HS + d0;
                    *(uint32_t*)(hi + o) = pack2bf(v0, v1);
                    *(uint32_t*)(lo + o) = packlo2(v0, v1);
                } else if (MODE == 1) {
                    v0 += bn0; v1 += bn1;
                    size_t o = (size_t)m * N + n;
                    *(uint32_t*)(out_hi + o) = pack2bf(v0, v1);
                    *(uint32_t*)(out_lo + o) = packlo2(v0, v1);
                } else {
                    v0 = fmaxf(v0 + bn0, 0.f);
                    v1 = fmaxf(v1 + bn1, 0.f);
                    *(float2*)(out_f + (size_t)m * N + n) = make_float2(v0, v1);
                }
            }
        }
    }
}

// ================= mma.sync causal flash attention =================
// 128 queries/CTA, 8 warps x 16 rows; Bc=64 key tile; double-buffered K/V.
// V stored [T,D]; PV B-fragments via ldmatrix.trans.
#define PADB   144
#define QTILE  (128*PADB)       // 18432
#define KVTILE (64*PADB)        // 9216
#define ASTAGE (4*KVTILE)       // 36864
#define ATTN_SMEM (2*QTILE + 2*ASTAGE)   // 110592

__global__ __launch_bounds__(256, 1)
void attn_mma()
{
    extern __shared__ char smem[];
    uint32_t sb = smem_u32(smem);
    int tid = threadIdx.x, wid = tid >> 5, lid = tid & 31;
    int qt = blockIdx.x, h = blockIdx.y, b = blockIdx.z;
    int q0 = qt * 128;
    int wm = wid;
    int g = lid >> 3, rr = lid & 7;
    uint32_t a_off = (uint32_t)(((g & 1) * 8 + rr) * PADB + (g >> 1) * 16);
    uint32_t b_off = (uint32_t)(((g >> 1) * 8 + rr) * PADB + (g & 1) * 16);
    int t4 = lid >> 2, t2 = lid & 3;

    size_t hb = (size_t)(b * NH + h);
    const bf16* qhB = g_qhi + hb * CTX * HS;
    const bf16* qlB = g_qlo + hb * CTX * HS;
    const bf16* khB = g_khi + hb * CTX * HS;
    const bf16* klB = g_klo + hb * CTX * HS;
    const bf16* vhB = g_vhi + hb * CTX * HS;
    const bf16* vlB = g_vlo + hb * CTX * HS;

    // Q tile (128 x 64) hi/lo
#pragma unroll
    for (int i = 0; i < 4; i++) {
        int idx = tid + i * 256;
        int r = idx >> 3, ch = idx & 7;
        uint32_t so = (uint32_t)(r * PADB + ch * 16);
        size_t gg = (size_t)(q0 + r) * HS + ch * 8;
        cp16(sb + so, qhB + gg);
        cp16(sb + QTILE + so, qlB + gg);
    }
    CP_COMMIT();

#define LOAD_TILE(st, kb_) do {                                            \
        uint32_t bs = sb + 2 * QTILE + (st) * ASTAGE;                      \
        for (int i_ = 0; i_ < 2; i_++) {                                   \
            int idx_ = tid + i_ * 256;                                     \
            int r_ = idx_ >> 3, ch_ = idx_ & 7;                            \
            uint32_t so_ = (uint32_t)(r_ * PADB + ch_ * 16);               \
            size_t kg_ = (size_t)((kb_) + r_) * HS + ch_ * 8;              \
            cp16(bs + so_, khB + kg_);                                     \
            cp16(bs + KVTILE + so_, klB + kg_);                            \
            cp16(bs + 2 * KVTILE + so_, vhB + kg_);                        \
            cp16(bs + 3 * KVTILE + so_, vlB + kg_);                        \
        } } while (0)

    LOAD_TILE(0, 0);
    CP_COMMIT();

    uint32_t qfh[4][4], qfl[4][4];
    float of[8][4];
#pragma unroll
    for (int i = 0; i < 8; i++)
#pragma unroll
        for (int j = 0; j < 4; j++) of[i][j] = 0.f;
    float m0 = -1e30f, m1 = -1e30f, l0 = 0.f, l1 = 0.f;
    bool qload = false;

    int nkt = 2 * qt + 2;
    for (int kt = 0; kt < nkt; kt++) {
        int kb = kt * 64;
        if (kt + 1 < nkt) { LOAD_TILE((kt + 1) & 1, kb + 64); CP_COMMIT(); CP_WAIT(1); }
        else { CP_WAIT(0); }
        __syncthreads();
        if (!qload) {
#pragma unroll
            for (int ks = 0; ks < 4; ks++) {
                uint32_t qo = (uint32_t)((wm * 16) * PADB + ks * 32) + a_off;
                ldm4(qfh[ks], sb + qo);
                ldm4(qfl[ks], sb + QTILE + qo);
            }
            qload = true;
        }
        if (q0 + wm * 16 + 15 >= kb) {
            uint32_t base = sb + 2 * QTILE + (kt & 1) * ASTAGE;
            float sf[8][4];
#pragma unroll
            for (int i = 0; i < 8; i++)
#pragma unroll
                for (int j = 0; j < 4; j++) sf[i][j] = 0.f;

#pragma unroll
            for (int ks = 0; ks < 4; ks++) {
                uint32_t bh[4][4], bl[4][4];
#pragma unroll
                for (int p = 0; p < 4; p++) {
                    uint32_t off = (uint32_t)((p * 16) * PADB + ks * 32) + b_off;
                    ldm4(bh[p], base + off);
                    ldm4(bl[p], base + KVTILE + off);
                }
                // 3 passes for ILP (dependent MMAs 8 apart)
#pragma unroll
                for (int ni = 0; ni < 8; ni++)
                    mma_bf16(sf[ni], qfh[ks], &bh[ni >> 1][(ni & 1) * 2]);
#pragma unroll
                for (int ni = 0; ni < 8; ni++)
                    mma_bf16(sf[ni], qfh[ks], &bl[ni >> 1][(ni & 1) * 2]);
#pragma unroll
                for (int ni = 0; ni < 8; ni++)
                    mma_bf16(sf[ni], qfl[ks], &bh[ni >> 1][(ni & 1) * 2]);
            }

            int row0 = q0 + wm * 16 + t4, row1 = row0 + 8;
            bool needm = (kb + 63 > q0 + wm * 16);
            float mx0 = -1e30f, mx1 = -1e30f;
#pragma unroll
            for (int ni = 0; ni < 8; ni++) {
                int c = kb + ni * 8 + t2 * 2;
                float s0 = sf[ni][0] * 0.125f, s1 = sf[ni][1] * 0.125f;
                float s2 = sf[ni][2] * 0.125f, s3 = sf[ni][3] * 0.125f;
                if (needm) {
                    if (c > row0)     s0 = -1e30f;
                    if (c + 1 > row0) s1 = -1e30f;
                    if (c > row1)     s2 = -1e30f;
                    if (c + 1 > row1) s3 = -1e30f;
                }
                sf[ni][0] = s0; sf[ni][1] = s1; sf[ni][2] = s2; sf[ni][3] = s3;
                mx0 = fmaxf(mx0, fmaxf(s0, s1));
                mx1 = fmaxf(mx1, fmaxf(s2, s3));
            }
            mx0 = fmaxf(mx0, __shfl_xor_sync(0xffffffffu, mx0, 1));
            mx0 = fmaxf(mx0, __shfl_xor_sync(0xffffffffu, mx0, 2));
            mx1 = fmaxf(mx1, __shfl_xor_sync(0xffffffffu, mx1, 1));
            mx1 = fmaxf(mx1, __shfl_xor_sync(0xffffffffu, mx1, 2));
            float nm0 = fmaxf(m0, mx0), nm1 = fmaxf(m1, mx1);
            float cr0 = __expf(m0 - nm0), cr1 = __expf(m1 - nm1);
            m0 = nm0; m1 = nm1;
            l0 *= cr0; l1 *= cr1;
#pragma unroll
            for (int ni = 0; ni < 8; ni++) {
                float p0 = __expf(sf[ni][0] - m0), p1 = __expf(sf[ni][1] - m0);
                float p2 = __expf(sf[ni][2] - m1), p3 = __expf(sf[ni][3] - m1);
                sf[ni][0] = p0; sf[ni][1] = p1; sf[ni][2] = p2; sf[ni][3] = p3;
                l0 += p0 + p1; l1 += p2 + p3;
                of[ni][0] *= cr0; of[ni][1] *= cr0; of[ni][2] *= cr1; of[ni][3] *= cr1;
            }

#pragma unroll
            for (int ks2 = 0; ks2 < 4; ks2++) {
                int n0b = 2 * ks2, n1b = n0b + 1;
                uint32_t pah[4], pal[4];
                pah[0] = pack2bf(sf[n0b][0], sf[n0b][1]);
                pah[1] = pack2bf(sf[n0b][2], sf[n0b][3]);
                pah[2] = pack2bf(sf[n1b][0], sf[n1b][1]);
                pah[3] = pack2bf(sf[n1b][2], sf[n1b][3]);
                pal[0] = packlo2(sf[n0b][0], sf[n0b][1]);
                pal[1] = packlo2(sf[n0b][2], sf[n0b][3]);
                pal[2] = packlo2(sf[n1b][0], sf[n1b][1]);
                pal[3] = packlo2(sf[n1b][2], sf[n1b][3]);
                uint32_t vh[4][4], vl[4][4];
#pragma unroll
                for (int p = 0; p < 4; p++) {
                    uint32_t off = (uint32_t)((ks2 * 16) * PADB + p * 32) + a_off;
                    ldm4t(vh[p], base + 2 * KVTILE + off);
                    ldm4t(vl[p], base + 3 * KVTILE + off);
                }
#pragma unroll
                for (int ni = 0; ni < 8; ni++)
                    mma_bf16(of[ni], pah, &vh[ni >> 1][(ni & 1) * 2]);
#pragma unroll
                for (int ni = 0; ni < 8; ni++)
                    mma_bf16(of[ni], pah, &vl[ni >> 1][(ni & 1) * 2]);
#pragma unroll
                for (int ni = 0; ni < 8; ni++)
                    mma_bf16(of[ni], pal, &vh[ni >> 1][(ni & 1) * 2]);
            }
        }
        __syncthreads();
    }
#undef LOAD_TILE

    l0 += __shfl_xor_sync(0xffffffffu, l0, 1);
    l0 += __shfl_xor_sync(0xffffffffu, l0, 2);
    l1 += __shfl_xor_sync(0xffffffffu, l1, 1);
    l1 += __shfl_xor_sync(0xffffffffu, l1, 2);
    float inv0 = 1.f / l0, inv1 = 1.f / l1;

    int row0 = q0 + wm * 16 + t4;
#pragma unroll
    for (int ni = 0; ni < 8; ni++) {
        int col = h * HS + ni * 8 + t2 * 2;
        float v0 = of[ni][0] * inv0, v1 = of[ni][1] * inv0;
        float v2 = of[ni][2] * inv1, v3 = of[ni][3] * inv1;
        size_t o0 = ((size_t)(b * CTX) + row0) * DM + col;
        size_t o1 = o0 + (size_t)8 * DM;
        *(uint32_t*)(g_ahi + o0) = pack2bf(v0, v1);
        *(uint32_t*)(g_alo + o0) = packlo2(v0, v1);
        *(uint32_t*)(g_ahi + o1) = pack2bf(v2, v3);
        *(uint32_t*)(g_alo + o1) = packlo2(v2, v3);
    }
}

// ================= launch =================
extern "C" void kernel_launch(void* const* d_in, const int* in_sizes, int n_in,
                              void* d_out, int out_size)
{
    const float* x  = (const float*)d_in[0];
    const float* Wq = (const float*)d_in[1];
    const float* Wk = (const float*)d_in[2];
    const float* Wv = (const float*)d_in[3];
    const float* W1 = (const float*)d_in[4];
    const float* b1 = (const float*)d_in[5];
    const float* W2 = (const float*)d_in[6];
    const float* b2 = (const float*)d_in[7];
    float* out = (float*)d_out;

    bf16 *qhi, *qlo, *khi, *klo, *vhi, *vlo;
    bf16 *xhi, *xlo, *bqhi, *bqlo, *ahi, *alo, *w1hi, *w1lo, *hhi, *hlo, *w2hi, *w2lo;
    cudaGetSymbolAddress((void**)&qhi, g_qhi);
    cudaGetSymbolAddress((void**)&qlo, g_qlo);
    cudaGetSymbolAddress((void**)&khi, g_khi);
    cudaGetSymbolAddress((void**)&klo, g_klo);
    cudaGetSymbolAddress((void**)&vhi, g_vhi);
    cudaGetSymbolAddress((void**)&vlo, g_vlo);
    cudaGetSymbolAddress((void**)&xhi, g_xhi);
    cudaGetSymbolAddress((void**)&xlo, g_xlo);
    cudaGetSymbolAddress((void**)&bqhi, g_bqhi);
    cudaGetSymbolAddress((void**)&bqlo, g_bqlo);
    cudaGetSymbolAddress((void**)&ahi, g_ahi);
    cudaGetSymbolAddress((void**)&alo, g_alo);
    cudaGetSymbolAddress((void**)&w1hi, g_w1hi);
    cudaGetSymbolAddress((void**)&w1lo, g_w1lo);
    cudaGetSymbolAddress((void**)&hhi, g_hhi);
    cudaGetSymbolAddress((void**)&hlo, g_hlo);
    cudaGetSymbolAddress((void**)&w2hi, g_w2hi);
    cudaGetSymbolAddress((void**)&w2lo, g_w2lo);

    cudaFuncSetAttribute(gemm_split<0>, cudaFuncAttributeMaxDynamicSharedMemorySize, GEMM_SMEM);
    cudaFuncSetAttribute(gemm_split<1>, cudaFuncAttributeMaxDynamicSharedMemorySize, GEMM_SMEM);
    cudaFuncSetAttribute(gemm_split<2>, cudaFuncAttributeMaxDynamicSharedMemorySize, GEMM_SMEM);
    cudaFuncSetAttribute(attn_mma, cudaFuncAttributeMaxDynamicSharedMemorySize, ATTN_SMEM);

    // input conversions
    split_x_kernel<<<(size_t)MTOT * NEMB / 1024, 256>>>(x, xhi, xlo);
    qkv_transpose_split<<<dim3(NEMB / 32, HS / 32, 48), dim3(32, 8)>>>(Wq, Wk, Wv, bqhi, bqlo);
    transpose_split<<<dim3(FF / 32, DM / 32), dim3(32, 8)>>>(W1, w1hi, w1lo, DM, FF);
    transpose_split<<<dim3(DM / 32, FF / 32), dim3(32, 8)>>>(W2, w2hi, w2lo, FF, DM);

    // QKV: [8192,1024] @ [1024,3072] -> split bf16 q/k/v [B,H,T,D]
    gemm_split<0><<<dim3(3 * DM / 256, MTOT / 128), 256, GEMM_SMEM>>>(
        xhi, xlo, bqhi, bqlo, nullptr,
        nullptr, nullptr, nullptr,
        qhi, qlo, khi, klo, vhi, vlo, 3 * DM, NEMB);

    // attention -> att hi/lo
    attn_mma<<<dim3(CTX / 128, NH, BATCH), 256, ATTN_SMEM>>>();

    // FFN1: [8192,1024] @ [1024,4096] + b1 -> h hi/lo
    gemm_split<1><<<dim3(FF / 256, MTOT / 128), 256, GEMM_SMEM>>>(
        ahi, alo, w1hi, w1lo, b1,
        nullptr, hhi, hlo,
        nullptr, nullptr, nullptr, nullptr, nullptr, nullptr, FF, DM);

    // FFN2: [8192,4096] @ [4096,1024] + b2, relu -> out
    gemm_split<2><<<dim3(DM / 256, MTOT / 128), 256, GEMM_SMEM>>>(
        hhi, hlo, w2hi, w2lo, b2,
        out, nullptr, nullptr,
        nullptr, nullptr, nullptr, nullptr, nullptr, nullptr, DM, FF);
}

// round 9
// speedup vs baseline: 1.7557x; 1.3166x over previous
#include <cuda_runtime.h>
#include <cuda_bf16.h>
#include <cuda_fp16.h>
#include <cstdint>

#define BATCH 4
#define CTX   2048
#define NEMB  1024
#define NH    16
#define HS    64
#define DM    1024
#define FF    4096
#define MTOT  (BATCH*CTX)   // 8192

typedef __nv_bfloat16 bf16;
typedef __half f16;

// ================= scratch =================
// attention operands stay bf16 hi/lo (3-term path)
__device__ bf16 g_qhi[(size_t)BATCH*NH*CTX*HS], g_qlo[(size_t)BATCH*NH*CTX*HS];
__device__ bf16 g_khi[(size_t)BATCH*NH*CTX*HS], g_klo[(size_t)BATCH*NH*CTX*HS];
__device__ bf16 g_vhi[(size_t)BATCH*NH*CTX*HS], g_vlo[(size_t)BATCH*NH*CTX*HS];
// GEMM activations: fp16 hi/lo, pre-scaled x256
__device__ f16 g_x16h[(size_t)MTOT*NEMB],  g_x16l[(size_t)MTOT*NEMB];
__device__ f16 g_a16h[(size_t)MTOT*DM],    g_a16l[(size_t)MTOT*DM];
__device__ f16 g_h16h[(size_t)MTOT*FF],    g_h16l[(size_t)MTOT*FF];
// GEMM weights: single fp16, [N,K]
__device__ f16 g_bq16[(size_t)3*DM*NEMB];
__device__ f16 g_w116[(size_t)FF*DM];
__device__ f16 g_w216[(size_t)DM*FF];

#define ASCALE 256.f
#define INVASC (1.f/256.f)

__device__ __forceinline__ uint32_t pack2bf(float a, float b) {
    __nv_bfloat162 p(__float2bfloat16(a), __float2bfloat16(b));
    return *reinterpret_cast<uint32_t*>(&p);
}
__device__ __forceinline__ uint32_t packlo2(float a, float b) {
    float ra = __bfloat162float(__float2bfloat16(a));
    float rb = __bfloat162float(__float2bfloat16(b));
    return pack2bf(a - ra, b - rb);
}
__device__ __forceinline__ uint32_t pack2h(float a, float b) {
    __half2 p = __floats2half2_rn(a, b);
    return *reinterpret_cast<uint32_t*>(&p);
}
__device__ __forceinline__ uint32_t packlo2h(float a, float b) {
    float ra = __half2float(__float2half_rn(a));
    float rb = __half2float(__float2half_rn(b));
    return pack2h(a - ra, b - rb);
}
__device__ __forceinline__ uint32_t smem_u32(const void* p) {
    uint32_t a;
    asm("{ .reg .u64 t; cvta.to.shared.u64 t, %1; cvt.u32.u64 %0, t; }" : "=r"(a) : "l"(p));
    return a;
}
__device__ __forceinline__ void cp16(uint32_t dst, const void* src) {
    asm volatile("cp.async.cg.shared.global [%0], [%1], 16;" :: "r"(dst), "l"(src));
}
#define CP_COMMIT() asm volatile("cp.async.commit_group;" ::: "memory")
#define CP_WAIT(n)  asm volatile("cp.async.wait_group %0;" :: "n"(n) : "memory")

__device__ __forceinline__ void ldm4(uint32_t* r, uint32_t addr) {
    asm volatile("ldmatrix.sync.aligned.m8n8.x4.shared.b16 {%0,%1,%2,%3}, [%4];"
        : "=r"(r[0]), "=r"(r[1]), "=r"(r[2]), "=r"(r[3]) : "r"(addr));
}
__device__ __forceinline__ void ldm4t(uint32_t* r, uint32_t addr) {
    asm volatile("ldmatrix.sync.aligned.m8n8.x4.trans.shared.b16 {%0,%1,%2,%3}, [%4];"
        : "=r"(r[0]), "=r"(r[1]), "=r"(r[2]), "=r"(r[3]) : "r"(addr));
}
__device__ __forceinline__ void mma_bf16(float* d, const uint32_t* a, const uint32_t* b) {
    asm volatile("mma.sync.aligned.m16n8k16.row.col.f32.bf16.bf16.f32 "
        "{%0,%1,%2,%3}, {%4,%5,%6,%7}, {%8,%9}, {%0,%1,%2,%3};"
        : "+f"(d[0]), "+f"(d[1]), "+f"(d[2]), "+f"(d[3])
        : "r"(a[0]), "r"(a[1]), "r"(a[2]), "r"(a[3]), "r"(b[0]), "r"(b[1]));
}
__device__ __forceinline__ void mma_f16(float* d, const uint32_t* a, const uint32_t* b) {
    asm volatile("mma.sync.aligned.m16n8k16.row.col.f32.f16.f16.f32 "
        "{%0,%1,%2,%3}, {%4,%5,%6,%7}, {%8,%9}, {%0,%1,%2,%3};"
        : "+f"(d[0]), "+f"(d[1]), "+f"(d[2]), "+f"(d[3])
        : "r"(a[0]), "r"(a[1]), "r"(a[2]), "r"(a[3]), "r"(b[0]), "r"(b[1]));
}

// ================= split / transpose kernels =================
// x -> fp16 hi/lo, scaled x256
__global__ __launch_bounds__(256) void split_x_kernel(const float* __restrict__ x,
                                                      f16* __restrict__ hi, f16* __restrict__ lo)
{
    size_t i = (size_t)blockIdx.x * 256 + threadIdx.x;
    float4 v = ((const float4*)x)[i];
    float s0 = v.x * ASCALE, s1 = v.y * ASCALE, s2 = v.z * ASCALE, s3 = v.w * ASCALE;
    ((uint2*)hi)[i] = make_uint2(pack2h(s0, s1), pack2h(s2, s3));
    ((uint2*)lo)[i] = make_uint2(packlo2h(s0, s1), packlo2h(s2, s3));
}

// W [K,N] row-major -> out [N,K] single fp16
__global__ __launch_bounds__(256) void transpose_h(const float* __restrict__ W,
                                                   f16* __restrict__ out, int K, int N)
{
    __shared__ float t[32][33];
    int n0 = blockIdx.x * 32, k0 = blockIdx.y * 32;
    int tx = threadIdx.x, ty = threadIdx.y;
#pragma unroll
    for (int i = ty; i < 32; i += 8)
        t[i][tx] = W[(size_t)(k0 + i) * N + n0 + tx];
    __syncthreads();
#pragma unroll
    for (int i = ty; i < 32; i += 8)
        out[(size_t)(n0 + i) * K + k0 + tx] = __float2half_rn(t[tx][i]);
}

// Wq/Wk/Wv [H,C,D] -> bqkv[n = sel*1024 + h*64 + d][k = c], single fp16
__global__ __launch_bounds__(256) void qkv_transpose_h(const float* __restrict__ Wq,
                                                       const float* __restrict__ Wk,
                                                       const float* __restrict__ Wv,
                                                       f16* __restrict__ out)
{
    __shared__ float t[32][33];
    int sel = blockIdx.z >> 4, h = blockIdx.z & 15;
    const float* W = (sel == 0 ? Wq : sel == 1 ? Wk : Wv) + (size_t)h * NEMB * HS;
    int c0 = blockIdx.x * 32, d0 = blockIdx.y * 32;
    int tx = threadIdx.x, ty = threadIdx.y;
#pragma unroll
    for (int i = ty; i < 32; i += 8)
        t[i][tx] = W[(size_t)(c0 + i) * HS + d0 + tx];
    __syncthreads();
    int nbase = sel * DM + h * HS + d0;
#pragma unroll
    for (int i = ty; i < 32; i += 8)
        out[(size_t)(nbase + i) * NEMB + c0 + tx] = __float2half_rn(t[tx][i]);
}

// ================= fp16 2-term GEMM, 128x256 CTA tile, 4-stage =================
// D = (Ah + Al) * Bh, A pre-scaled x256, rescale 1/256 in epilogue.
// MODE 0: scatter split bf16 -> q/k/v [B,H,T,D] hi/lo
// MODE 1: +bias, write fp16 x256 hi/lo (FFN1 -> h)
// MODE 2: +bias, relu, write fp32 (FFN2 -> out)
#define ROWB    80
#define TA      (128*ROWB)   // 10240
#define TBL     (256*ROWB)   // 20480
#define OFF_AH  0
#define OFF_AL  (TA)
#define OFF_BH  (2*TA)
#define STAGE_B (2*TA + TBL)     // 40960
#define NSTAGE  4
#define GEMM_SMEM (NSTAGE*STAGE_B)   // 163840

template <int MODE>
__global__ __launch_bounds__(256, 1)
void gemm_f16(const f16* __restrict__ Ahi, const f16* __restrict__ Alo,
              const f16* __restrict__ Bh,
              const float* __restrict__ bias,
              float* __restrict__ out_f, f16* __restrict__ out_hi, f16* __restrict__ out_lo,
              bf16* __restrict__ qhi, bf16* __restrict__ qlo,
              bf16* __restrict__ khi, bf16* __restrict__ klo,
              bf16* __restrict__ vhi, bf16* __restrict__ vlo,
              int N, int K)
{
    extern __shared__ char smem[];
    uint32_t sb = smem_u32(smem);

    int tid = threadIdx.x, wid = tid >> 5, lid = tid & 31;
    int wm = wid >> 2, wn = wid & 3;          // warp tile 64(M) x 64(N)
    int bx = blockIdx.x, by = blockIdx.y;

    const f16* aH = Ahi + (size_t)by * 128 * K;
    const f16* aL = Alo + (size_t)by * 128 * K;
    const f16* bH = Bh + (size_t)bx * 256 * K;

    float acc[4][8][4];
#pragma unroll
    for (int i = 0; i < 4; i++)
#pragma unroll
        for (int j = 0; j < 8; j++)
#pragma unroll
            for (int l = 0; l < 4; l++) acc[i][j][l] = 0.f;

    int ITERS = K >> 5;

#define ISSUE(st, k0) do {                                                         \
        uint32_t _b = sb + (st) * STAGE_B;                                         \
        _Pragma("unroll")                                                          \
        for (int _i = 0; _i < 2; _i++) {                                           \
            int _c = tid + _i * 256; int _r = _c >> 2, _q = _c & 3;                \
            uint32_t _so = (uint32_t)(_r * ROWB + _q * 16);                        \
            size_t _g = (size_t)_r * K + (k0) + _q * 8;                            \
            cp16(_b + OFF_AH + _so, aH + _g);                                      \
            cp16(_b + OFF_AL + _so, aL + _g);                                      \
        }                                                                          \
        _Pragma("unroll")                                                          \
        for (int _i = 0; _i < 4; _i++) {                                           \
            int _c = tid + _i * 256; int _r = _c >> 2, _q = _c & 3;                \
            uint32_t _so = (uint32_t)(_r * ROWB + _q * 16);                        \
            size_t _g = (size_t)_r * K + (k0) + _q * 8;                            \
            cp16(_b + OFF_BH + _so, bH + _g);                                      \
        }                                                                          \
    } while (0)

    ISSUE(0, 0);  CP_COMMIT();
    ISSUE(1, 32); CP_COMMIT();
    ISSUE(2, 64); CP_COMMIT();

    int g = lid >> 3, rr = lid & 7;
    uint32_t a_row_off = (uint32_t)(((g & 1) * 8 + rr) * ROWB + (g >> 1) * 16);
    uint32_t b_row_off = (uint32_t)(((g >> 1) * 8 + rr) * ROWB + (g & 1) * 16);

    for (int it = 0; it < ITERS; it++) {
        CP_WAIT(NSTAGE - 2);        // stage it resident
        __syncthreads();            // all warps done with stage it-1 (aliased by it+3)
        int pre = it + NSTAGE - 1;
        if (pre < ITERS) { ISSUE(pre % NSTAGE, pre * 32); }
        CP_COMMIT();

        uint32_t base = sb + (it % NSTAGE) * STAGE_B;
#pragma unroll
        for (int ks = 0; ks < 2; ks++) {
            uint32_t ah[4][4], al[4][4], bh[4][4];
#pragma unroll
            for (int mi = 0; mi < 4; mi++) {
                uint32_t off = (uint32_t)((wm * 64 + mi * 16) * ROWB + ks * 32) + a_row_off;
                ldm4(ah[mi], base + OFF_AH + off);
                ldm4(al[mi], base + OFF_AL + off);
            }
#pragma unroll
            for (int p = 0; p < 4; p++) {
                uint32_t off = (uint32_t)((wn * 64 + p * 16) * ROWB + ks * 32) + b_row_off;
                ldm4(bh[p], base + OFF_BH + off);
            }
            // 2 passes: hi and lo vs same B
#pragma unroll
            for (int mi = 0; mi < 4; mi++)
#pragma unroll
                for (int ni = 0; ni < 8; ni++)
                    mma_f16(acc[mi][ni], ah[mi], &bh[ni >> 1][(ni & 1) * 2]);
#pragma unroll
            for (int mi = 0; mi < 4; mi++)
#pragma unroll
                for (int ni = 0; ni < 8; ni++)
                    mma_f16(acc[mi][ni], al[mi], &bh[ni >> 1][(ni & 1) * 2]);
        }
    }
#undef ISSUE

    // ---------------- epilogue (rescale 1/256) ----------------
    int t4 = lid >> 2, t2 = (lid & 3) * 2;
#pragma unroll
    for (int mi = 0; mi < 4; mi++) {
#pragma unroll
        for (int ni = 0; ni < 8; ni++) {
            int n = bx * 256 + wn * 64 + ni * 8 + t2;
            int m0 = by * 128 + wm * 64 + mi * 16 + t4;
            float bn0 = 0.f, bn1 = 0.f;
            if (MODE != 0) { bn0 = bias[n]; bn1 = bias[n + 1]; }
#pragma unroll
            for (int half = 0; half < 2; half++) {
                int m = m0 + half * 8;
                float v0 = acc[mi][ni][half * 2]     * INVASC;
                float v1 = acc[mi][ni][half * 2 + 1] * INVASC;
                if (MODE == 0) {
                    int b = m >> 11, t = m & (CTX - 1);
                    int sel = n >> 10, hh = (n & 1023) >> 6, d0 = n & 63;
                    bf16* hi = (sel == 0) ? qhi : (sel == 1 ? khi : vhi);
                    bf16* lo = (sel == 0) ? qlo : (sel == 1 ? klo : vlo);
                    size_t o = ((size_t)(b * NH + hh) * CTX + t) * HS + d0;
                    *(uint32_t*)(hi + o) = pack2bf(v0, v1);
                    *(uint32_t*)(lo + o) = packlo2(v0, v1);
                } else if (MODE == 1) {
                    float s0 = (v0 + bn0) * ASCALE;
                    float s1 = (v1 + bn1) * ASCALE;
                    size_t o = (size_t)m * N + n;
                    *(uint32_t*)(out_hi + o) = pack2h(s0, s1);
                    *(uint32_t*)(out_lo + o) = packlo2h(s0, s1);
                } else {
                    v0 = fmaxf(v0 + bn0, 0.f);
                    v1 = fmaxf(v1 + bn1, 0.f);
                    *(float2*)(out_f + (size_t)m * N + n) = make_float2(v0, v1);
                }
            }
        }
    }
}

// ================= mma.sync causal flash attention (3-term bf16) =================
// 128 queries/CTA, 8 warps x 16 rows; Bc=64 key tile; double-buffered K/V.
// V stored [T,D]; PV B-fragments via ldmatrix.trans.
// Epilogue writes fp16 x256 hi/lo for FFN1's A operand.
#define PADB   144
#define QTILE  (128*PADB)       // 18432
#define KVTILE (64*PADB)        // 9216
#define ASTAGE (4*KVTILE)       // 36864
#define ATTN_SMEM (2*QTILE + 2*ASTAGE)   // 110592

__global__ __launch_bounds__(256, 1)
void attn_mma()
{
    extern __shared__ char smem[];
    uint32_t sb = smem_u32(smem);
    int tid = threadIdx.x, wid = tid >> 5, lid = tid & 31;
    int qt = blockIdx.x, h = blockIdx.y, b = blockIdx.z;
    int q0 = qt * 128;
    int wm = wid;
    int g = lid >> 3, rr = lid & 7;
    uint32_t a_off = (uint32_t)(((g & 1) * 8 + rr) * PADB + (g >> 1) * 16);
    uint32_t b_off = (uint32_t)(((g >> 1) * 8 + rr) * PADB + (g & 1) * 16);
    int t4 = lid >> 2, t2 = lid & 3;

    size_t hb = (size_t)(b * NH + h);
    const bf16* qhB = g_qhi + hb * CTX * HS;
    const bf16* qlB = g_qlo + hb * CTX * HS;
    const bf16* khB = g_khi + hb * CTX * HS;
    const bf16* klB = g_klo + hb * CTX * HS;
    const bf16* vhB = g_vhi + hb * CTX * HS;
    const bf16* vlB = g_vlo + hb * CTX * HS;

    // Q tile (128 x 64) hi/lo
#pragma unroll
    for (int i = 0; i < 4; i++) {
        int idx = tid + i * 256;
        int r = idx >> 3, ch = idx & 7;
        uint32_t so = (uint32_t)(r * PADB + ch * 16);
        size_t gg = (size_t)(q0 + r) * HS + ch * 8;
        cp16(sb + so, qhB + gg);
        cp16(sb + QTILE + so, qlB + gg);
    }
    CP_COMMIT();

#define LOAD_TILE(st, kb_) do {                                            \
        uint32_t bs = sb + 2 * QTILE + (st) * ASTAGE;                      \
        for (int i_ = 0; i_ < 2; i_++) {                                   \
            int idx_ = tid + i_ * 256;                                     \
            int r_ = idx_ >> 3, ch_ = idx_ & 7;                            \
            uint32_t so_ = (uint32_t)(r_ * PADB + ch_ * 16);               \
            size_t kg_ = (size_t)((kb_) + r_) * HS + ch_ * 8;              \
            cp16(bs + so_, khB + kg_);                                     \
            cp16(bs + KVTILE + so_, klB + kg_);                            \
            cp16(bs + 2 * KVTILE + so_, vhB + kg_);                        \
            cp16(bs + 3 * KVTILE + so_, vlB + kg_);                        \
        } } while (0)

    LOAD_TILE(0, 0);
    CP_COMMIT();

    uint32_t qfh[4][4], qfl[4][4];
    float of[8][4];
#pragma unroll
    for (int i = 0; i < 8; i++)
#pragma unroll
        for (int j = 0; j < 4; j++) of[i][j] = 0.f;
    float m0 = -1e30f, m1 = -1e30f, l0 = 0.f, l1 = 0.f;
    bool qload = false;

    int nkt = 2 * qt + 2;
    for (int kt = 0; kt < nkt; kt++) {
        int kb = kt * 64;
        if (kt + 1 < nkt) { LOAD_TILE((kt + 1) & 1, kb + 64); CP_COMMIT(); CP_WAIT(1); }
        else { CP_WAIT(0); }
        __syncthreads();
        if (!qload) {
#pragma unroll
            for (int ks = 0; ks < 4; ks++) {
                uint32_t qo = (uint32_t)((wm * 16) * PADB + ks * 32) + a_off;
                ldm4(qfh[ks], sb + qo);
                ldm4(qfl[ks], sb + QTILE + qo);
            }
            qload = true;
        }
        if (q0 + wm * 16 + 15 >= kb) {
            uint32_t base = sb + 2 * QTILE + (kt & 1) * ASTAGE;
            float sf[8][4];
#pragma unroll
            for (int i = 0; i < 8; i++)
#pragma unroll
                for (int j = 0; j < 4; j++) sf[i][j] = 0.f;

#pragma unroll
            for (int ks = 0; ks < 4; ks++) {
                uint32_t bh[4][4], bl[4][4];
#pragma unroll
                for (int p = 0; p < 4; p++) {
                    uint32_t off = (uint32_t)((p * 16) * PADB + ks * 32) + b_off;
                    ldm4(bh[p], base + off);
                    ldm4(bl[p], base + KVTILE + off);
                }
#pragma unroll
                for (int ni = 0; ni < 8; ni++)
                    mma_bf16(sf[ni], qfh[ks], &bh[ni >> 1][(ni & 1) * 2]);
#pragma unroll
                for (int ni = 0; ni < 8; ni++)
                    mma_bf16(sf[ni], qfh[ks], &bl[ni >> 1][(ni & 1) * 2]);
#pragma unroll
                for (int ni = 0; ni < 8; ni++)
                    mma_bf16(sf[ni], qfl[ks], &bh[ni >> 1][(ni & 1) * 2]);
            }

            int row0 = q0 + wm * 16 + t4, row1 = row0 + 8;
            bool needm = (kb + 63 > q0 + wm * 16);
            float mx0 = -1e30f, mx1 = -1e30f;
#pragma unroll
            for (int ni = 0; ni < 8; ni++) {
                int c = kb + ni * 8 + t2 * 2;
                float s0 = sf[ni][0] * 0.125f, s1 = sf[ni][1] * 0.125f;
                float s2 = sf[ni][2] * 0.125f, s3 = sf[ni][3] * 0.125f;
                if (needm) {
                    if (c > row0)     s0 = -1e30f;
                    if (c + 1 > row0) s1 = -1e30f;
                    if (c > row1)     s2 = -1e30f;
                    if (c + 1 > row1) s3 = -1e30f;
                }
                sf[ni][0] = s0; sf[ni][1] = s1; sf[ni][2] = s2; sf[ni][3] = s3;
                mx0 = fmaxf(mx0, fmaxf(s0, s1));
                mx1 = fmaxf(mx1, fmaxf(s2, s3));
            }
            mx0 = fmaxf(mx0, __shfl_xor_sync(0xffffffffu, mx0, 1));
            mx0 = fmaxf(mx0, __shfl_xor_sync(0xffffffffu, mx0, 2));
            mx1 = fmaxf(mx1, __shfl_xor_sync(0xffffffffu, mx1, 1));
            mx1 = fmaxf(mx1, __shfl_xor_sync(0xffffffffu, mx1, 2));
            float nm0 = fmaxf(m0, mx0), nm1 = fmaxf(m1, mx1);
            float cr0 = __expf(m0 - nm0), cr1 = __expf(m1 - nm1);
            m0 = nm0; m1 = nm1;
            l0 *= cr0; l1 *= cr1;
#pragma unroll
            for (int ni = 0; ni < 8; ni++) {
                float p0 = __expf(sf[ni][0] - m0), p1 = __expf(sf[ni][1] - m0);
                float p2 = __expf(sf[ni][2] - m1), p3 = __expf(sf[ni][3] - m1);
                sf[ni][0] = p0; sf[ni][1] = p1; sf[ni][2] = p2; sf[ni][3] = p3;
                l0 += p0 + p1; l1 += p2 + p3;
                of[ni][0] *= cr0; of[ni][1] *= cr0; of[ni][2] *= cr1; of[ni][3] *= cr1;
            }

#pragma unroll
            for (int ks2 = 0; ks2 < 4; ks2++) {
                int n0b = 2 * ks2, n1b = n0b + 1;
                uint32_t pah[4], pal[4];
                pah[0] = pack2bf(sf[n0b][0], sf[n0b][1]);
                pah[1] = pack2bf(sf[n0b][2], sf[n0b][3]);
                pah[2] = pack2bf(sf[n1b][0], sf[n1b][1]);
                pah[3] = pack2bf(sf[n1b][2], sf[n1b][3]);
                pal[0] = packlo2(sf[n0b][0], sf[n0b][1]);
                pal[1] = packlo2(sf[n0b][2], sf[n0b][3]);
                pal[2] = packlo2(sf[n1b][0], sf[n1b][1]);
                pal[3] = packlo2(sf[n1b][2], sf[n1b][3]);
                uint32_t vh[4][4], vl[4][4];
#pragma unroll
                for (int p = 0; p < 4; p++) {
                    uint32_t off = (uint32_t)((ks2 * 16) * PADB + p * 32) + a_off;
                    ldm4t(vh[p], base + 2 * KVTILE + off);
                    ldm4t(vl[p], base + 3 * KVTILE + off);
                }
#pragma unroll
                for (int ni = 0; ni < 8; ni++)
                    mma_bf16(of[ni], pah, &vh[ni >> 1][(ni & 1) * 2]);
#pragma unroll
                for (int ni = 0; ni < 8; ni++)
                    mma_bf16(of[ni], pah, &vl[ni >> 1][(ni & 1) * 2]);
#pragma unroll
                for (int ni = 0; ni < 8; ni++)
                    mma_bf16(of[ni], pal, &vh[ni >> 1][(ni & 1) * 2]);
            }
        }
        __syncthreads();
    }
#undef LOAD_TILE

    l0 += __shfl_xor_sync(0xffffffffu, l0, 1);
    l0 += __shfl_xor_sync(0xffffffffu, l0, 2);
    l1 += __shfl_xor_sync(0xffffffffu, l1, 1);
    l1 += __shfl_xor_sync(0xffffffffu, l1, 2);
    float inv0 = ASCALE / l0, inv1 = ASCALE / l1;   // fold x256 A-scale into normalize

    int row0 = q0 + wm * 16 + t4;
#pragma unroll
    for (int ni = 0; ni < 8; ni++) {
        int col = h * HS + ni * 8 + t2 * 2;
        float s0 = of[ni][0] * inv0, s1 = of[ni][1] * inv0;
        float s2 = of[ni][2] * inv1, s3 = of[ni][3] * inv1;
        size_t o0 = ((size_t)(b * CTX) + row0) * DM + col;
        size_t o1 = o0 + (size_t)8 * DM;
        *(uint32_t*)(g_a16h + o0) = pack2h(s0, s1);
        *(uint32_t*)(g_a16l + o0) = packlo2h(s0, s1);
        *(uint32_t*)(g_a16h + o1) = pack2h(s2, s3);
        *(uint32_t*)(g_a16l + o1) = packlo2h(s2, s3);
    }
}

// ================= launch =================
extern "C" void kernel_launch(void* const* d_in, const int* in_sizes, int n_in,
                              void* d_out, int out_size)
{
    const float* x  = (const float*)d_in[0];
    const float* Wq = (const float*)d_in[1];
    const float* Wk = (const float*)d_in[2];
    const float* Wv = (const float*)d_in[3];
    const float* W1 = (const float*)d_in[4];
    const float* b1 = (const float*)d_in[5];
    const float* W2 = (const float*)d_in[6];
    const float* b2 = (const float*)d_in[7];
    float* out = (float*)d_out;

    bf16 *qhi, *qlo, *khi, *klo, *vhi, *vlo;
    f16 *x16h, *x16l, *a16h, *a16l, *h16h, *h16l, *bq16, *w116, *w216;
    cudaGetSymbolAddress((void**)&qhi, g_qhi);
    cudaGetSymbolAddress((void**)&qlo, g_qlo);
    cudaGetSymbolAddress((void**)&khi, g_khi);
    cudaGetSymbolAddress((void**)&klo, g_klo);
    cudaGetSymbolAddress((void**)&vhi, g_vhi);
    cudaGetSymbolAddress((void**)&vlo, g_vlo);
    cudaGetSymbolAddress((void**)&x16h, g_x16h);
    cudaGetSymbolAddress((void**)&x16l, g_x16l);
    cudaGetSymbolAddress((void**)&a16h, g_a16h);
    cudaGetSymbolAddress((void**)&a16l, g_a16l);
    cudaGetSymbolAddress((void**)&h16h, g_h16h);
    cudaGetSymbolAddress((void**)&h16l, g_h16l);
    cudaGetSymbolAddress((void**)&bq16, g_bq16);
    cudaGetSymbolAddress((void**)&w116, g_w116);
    cudaGetSymbolAddress((void**)&w216, g_w216);

    cudaFuncSetAttribute(gemm_f16<0>, cudaFuncAttributeMaxDynamicSharedMemorySize, GEMM_SMEM);
    cudaFuncSetAttribute(gemm_f16<1>, cudaFuncAttributeMaxDynamicSharedMemorySize, GEMM_SMEM);
    cudaFuncSetAttribute(gemm_f16<2>, cudaFuncAttributeMaxDynamicSharedMemorySize, GEMM_SMEM);
    cudaFuncSetAttribute(attn_mma, cudaFuncAttributeMaxDynamicSharedMemorySize, ATTN_SMEM);

    // input conversions
    split_x_kernel<<<(size_t)MTOT * NEMB / 1024, 256>>>(x, x16h, x16l);
    qkv_transpose_h<<<dim3(NEMB / 32, HS / 32, 48), dim3(32, 8)>>>(Wq, Wk, Wv, bq16);
    transpose_h<<<dim3(FF / 32, DM / 32), dim3(32, 8)>>>(W1, w116, DM, FF);
    transpose_h<<<dim3(DM / 32, FF / 32), dim3(32, 8)>>>(W2, w216, FF, DM);

    // QKV: [8192,1024] @ [1024,3072] -> split bf16 q/k/v [B,H,T,D]
    gemm_f16<0><<<dim3(3 * DM / 256, MTOT / 128), 256, GEMM_SMEM>>>(
        x16h, x16l, bq16, nullptr,
        nullptr, nullptr, nullptr,
        qhi, qlo, khi, klo, vhi, vlo, 3 * DM, NEMB);

    // attention -> att fp16 x256 hi/lo
    attn_mma<<<dim3(CTX / 128, NH, BATCH), 256, ATTN_SMEM>>>();

    // FFN1: [8192,1024] @ [1024,4096] + b1 -> h fp16 x256 hi/lo
    gemm_f16<1><<<dim3(FF / 256, MTOT / 128), 256, GEMM_SMEM>>>(
        a16h, a16l, w116, b1,
        nullptr, h16h, h16l,
        nullptr, nullptr, nullptr, nullptr, nullptr, nullptr, FF, DM);

    // FFN2: [8192,4096] @ [4096,1024] + b2, relu -> out
    gemm_f16<2><<<dim3(DM / 256, MTOT / 128), 256, GEMM_SMEM>>>(
        h16h, h16l, w216, b2,
        out, nullptr, nullptr,
        nullptr, nullptr, nullptr, nullptr, nullptr, nullptr, DM, FF);
}

// round 10
// speedup vs baseline: 1.9892x; 1.1330x over previous
#include <cuda_runtime.h>
#include <cuda_bf16.h>
#include <cuda_fp16.h>
#include <cstdint>

#define BATCH 4
#define CTX   2048
#define NEMB  1024
#define NH    16
#define HS    64
#define DM    1024
#define FF    4096
#define MTOT  (BATCH*CTX)   // 8192

typedef __nv_bfloat16 bf16;
typedef __half f16;

// ================= scratch =================
// attention operands stay bf16 hi/lo (3-term path)
__device__ bf16 g_qhi[(size_t)BATCH*NH*CTX*HS], g_qlo[(size_t)BATCH*NH*CTX*HS];
__device__ bf16 g_khi[(size_t)BATCH*NH*CTX*HS], g_klo[(size_t)BATCH*NH*CTX*HS];
__device__ bf16 g_vhi[(size_t)BATCH*NH*CTX*HS], g_vlo[(size_t)BATCH*NH*CTX*HS];
// GEMM activations: fp16, pre-scaled x256 (x and attention-out keep hi/lo; h is hi only)
__device__ f16 g_x16h[(size_t)MTOT*NEMB],  g_x16l[(size_t)MTOT*NEMB];
__device__ f16 g_a16h[(size_t)MTOT*DM],    g_a16l[(size_t)MTOT*DM];
__device__ f16 g_h16h[(size_t)MTOT*FF];
// GEMM weights: single fp16, [N,K]
__device__ f16 g_bq16[(size_t)3*DM*NEMB];
__device__ f16 g_w116[(size_t)FF*DM];
__device__ f16 g_w216[(size_t)DM*FF];

#define ASCALE 256.f
#define INVASC (1.f/256.f)

__device__ __forceinline__ uint32_t pack2bf(float a, float b) {
    __nv_bfloat162 p(__float2bfloat16(a), __float2bfloat16(b));
    return *reinterpret_cast<uint32_t*>(&p);
}
__device__ __forceinline__ uint32_t packlo2(float a, float b) {
    float ra = __bfloat162float(__float2bfloat16(a));
    float rb = __bfloat162float(__float2bfloat16(b));
    return pack2bf(a - ra, b - rb);
}
__device__ __forceinline__ uint32_t pack2h(float a, float b) {
    __half2 p = __floats2half2_rn(a, b);
    return *reinterpret_cast<uint32_t*>(&p);
}
__device__ __forceinline__ uint32_t packlo2h(float a, float b) {
    float ra = __half2float(__float2half_rn(a));
    float rb = __half2float(__float2half_rn(b));
    return pack2h(a - ra, b - rb);
}
__device__ __forceinline__ uint32_t smem_u32(const void* p) {
    uint32_t a;
    asm("{ .reg .u64 t; cvta.to.shared.u64 t, %1; cvt.u32.u64 %0, t; }" : "=r"(a) : "l"(p));
    return a;
}
__device__ __forceinline__ void cp16(uint32_t dst, const void* src) {
    asm volatile("cp.async.cg.shared.global [%0], [%1], 16;" :: "r"(dst), "l"(src));
}
#define CP_COMMIT() asm volatile("cp.async.commit_group;" ::: "memory")
#define CP_WAIT(n)  asm volatile("cp.async.wait_group %0;" :: "n"(n) : "memory")

__device__ __forceinline__ void ldm4(uint32_t* r, uint32_t addr) {
    asm volatile("ldmatrix.sync.aligned.m8n8.x4.shared.b16 {%0,%1,%2,%3}, [%4];"
        : "=r"(r[0]), "=r"(r[1]), "=r"(r[2]), "=r"(r[3]) : "r"(addr));
}
__device__ __forceinline__ void ldm4t(uint32_t* r, uint32_t addr) {
    asm volatile("ldmatrix.sync.aligned.m8n8.x4.trans.shared.b16 {%0,%1,%2,%3}, [%4];"
        : "=r"(r[0]), "=r"(r[1]), "=r"(r[2]), "=r"(r[3]) : "r"(addr));
}
__device__ __forceinline__ void mma_bf16(float* d, const uint32_t* a, const uint32_t* b) {
    asm volatile("mma.sync.aligned.m16n8k16.row.col.f32.bf16.bf16.f32 "
        "{%0,%1,%2,%3}, {%4,%5,%6,%7}, {%8,%9}, {%0,%1,%2,%3};"
        : "+f"(d[0]), "+f"(d[1]), "+f"(d[2]), "+f"(d[3])
        : "r"(a[0]), "r"(a[1]), "r"(a[2]), "r"(a[3]), "r"(b[0]), "r"(b[1]));
}
__device__ __forceinline__ void mma_f16(float* d, const uint32_t* a, const uint32_t* b) {
    asm volatile("mma.sync.aligned.m16n8k16.row.col.f32.f16.f16.f32 "
        "{%0,%1,%2,%3}, {%4,%5,%6,%7}, {%8,%9}, {%0,%1,%2,%3};"
        : "+f"(d[0]), "+f"(d[1]), "+f"(d[2]), "+f"(d[3])
        : "r"(a[0]), "r"(a[1]), "r"(a[2]), "r"(a[3]), "r"(b[0]), "r"(b[1]));
}

// ================= split / transpose kernels =================
// x -> fp16 hi/lo, scaled x256
__global__ __launch_bounds__(256) void split_x_kernel(const float* __restrict__ x,
                                                      f16* __restrict__ hi, f16* __restrict__ lo)
{
    size_t i = (size_t)blockIdx.x * 256 + threadIdx.x;
    float4 v = ((const float4*)x)[i];
    float s0 = v.x * ASCALE, s1 = v.y * ASCALE, s2 = v.z * ASCALE, s3 = v.w * ASCALE;
    ((uint2*)hi)[i] = make_uint2(pack2h(s0, s1), pack2h(s2, s3));
    ((uint2*)lo)[i] = make_uint2(packlo2h(s0, s1), packlo2h(s2, s3));
}

// W [K,N] row-major -> out [N,K] single fp16
__global__ __launch_bounds__(256) void transpose_h(const float* __restrict__ W,
                                                   f16* __restrict__ out, int K, int N)
{
    __shared__ float t[32][33];
    int n0 = blockIdx.x * 32, k0 = blockIdx.y * 32;
    int tx = threadIdx.x, ty = threadIdx.y;
#pragma unroll
    for (int i = ty; i < 32; i += 8)
        t[i][tx] = W[(size_t)(k0 + i) * N + n0 + tx];
    __syncthreads();
#pragma unroll
    for (int i = ty; i < 32; i += 8)
        out[(size_t)(n0 + i) * K + k0 + tx] = __float2half_rn(t[tx][i]);
}

// Wq/Wk/Wv [H,C,D] -> bqkv[n = sel*1024 + h*64 + d][k = c], single fp16
__global__ __launch_bounds__(256) void qkv_transpose_h(const float* __restrict__ Wq,
                                                       const float* __restrict__ Wk,
                                                       const float* __restrict__ Wv,
                                                       f16* __restrict__ out)
{
    __shared__ float t[32][33];
    int sel = blockIdx.z >> 4, h = blockIdx.z & 15;
    const float* W = (sel == 0 ? Wq : sel == 1 ? Wk : Wv) + (size_t)h * NEMB * HS;
    int c0 = blockIdx.x * 32, d0 = blockIdx.y * 32;
    int tx = threadIdx.x, ty = threadIdx.y;
#pragma unroll
    for (int i = ty; i < 32; i += 8)
        t[i][tx] = W[(size_t)(c0 + i) * HS + d0 + tx];
    __syncthreads();
    int nbase = sel * DM + h * HS + d0;
#pragma unroll
    for (int i = ty; i < 32; i += 8)
        out[(size_t)(nbase + i) * NEMB + c0 + tx] = __float2half_rn(t[tx][i]);
}

// ================= fp16 GEMM, 128x256 CTA tile, 4-stage =================
// SPLITA=1: D = (Ah + Al) * Bh;  SPLITA=0: D = Ah * Bh.  A pre-scaled x256.
// MODE 0: scatter split bf16 -> q/k/v [B,H,T,D] hi/lo
// MODE 1: +bias, write fp16 x256 hi only (FFN1 -> h)
// MODE 2: +bias, relu, write fp32 (FFN2 -> out)
#define ROWB    80
#define TA      (128*ROWB)   // 10240
#define TBL     (256*ROWB)   // 20480
#define OFF_AH  0
#define OFF_AL  (TA)
#define OFF_BH  (2*TA)
#define STAGE_B (2*TA + TBL)     // 40960
#define NSTAGE  4
#define GEMM_SMEM (NSTAGE*STAGE_B)   // 163840

template <int MODE, int SPLITA>
__global__ __launch_bounds__(256, 1)
void gemm_f16(const f16* __restrict__ Ahi, const f16* __restrict__ Alo,
              const f16* __restrict__ Bh,
              const float* __restrict__ bias,
              float* __restrict__ out_f, f16* __restrict__ out_hi,
              bf16* __restrict__ qhi, bf16* __restrict__ qlo,
              bf16* __restrict__ khi, bf16* __restrict__ klo,
              bf16* __restrict__ vhi, bf16* __restrict__ vlo,
              int N, int K)
{
    extern __shared__ char smem[];
    uint32_t sb = smem_u32(smem);

    int tid = threadIdx.x, wid = tid >> 5, lid = tid & 31;
    int wm = wid >> 2, wn = wid & 3;          // warp tile 64(M) x 64(N)
    int bx = blockIdx.x, by = blockIdx.y;

    const f16* aH = Ahi + (size_t)by * 128 * K;
    const f16* aL = SPLITA ? (Alo + (size_t)by * 128 * K) : aH;
    const f16* bH = Bh + (size_t)bx * 256 * K;

    float acc[4][8][4];
#pragma unroll
    for (int i = 0; i < 4; i++)
#pragma unroll
        for (int j = 0; j < 8; j++)
#pragma unroll
            for (int l = 0; l < 4; l++) acc[i][j][l] = 0.f;

    int ITERS = K >> 5;

#define ISSUE(st, k0) do {                                                         \
        uint32_t _b = sb + (st) * STAGE_B;                                         \
        _Pragma("unroll")                                                          \
        for (int _i = 0; _i < 2; _i++) {                                           \
            int _c = tid + _i * 256; int _r = _c >> 2, _q = _c & 3;                \
            uint32_t _so = (uint32_t)(_r * ROWB + _q * 16);                        \
            size_t _g = (size_t)_r * K + (k0) + _q * 8;                            \
            cp16(_b + OFF_AH + _so, aH + _g);                                      \
            if (SPLITA) cp16(_b + OFF_AL + _so, aL + _g);                          \
        }                                                                          \
        _Pragma("unroll")                                                          \
        for (int _i = 0; _i < 4; _i++) {                                           \
            int _c = tid + _i * 256; int _r = _c >> 2, _q = _c & 3;                \
            uint32_t _so = (uint32_t)(_r * ROWB + _q * 16);                        \
            size_t _g = (size_t)_r * K + (k0) + _q * 8;                            \
            cp16(_b + OFF_BH + _so, bH + _g);                                      \
        }                                                                          \
    } while (0)

    ISSUE(0, 0);  CP_COMMIT();
    ISSUE(1, 32); CP_COMMIT();
    ISSUE(2, 64); CP_COMMIT();

    int g = lid >> 3, rr = lid & 7;
    uint32_t a_row_off = (uint32_t)(((g & 1) * 8 + rr) * ROWB + (g >> 1) * 16);
    uint32_t b_row_off = (uint32_t)(((g >> 1) * 8 + rr) * ROWB + (g & 1) * 16);

    for (int it = 0; it < ITERS; it++) {
        CP_WAIT(NSTAGE - 2);        // stage it resident
        __syncthreads();            // all warps done with stage it-1 (aliased by it+3)
        int pre = it + NSTAGE - 1;
        if (pre < ITERS) { ISSUE(pre % NSTAGE, pre * 32); }
        CP_COMMIT();

        uint32_t base = sb + (it % NSTAGE) * STAGE_B;
#pragma unroll
        for (int ks = 0; ks < 2; ks++) {
            uint32_t ah[4][4], al[4][4], bh[4][4];
#pragma unroll
            for (int mi = 0; mi < 4; mi++) {
                uint32_t off = (uint32_t)((wm * 64 + mi * 16) * ROWB + ks * 32) + a_row_off;
                ldm4(ah[mi], base + OFF_AH + off);
                if (SPLITA) ldm4(al[mi], base + OFF_AL + off);
            }
#pragma unroll
            for (int p = 0; p < 4; p++) {
                uint32_t off = (uint32_t)((wn * 64 + p * 16) * ROWB + ks * 32) + b_row_off;
                ldm4(bh[p], base + OFF_BH + off);
            }
#pragma unroll
            for (int mi = 0; mi < 4; mi++)
#pragma unroll
                for (int ni = 0; ni < 8; ni++)
                    mma_f16(acc[mi][ni], ah[mi], &bh[ni >> 1][(ni & 1) * 2]);
            if (SPLITA) {
#pragma unroll
                for (int mi = 0; mi < 4; mi++)
#pragma unroll
                    for (int ni = 0; ni < 8; ni++)
                        mma_f16(acc[mi][ni], al[mi], &bh[ni >> 1][(ni & 1) * 2]);
            }
        }
    }
#undef ISSUE

    // ---------------- epilogue (rescale 1/256) ----------------
    int t4 = lid >> 2, t2 = (lid & 3) * 2;
#pragma unroll
    for (int mi = 0; mi < 4; mi++) {
#pragma unroll
        for (int ni = 0; ni < 8; ni++) {
            int n = bx * 256 + wn * 64 + ni * 8 + t2;
            int m0 = by * 128 + wm * 64 + mi * 16 + t4;
            float bn0 = 0.f, bn1 = 0.f;
            if (MODE != 0) { bn0 = bias[n]; bn1 = bias[n + 1]; }
#pragma unroll
            for (int half = 0; half < 2; half++) {
                int m = m0 + half * 8;
                float v0 = acc[mi][ni][half * 2]     * INVASC;
                float v1 = acc[mi][ni][half * 2 + 1] * INVASC;
                if (MODE == 0) {
                    int b = m >> 11, t = m & (CTX - 1);
                    int sel = n >> 10, hh = (n & 1023) >> 6, d0 = n & 63;
                    bf16* hi = (sel == 0) ? qhi : (sel == 1 ? khi : vhi);
                    bf16* lo = (sel == 0) ? qlo : (sel == 1 ? klo : vlo);
                    size_t o = ((size_t)(b * NH + hh) * CTX + t) * HS + d0;
                    *(uint32_t*)(hi + o) = pack2bf(v0, v1);
                    *(uint32_t*)(lo + o) = packlo2(v0, v1);
                } else if (MODE == 1) {
                    float s0 = (v0 + bn0) * ASCALE;
                    float s1 = (v1 + bn1) * ASCALE;
                    size_t o = (size_t)m * N + n;
                    *(uint32_t*)(out_hi + o) = pack2h(s0, s1);
                } else {
                    v0 = fmaxf(v0 + bn0, 0.f);
                    v1 = fmaxf(v1 + bn1, 0.f);
                    *(float2*)(out_f + (size_t)m * N + n) = make_float2(v0, v1);
                }
            }
        }
    }
}

// ================= mma.sync causal flash attention (3-term bf16) =================
// 128 queries/CTA, 8 warps x 16 rows; Bc=64 key tile; double-buffered K/V.
// V stored [T,D]; PV B-fragments via ldmatrix.trans.
// Epilogue writes fp16 x256 hi/lo for FFN1's A operand.
#define PADB   144
#define QTILE  (128*PADB)       // 18432
#define KVTILE (64*PADB)        // 9216
#define ASTAGE (4*KVTILE)       // 36864
#define ATTN_SMEM (2*QTILE + 2*ASTAGE)   // 110592

__global__ __launch_bounds__(256, 1)
void attn_mma()
{
    extern __shared__ char smem[];
    uint32_t sb = smem_u32(smem);
    int tid = threadIdx.x, wid = tid >> 5, lid = tid & 31;
    int qt = blockIdx.x, h = blockIdx.y, b = blockIdx.z;
    int q0 = qt * 128;
    int wm = wid;
    int g = lid >> 3, rr = lid & 7;
    uint32_t a_off = (uint32_t)(((g & 1) * 8 + rr) * PADB + (g >> 1) * 16);
    uint32_t b_off = (uint32_t)(((g >> 1) * 8 + rr) * PADB + (g & 1) * 16);
    int t4 = lid >> 2, t2 = lid & 3;

    size_t hb = (size_t)(b * NH + h);
    const bf16* qhB = g_qhi + hb * CTX * HS;
    const bf16* qlB = g_qlo + hb * CTX * HS;
    const bf16* khB = g_khi + hb * CTX * HS;
    const bf16* klB = g_klo + hb * CTX * HS;
    const bf16* vhB = g_vhi + hb * CTX * HS;
    const bf16* vlB = g_vlo + hb * CTX * HS;

    // Q tile (128 x 64) hi/lo
#pragma unroll
    for (int i = 0; i < 4; i++) {
        int idx = tid + i * 256;
        int r = idx >> 3, ch = idx & 7;
        uint32_t so = (uint32_t)(r * PADB + ch * 16);
        size_t gg = (size_t)(q0 + r) * HS + ch * 8;
        cp16(sb + so, qhB + gg);
        cp16(sb + QTILE + so, qlB + gg);
    }
    CP_COMMIT();

#define LOAD_TILE(st, kb_) do {                                            \
        uint32_t bs = sb + 2 * QTILE + (st) * ASTAGE;                      \
        for (int i_ = 0; i_ < 2; i_++) {                                   \
            int idx_ = tid + i_ * 256;                                     \
            int r_ = idx_ >> 3, ch_ = idx_ & 7;                            \
            uint32_t so_ = (uint32_t)(r_ * PADB + ch_ * 16);               \
            size_t kg_ = (size_t)((kb_) + r_) * HS + ch_ * 8;              \
            cp16(bs + so_, khB + kg_);                                     \
            cp16(bs + KVTILE + so_, klB + kg_);                            \
            cp16(bs + 2 * KVTILE + so_, vhB + kg_);                        \
            cp16(bs + 3 * KVTILE + so_, vlB + kg_);                        \
        } } while (0)

    LOAD_TILE(0, 0);
    CP_COMMIT();

    uint32_t qfh[4][4], qfl[4][4];
    float of[8][4];
#pragma unroll
    for (int i = 0; i < 8; i++)
#pragma unroll
        for (int j = 0; j < 4; j++) of[i][j] = 0.f;
    float m0 = -1e30f, m1 = -1e30f, l0 = 0.f, l1 = 0.f;
    bool qload = false;

    int nkt = 2 * qt + 2;
    for (int kt = 0; kt < nkt; kt++) {
        int kb = kt * 64;
        if (kt + 1 < nkt) { LOAD_TILE((kt + 1) & 1, kb + 64); CP_COMMIT(); CP_WAIT(1); }
        else { CP_WAIT(0); }
        __syncthreads();
        if (!qload) {
#pragma unroll
            for (int ks = 0; ks < 4; ks++) {
                uint32_t qo = (uint32_t)((wm * 16) * PADB + ks * 32) + a_off;
                ldm4(qfh[ks], sb + qo);
                ldm4(qfl[ks], sb + QTILE + qo);
            }
            qload = true;
        }
        if (q0 + wm * 16 + 15 >= kb) {
            uint32_t base = sb + 2 * QTILE + (kt & 1) * ASTAGE;
            float sf[8][4];
#pragma unroll
            for (int i = 0; i < 8; i++)
#pragma unroll
                for (int j = 0; j < 4; j++) sf[i][j] = 0.f;

#pragma unroll
            for (int ks = 0; ks < 4; ks++) {
                uint32_t bh[4][4], bl[4][4];
#pragma unroll
                for (int p = 0; p < 4; p++) {
                    uint32_t off = (uint32_t)((p * 16) * PADB + ks * 32) + b_off;
                    ldm4(bh[p], base + off);
                    ldm4(bl[p], base + KVTILE + off);
                }
#pragma unroll
                for (int ni = 0; ni < 8; ni++)
                    mma_bf16(sf[ni], qfh[ks], &bh[ni >> 1][(ni & 1) * 2]);
#pragma unroll
                for (int ni = 0; ni < 8; ni++)
                    mma_bf16(sf[ni], qfh[ks], &bl[ni >> 1][(ni & 1) * 2]);
#pragma unroll
                for (int ni = 0; ni < 8; ni++)
                    mma_bf16(sf[ni], qfl[ks], &bh[ni >> 1][(ni & 1) * 2]);
            }

            int row0 = q0 + wm * 16 + t4, row1 = row0 + 8;
            bool needm = (kb + 63 > q0 + wm * 16);
            float mx0 = -1e30f, mx1 = -1e30f;
#pragma unroll
            for (int ni = 0; ni < 8; ni++) {
                int c = kb + ni * 8 + t2 * 2;
                float s0 = sf[ni][0] * 0.125f, s1 = sf[ni][1] * 0.125f;
                float s2 = sf[ni][2] * 0.125f, s3 = sf[ni][3] * 0.125f;
                if (needm) {
                    if (c > row0)     s0 = -1e30f;
                    if (c + 1 > row0) s1 = -1e30f;
                    if (c > row1)     s2 = -1e30f;
                    if (c + 1 > row1) s3 = -1e30f;
                }
                sf[ni][0] = s0; sf[ni][1] = s1; sf[ni][2] = s2; sf[ni][3] = s3;
                mx0 = fmaxf(mx0, fmaxf(s0, s1));
                mx1 = fmaxf(mx1, fmaxf(s2, s3));
            }
            mx0 = fmaxf(mx0, __shfl_xor_sync(0xffffffffu, mx0, 1));
            mx0 = fmaxf(mx0, __shfl_xor_sync(0xffffffffu, mx0, 2));
            mx1 = fmaxf(mx1, __shfl_xor_sync(0xffffffffu, mx1, 1));
            mx1 = fmaxf(mx1, __shfl_xor_sync(0xffffffffu, mx1, 2));
            float nm0 = fmaxf(m0, mx0), nm1 = fmaxf(m1, mx1);
            float cr0 = __expf(m0 - nm0), cr1 = __expf(m1 - nm1);
            m0 = nm0; m1 = nm1;
            l0 *= cr0; l1 *= cr1;
#pragma unroll
            for (int ni = 0; ni < 8; ni++) {
                float p0 = __expf(sf[ni][0] - m0), p1 = __expf(sf[ni][1] - m0);
                float p2 = __expf(sf[ni][2] - m1), p3 = __expf(sf[ni][3] - m1);
                sf[ni][0] = p0; sf[ni][1] = p1; sf[ni][2] = p2; sf[ni][3] = p3;
                l0 += p0 + p1; l1 += p2 + p3;
                of[ni][0] *= cr0; of[ni][1] *= cr0; of[ni][2] *= cr1; of[ni][3] *= cr1;
            }

#pragma unroll
            for (int ks2 = 0; ks2 < 4; ks2++) {
                int n0b = 2 * ks2, n1b = n0b + 1;
                uint32_t pah[4], pal[4];
                pah[0] = pack2bf(sf[n0b][0], sf[n0b][1]);
                pah[1] = pack2bf(sf[n0b][2], sf[n0b][3]);
                pah[2] = pack2bf(sf[n1b][0], sf[n1b][1]);
                pah[3] = pack2bf(sf[n1b][2], sf[n1b][3]);
                pal[0] = packlo2(sf[n0b][0], sf[n0b][1]);
                pal[1] = packlo2(sf[n0b][2], sf[n0b][3]);
                pal[2] = packlo2(sf[n1b][0], sf[n1b][1]);
                pal[3] = packlo2(sf[n1b][2], sf[n1b][3]);
                uint32_t vh[4][4], vl[4][4];
#pragma unroll
                for (int p = 0; p < 4; p++) {
                    uint32_t off = (uint32_t)((ks2 * 16) * PADB + p * 32) + a_off;
                    ldm4t(vh[p], base + 2 * KVTILE + off);
                    ldm4t(vl[p], base + 3 * KVTILE + off);
                }
#pragma unroll
                for (int ni = 0; ni < 8; ni++)
                    mma_bf16(of[ni], pah, &vh[ni >> 1][(ni & 1) * 2]);
#pragma unroll
                for (int ni = 0; ni < 8; ni++)
                    mma_bf16(of[ni], pah, &vl[ni >> 1][(ni & 1) * 2]);
#pragma unroll
                for (int ni = 0; ni < 8; ni++)
                    mma_bf16(of[ni], pal, &vh[ni >> 1][(ni & 1) * 2]);
            }
        }
        __syncthreads();
    }
#undef LOAD_TILE

    l0 += __shfl_xor_sync(0xffffffffu, l0, 1);
    l0 += __shfl_xor_sync(0xffffffffu, l0, 2);
    l1 += __shfl_xor_sync(0xffffffffu, l1, 1);
    l1 += __shfl_xor_sync(0xffffffffu, l1, 2);
    float inv0 = ASCALE / l0, inv1 = ASCALE / l1;   // fold x256 A-scale into normalize

    int row0 = q0 + wm * 16 + t4;
#pragma unroll
    for (int ni = 0; ni < 8; ni++) {
        int col = h * HS + ni * 8 + t2 * 2;
        float s0 = of[ni][0] * inv0, s1 = of[ni][1] * inv0;
        float s2 = of[ni][2] * inv1, s3 = of[ni][3] * inv1;
        size_t o0 = ((size_t)(b * CTX) + row0) * DM + col;
        size_t o1 = o0 + (size_t)8 * DM;
        *(uint32_t*)(g_a16h + o0) = pack2h(s0, s1);
        *(uint32_t*)(g_a16l + o0) = packlo2h(s0, s1);
        *(uint32_t*)(g_a16h + o1) = pack2h(s2, s3);
        *(uint32_t*)(g_a16l + o1) = packlo2h(s2, s3);
    }
}

// ================= launch =================
extern "C" void kernel_launch(void* const* d_in, const int* in_sizes, int n_in,
                              void* d_out, int out_size)
{
    const float* x  = (const float*)d_in[0];
    const float* Wq = (const float*)d_in[1];
    const float* Wk = (const float*)d_in[2];
    const float* Wv = (const float*)d_in[3];
    const float* W1 = (const float*)d_in[4];
    const float* b1 = (const float*)d_in[5];
    const float* W2 = (const float*)d_in[6];
    const float* b2 = (const float*)d_in[7];
    float* out = (float*)d_out;

    bf16 *qhi, *qlo, *khi, *klo, *vhi, *vlo;
    f16 *x16h, *x16l, *a16h, *a16l, *h16h, *bq16, *w116, *w216;
    cudaGetSymbolAddress((void**)&qhi, g_qhi);
    cudaGetSymbolAddress((void**)&qlo, g_qlo);
    cudaGetSymbolAddress((void**)&khi, g_khi);
    cudaGetSymbolAddress((void**)&klo, g_klo);
    cudaGetSymbolAddress((void**)&vhi, g_vhi);
    cudaGetSymbolAddress((void**)&vlo, g_vlo);
    cudaGetSymbolAddress((void**)&x16h, g_x16h);
    cudaGetSymbolAddress((void**)&x16l, g_x16l);
    cudaGetSymbolAddress((void**)&a16h, g_a16h);
    cudaGetSymbolAddress((void**)&a16l, g_a16l);
    cudaGetSymbolAddress((void**)&h16h, g_h16h);
    cudaGetSymbolAddress((void**)&bq16, g_bq16);
    cudaGetSymbolAddress((void**)&w116, g_w116);
    cudaGetSymbolAddress((void**)&w216, g_w216);

    cudaFuncSetAttribute((const void*)gemm_f16<0,1>, cudaFuncAttributeMaxDynamicSharedMemorySize, GEMM_SMEM);
    cudaFuncSetAttribute((const void*)gemm_f16<1,1>, cudaFuncAttributeMaxDynamicSharedMemorySize, GEMM_SMEM);
    cudaFuncSetAttribute((const void*)gemm_f16<2,0>, cudaFuncAttributeMaxDynamicSharedMemorySize, GEMM_SMEM);
    cudaFuncSetAttribute(attn_mma, cudaFuncAttributeMaxDynamicSharedMemorySize, ATTN_SMEM);

    // input conversions
    split_x_kernel<<<(size_t)MTOT * NEMB / 1024, 256>>>(x, x16h, x16l);
    qkv_transpose_h<<<dim3(NEMB / 32, HS / 32, 48), dim3(32, 8)>>>(Wq, Wk, Wv, bq16);
    transpose_h<<<dim3(FF / 32, DM / 32), dim3(32, 8)>>>(W1, w116, DM, FF);
    transpose_h<<<dim3(DM / 32, FF / 32), dim3(32, 8)>>>(W2, w216, FF, DM);

    // QKV: [8192,1024] @ [1024,3072] -> split bf16 q/k/v [B,H,T,D]
    gemm_f16<0,1><<<dim3(3 * DM / 256, MTOT / 128), 256, GEMM_SMEM>>>(
        x16h, x16l, bq16, nullptr,
        nullptr, nullptr,
        qhi, qlo, khi, klo, vhi, vlo, 3 * DM, NEMB);

    // attention -> att fp16 x256 hi/lo
    attn_mma<<<dim3(CTX / 128, NH, BATCH), 256, ATTN_SMEM>>>();

    // FFN1: [8192,1024] @ [1024,4096] + b1 -> h fp16 x256 (hi only)
    gemm_f16<1,1><<<dim3(FF / 256, MTOT / 128), 256, GEMM_SMEM>>>(
        a16h, a16l, w116, b1,
        nullptr, h16h,
        nullptr, nullptr, nullptr, nullptr, nullptr, nullptr, FF, DM);

    // FFN2: [8192,4096] @ [4096,1024] + b2, relu -> out  (single-A fp16)
    gemm_f16<2,0><<<dim3(DM / 256, MTOT / 128), 256, GEMM_SMEM>>>(
        h16h, nullptr, w216, b2,
        out, nullptr,
        nullptr, nullptr, nullptr, nullptr, nullptr, nullptr, DM, FF);
}

// round 11
// speedup vs baseline: 2.4806x; 1.2471x over previous
#include <cuda_runtime.h>
#include <cuda_bf16.h>
#include <cuda_fp16.h>
#include <cstdint>

#define BATCH 4
#define CTX   2048
#define NEMB  1024
#define NH    16
#define HS    64
#define DM    1024
#define FF    4096
#define MTOT  (BATCH*CTX)   // 8192

typedef __nv_bfloat16 bf16;
typedef __half f16;

// ================= scratch =================
// attention operands stay bf16 hi/lo (3-term path)
__device__ bf16 g_qhi[(size_t)BATCH*NH*CTX*HS], g_qlo[(size_t)BATCH*NH*CTX*HS];
__device__ bf16 g_khi[(size_t)BATCH*NH*CTX*HS], g_klo[(size_t)BATCH*NH*CTX*HS];
__device__ bf16 g_vhi[(size_t)BATCH*NH*CTX*HS], g_vlo[(size_t)BATCH*NH*CTX*HS];
// GEMM activations: single fp16, pre-scaled x256
__device__ f16 g_x16h[(size_t)MTOT*NEMB];
__device__ f16 g_a16h[(size_t)MTOT*DM];
__device__ f16 g_h16h[(size_t)MTOT*FF];
// GEMM weights: single fp16, [N,K]
__device__ f16 g_bq16[(size_t)3*DM*NEMB];
__device__ f16 g_w116[(size_t)FF*DM];
__device__ f16 g_w216[(size_t)DM*FF];

#define ASCALE 256.f
#define INVASC (1.f/256.f)

__device__ __forceinline__ uint32_t pack2bf(float a, float b) {
    __nv_bfloat162 p(__float2bfloat16(a), __float2bfloat16(b));
    return *reinterpret_cast<uint32_t*>(&p);
}
__device__ __forceinline__ uint32_t packlo2(float a, float b) {
    float ra = __bfloat162float(__float2bfloat16(a));
    float rb = __bfloat162float(__float2bfloat16(b));
    return pack2bf(a - ra, b - rb);
}
__device__ __forceinline__ uint32_t pack2h(float a, float b) {
    __half2 p = __floats2half2_rn(a, b);
    return *reinterpret_cast<uint32_t*>(&p);
}
__device__ __forceinline__ uint32_t smem_u32(const void* p) {
    uint32_t a;
    asm("{ .reg .u64 t; cvta.to.shared.u64 t, %1; cvt.u32.u64 %0, t; }" : "=r"(a) : "l"(p));
    return a;
}
__device__ __forceinline__ void cp16(uint32_t dst, const void* src) {
    asm volatile("cp.async.cg.shared.global [%0], [%1], 16;" :: "r"(dst), "l"(src));
}
#define CP_COMMIT() asm volatile("cp.async.commit_group;" ::: "memory")
#define CP_WAIT(n)  asm volatile("cp.async.wait_group %0;" :: "n"(n) : "memory")

__device__ __forceinline__ void ldm4(uint32_t* r, uint32_t addr) {
    asm volatile("ldmatrix.sync.aligned.m8n8.x4.shared.b16 {%0,%1,%2,%3}, [%4];"
        : "=r"(r[0]), "=r"(r[1]), "=r"(r[2]), "=r"(r[3]) : "r"(addr));
}
__device__ __forceinline__ void ldm4t(uint32_t* r, uint32_t addr) {
    asm volatile("ldmatrix.sync.aligned.m8n8.x4.trans.shared.b16 {%0,%1,%2,%3}, [%4];"
        : "=r"(r[0]), "=r"(r[1]), "=r"(r[2]), "=r"(r[3]) : "r"(addr));
}
__device__ __forceinline__ void mma_bf16(float* d, const uint32_t* a, const uint32_t* b) {
    asm volatile("mma.sync.aligned.m16n8k16.row.col.f32.bf16.bf16.f32 "
        "{%0,%1,%2,%3}, {%4,%5,%6,%7}, {%8,%9}, {%0,%1,%2,%3};"
        : "+f"(d[0]), "+f"(d[1]), "+f"(d[2]), "+f"(d[3])
        : "r"(a[0]), "r"(a[1]), "r"(a[2]), "r"(a[3]), "r"(b[0]), "r"(b[1]));
}
__device__ __forceinline__ void mma_f16(float* d, const uint32_t* a, const uint32_t* b) {
    asm volatile("mma.sync.aligned.m16n8k16.row.col.f32.f16.f16.f32 "
        "{%0,%1,%2,%3}, {%4,%5,%6,%7}, {%8,%9}, {%0,%1,%2,%3};"
        : "+f"(d[0]), "+f"(d[1]), "+f"(d[2]), "+f"(d[3])
        : "r"(a[0]), "r"(a[1]), "r"(a[2]), "r"(a[3]), "r"(b[0]), "r"(b[1]));
}

// ================= convert / transpose kernels =================
// x -> fp16, scaled x256
__global__ __launch_bounds__(256) void conv_x_kernel(const float* __restrict__ x,
                                                     f16* __restrict__ hi)
{
    size_t i = (size_t)blockIdx.x * 256 + threadIdx.x;
    float4 v = ((const float4*)x)[i];
    ((uint2*)hi)[i] = make_uint2(pack2h(v.x * ASCALE, v.y * ASCALE),
                                 pack2h(v.z * ASCALE, v.w * ASCALE));
}

// W [K,N] row-major -> out [N,K] single fp16
__global__ __launch_bounds__(256) void transpose_h(const float* __restrict__ W,
                                                   f16* __restrict__ out, int K, int N)
{
    __shared__ float t[32][33];
    int n0 = blockIdx.x * 32, k0 = blockIdx.y * 32;
    int tx = threadIdx.x, ty = threadIdx.y;
#pragma unroll
    for (int i = ty; i < 32; i += 8)
        t[i][tx] = W[(size_t)(k0 + i) * N + n0 + tx];
    __syncthreads();
#pragma unroll
    for (int i = ty; i < 32; i += 8)
        out[(size_t)(n0 + i) * K + k0 + tx] = __float2half_rn(t[tx][i]);
}

// Wq/Wk/Wv [H,C,D] -> bqkv[n = sel*1024 + h*64 + d][k = c], single fp16
__global__ __launch_bounds__(256) void qkv_transpose_h(const float* __restrict__ Wq,
                                                       const float* __restrict__ Wk,
                                                       const float* __restrict__ Wv,
                                                       f16* __restrict__ out)
{
    __shared__ float t[32][33];
    int sel = blockIdx.z >> 4, h = blockIdx.z & 15;
    const float* W = (sel == 0 ? Wq : sel == 1 ? Wk : Wv) + (size_t)h * NEMB * HS;
    int c0 = blockIdx.x * 32, d0 = blockIdx.y * 32;
    int tx = threadIdx.x, ty = threadIdx.y;
#pragma unroll
    for (int i = ty; i < 32; i += 8)
        t[i][tx] = W[(size_t)(c0 + i) * HS + d0 + tx];
    __syncthreads();
    int nbase = sel * DM + h * HS + d0;
#pragma unroll
    for (int i = ty; i < 32; i += 8)
        out[(size_t)(nbase + i) * NEMB + c0 + tx] = __float2half_rn(t[tx][i]);
}

// ================= single-fp16 GEMM, 128x256 CTA tile, 5-stage =================
// D = Ah * Bh, A pre-scaled x256, rescale 1/256 in epilogue.
// MODE 0: scatter split bf16 -> q/k/v [B,H,T,D] hi/lo
// MODE 1: +bias, write fp16 x256 (FFN1 -> h)
// MODE 2: +bias, relu, write fp32 (FFN2 -> out)
#define ROWB    80
#define TA      (128*ROWB)   // 10240
#define TBL     (256*ROWB)   // 20480
#define OFF_BH  (TA)
#define STAGE_B (TA + TBL)       // 30720
#define NSTAGE  5
#define GEMM_SMEM (NSTAGE*STAGE_B)   // 153600

template <int MODE>
__global__ __launch_bounds__(256, 1)
void gemm_f16(const f16* __restrict__ Ahi,
              const f16* __restrict__ Bh,
              const float* __restrict__ bias,
              float* __restrict__ out_f, f16* __restrict__ out_hi,
              bf16* __restrict__ qhi, bf16* __restrict__ qlo,
              bf16* __restrict__ khi, bf16* __restrict__ klo,
              bf16* __restrict__ vhi, bf16* __restrict__ vlo,
              int N, int K)
{
    extern __shared__ char smem[];
    uint32_t sb = smem_u32(smem);

    int tid = threadIdx.x, wid = tid >> 5, lid = tid & 31;
    int wm = wid >> 2, wn = wid & 3;          // warp tile 64(M) x 64(N)
    int bx = blockIdx.x, by = blockIdx.y;

    const f16* aH = Ahi + (size_t)by * 128 * K;
    const f16* bH = Bh + (size_t)bx * 256 * K;

    float acc[4][8][4];
#pragma unroll
    for (int i = 0; i < 4; i++)
#pragma unroll
        for (int j = 0; j < 8; j++)
#pragma unroll
            for (int l = 0; l < 4; l++) acc[i][j][l] = 0.f;

    int ITERS = K >> 5;

#define ISSUE(st, k0) do {                                                         \
        uint32_t _b = sb + (st) * STAGE_B;                                         \
        _Pragma("unroll")                                                          \
        for (int _i = 0; _i < 2; _i++) {                                           \
            int _c = tid + _i * 256; int _r = _c >> 2, _q = _c & 3;                \
            uint32_t _so = (uint32_t)(_r * ROWB + _q * 16);                        \
            size_t _g = (size_t)_r * K + (k0) + _q * 8;                            \
            cp16(_b + _so, aH + _g);                                               \
        }                                                                          \
        _Pragma("unroll")                                                          \
        for (int _i = 0; _i < 4; _i++) {                                           \
            int _c = tid + _i * 256; int _r = _c >> 2, _q = _c & 3;                \
            uint32_t _so = (uint32_t)(_r * ROWB + _q * 16);                        \
            size_t _g = (size_t)_r * K + (k0) + _q * 8;                            \
            cp16(_b + OFF_BH + _so, bH + _g);                                      \
        }                                                                          \
    } while (0)

#pragma unroll
    for (int s = 0; s < NSTAGE - 1; s++) { ISSUE(s, s * 32); CP_COMMIT(); }

    int g = lid >> 3, rr = lid & 7;
    uint32_t a_row_off = (uint32_t)(((g & 1) * 8 + rr) * ROWB + (g >> 1) * 16);
    uint32_t b_row_off = (uint32_t)(((g >> 1) * 8 + rr) * ROWB + (g & 1) * 16);

    for (int it = 0; it < ITERS; it++) {
        CP_WAIT(NSTAGE - 2);        // stage it resident
        __syncthreads();            // all warps done with stage it-1 (aliased by it+NSTAGE-1)
        int pre = it + NSTAGE - 1;
        if (pre < ITERS) { ISSUE(pre % NSTAGE, pre * 32); }
        CP_COMMIT();

        uint32_t base = sb + (it % NSTAGE) * STAGE_B;
#pragma unroll
        for (int ks = 0; ks < 2; ks++) {
            uint32_t ah[4][4], bh[4][4];
#pragma unroll
            for (int mi = 0; mi < 4; mi++)
                ldm4(ah[mi], base + (uint32_t)((wm * 64 + mi * 16) * ROWB + ks * 32) + a_row_off);
#pragma unroll
            for (int p = 0; p < 4; p++)
                ldm4(bh[p], base + OFF_BH + (uint32_t)((wn * 64 + p * 16) * ROWB + ks * 32) + b_row_off);
#pragma unroll
            for (int mi = 0; mi < 4; mi++)
#pragma unroll
                for (int ni = 0; ni < 8; ni++)
                    mma_f16(acc[mi][ni], ah[mi], &bh[ni >> 1][(ni & 1) * 2]);
        }
    }
#undef ISSUE

    // ---------------- epilogue (rescale 1/256) ----------------
    int t4 = lid >> 2, t2 = (lid & 3) * 2;
#pragma unroll
    for (int mi = 0; mi < 4; mi++) {
#pragma unroll
        for (int ni = 0; ni < 8; ni++) {
            int n = bx * 256 + wn * 64 + ni * 8 + t2;
            int m0 = by * 128 + wm * 64 + mi * 16 + t4;
            float bn0 = 0.f, bn1 = 0.f;
            if (MODE != 0) { bn0 = bias[n]; bn1 = bias[n + 1]; }
#pragma unroll
            for (int half = 0; half < 2; half++) {
                int m = m0 + half * 8;
                float v0 = acc[mi][ni][half * 2]     * INVASC;
                float v1 = acc[mi][ni][half * 2 + 1] * INVASC;
                if (MODE == 0) {
                    int b = m >> 11, t = m & (CTX - 1);
                    int sel = n >> 10, hh = (n & 1023) >> 6, d0 = n & 63;
                    bf16* hi = (sel == 0) ? qhi : (sel == 1 ? khi : vhi);
                    bf16* lo = (sel == 0) ? qlo : (sel == 1 ? klo : vlo);
                    size_t o = ((size_t)(b * NH + hh) * CTX + t) * HS + d0;
                    *(uint32_t*)(hi + o) = pack2bf(v0, v1);
                    *(uint32_t*)(lo + o) = packlo2(v0, v1);
                } else if (MODE == 1) {
                    float s0 = (v0 + bn0) * ASCALE;
                    float s1 = (v1 + bn1) * ASCALE;
                    size_t o = (size_t)m * N + n;
                    *(uint32_t*)(out_hi + o) = pack2h(s0, s1);
                } else {
                    v0 = fmaxf(v0 + bn0, 0.f);
                    v1 = fmaxf(v1 + bn1, 0.f);
                    *(float2*)(out_f + (size_t)m * N + n) = make_float2(v0, v1);
                }
            }
        }
    }
}

// ================= mma.sync causal flash attention (3-term bf16) =================
// 128 queries/CTA, 8 warps x 16 rows; Bc=64 key tile; double-buffered K/V.
// V stored [T,D]; PV B-fragments via ldmatrix.trans.
// Epilogue writes fp16 x256 (single) for FFN1's A operand.
#define PADB   144
#define QTILE  (128*PADB)       // 18432
#define KVTILE (64*PADB)        // 9216
#define ASTAGE (4*KVTILE)       // 36864
#define ATTN_SMEM (2*QTILE + 2*ASTAGE)   // 110592

__global__ __launch_bounds__(256, 1)
void attn_mma()
{
    extern __shared__ char smem[];
    uint32_t sb = smem_u32(smem);
    int tid = threadIdx.x, wid = tid >> 5, lid = tid & 31;
    int qt = blockIdx.x, h = blockIdx.y, b = blockIdx.z;
    int q0 = qt * 128;
    int wm = wid;
    int g = lid >> 3, rr = lid & 7;
    uint32_t a_off = (uint32_t)(((g & 1) * 8 + rr) * PADB + (g >> 1) * 16);
    uint32_t b_off = (uint32_t)(((g >> 1) * 8 + rr) * PADB + (g & 1) * 16);
    int t4 = lid >> 2, t2 = lid & 3;

    size_t hb = (size_t)(b * NH + h);
    const bf16* qhB = g_qhi + hb * CTX * HS;
    const bf16* qlB = g_qlo + hb * CTX * HS;
    const bf16* khB = g_khi + hb * CTX * HS;
    const bf16* klB = g_klo + hb * CTX * HS;
    const bf16* vhB = g_vhi + hb * CTX * HS;
    const bf16* vlB = g_vlo + hb * CTX * HS;

    // Q tile (128 x 64) hi/lo
#pragma unroll
    for (int i = 0; i < 4; i++) {
        int idx = tid + i * 256;
        int r = idx >> 3, ch = idx & 7;
        uint32_t so = (uint32_t)(r * PADB + ch * 16);
        size_t gg = (size_t)(q0 + r) * HS + ch * 8;
        cp16(sb + so, qhB + gg);
        cp16(sb + QTILE + so, qlB + gg);
    }
    CP_COMMIT();

#define LOAD_TILE(st, kb_) do {                                            \
        uint32_t bs = sb + 2 * QTILE + (st) * ASTAGE;                      \
        for (int i_ = 0; i_ < 2; i_++) {                                   \
            int idx_ = tid + i_ * 256;                                     \
            int r_ = idx_ >> 3, ch_ = idx_ & 7;                            \
            uint32_t so_ = (uint32_t)(r_ * PADB + ch_ * 16);               \
            size_t kg_ = (size_t)((kb_) + r_) * HS + ch_ * 8;              \
            cp16(bs + so_, khB + kg_);                                     \
            cp16(bs + KVTILE + so_, klB + kg_);                            \
            cp16(bs + 2 * KVTILE + so_, vhB + kg_);                        \
            cp16(bs + 3 * KVTILE + so_, vlB + kg_);                        \
        } } while (0)

    LOAD_TILE(0, 0);
    CP_COMMIT();

    uint32_t qfh[4][4], qfl[4][4];
    float of[8][4];
#pragma unroll
    for (int i = 0; i < 8; i++)
#pragma unroll
        for (int j = 0; j < 4; j++) of[i][j] = 0.f;
    float m0 = -1e30f, m1 = -1e30f, l0 = 0.f, l1 = 0.f;
    bool qload = false;

    int nkt = 2 * qt + 2;
    for (int kt = 0; kt < nkt; kt++) {
        int kb = kt * 64;
        if (kt + 1 < nkt) { LOAD_TILE((kt + 1) & 1, kb + 64); CP_COMMIT(); CP_WAIT(1); }
        else { CP_WAIT(0); }
        __syncthreads();
        if (!qload) {
#pragma unroll
            for (int ks = 0; ks < 4; ks++) {
                uint32_t qo = (uint32_t)((wm * 16) * PADB + ks * 32) + a_off;
                ldm4(qfh[ks], sb + qo);
                ldm4(qfl[ks], sb + QTILE + qo);
            }
            qload = true;
        }
        if (q0 + wm * 16 + 15 >= kb) {
            uint32_t base = sb + 2 * QTILE + (kt & 1) * ASTAGE;
            float sf[8][4];
#pragma unroll
            for (int i = 0; i < 8; i++)
#pragma unroll
                for (int j = 0; j < 4; j++) sf[i][j] = 0.f;

#pragma unroll
            for (int ks = 0; ks < 4; ks++) {
                uint32_t bh[4][4], bl[4][4];
#pragma unroll
                for (int p = 0; p < 4; p++) {
                    uint32_t off = (uint32_t)((p * 16) * PADB + ks * 32) + b_off;
                    ldm4(bh[p], base + off);
                    ldm4(bl[p], base + KVTILE + off);
                }
#pragma unroll
                for (int ni = 0; ni < 8; ni++)
                    mma_bf16(sf[ni], qfh[ks], &bh[ni >> 1][(ni & 1) * 2]);
#pragma unroll
                for (int ni = 0; ni < 8; ni++)
                    mma_bf16(sf[ni], qfh[ks], &bl[ni >> 1][(ni & 1) * 2]);
#pragma unroll
                for (int ni = 0; ni < 8; ni++)
                    mma_bf16(sf[ni], qfl[ks], &bh[ni >> 1][(ni & 1) * 2]);
            }

            int row0 = q0 + wm * 16 + t4, row1 = row0 + 8;
            bool needm = (kb + 63 > q0 + wm * 16);
            float mx0 = -1e30f, mx1 = -1e30f;
#pragma unroll
            for (int ni = 0; ni < 8; ni++) {
                int c = kb + ni * 8 + t2 * 2;
                float s0 = sf[ni][0] * 0.125f, s1 = sf[ni][1] * 0.125f;
                float s2 = sf[ni][2] * 0.125f, s3 = sf[ni][3] * 0.125f;
                if (needm) {
                    if (c > row0)     s0 = -1e30f;
                    if (c + 1 > row0) s1 = -1e30f;
                    if (c > row1)     s2 = -1e30f;
                    if (c + 1 > row1) s3 = -1e30f;
                }
                sf[ni][0] = s0; sf[ni][1] = s1; sf[ni][2] = s2; sf[ni][3] = s3;
                mx0 = fmaxf(mx0, fmaxf(s0, s1));
                mx1 = fmaxf(mx1, fmaxf(s2, s3));
            }
            mx0 = fmaxf(mx0, __shfl_xor_sync(0xffffffffu, mx0, 1));
            mx0 = fmaxf(mx0, __shfl_xor_sync(0xffffffffu, mx0, 2));
            mx1 = fmaxf(mx1, __shfl_xor_sync(0xffffffffu, mx1, 1));
            mx1 = fmaxf(mx1, __shfl_xor_sync(0xffffffffu, mx1, 2));
            float nm0 = fmaxf(m0, mx0), nm1 = fmaxf(m1, mx1);
            float cr0 = __expf(m0 - nm0), cr1 = __expf(m1 - nm1);
            m0 = nm0; m1 = nm1;
            l0 *= cr0; l1 *= cr1;
#pragma unroll
            for (int ni = 0; ni < 8; ni++) {
                float p0 = __expf(sf[ni][0] - m0), p1 = __expf(sf[ni][1] - m0);
                float p2 = __expf(sf[ni][2] - m1), p3 = __expf(sf[ni][3] - m1);
                sf[ni][0] = p0; sf[ni][1] = p1; sf[ni][2] = p2; sf[ni][3] = p3;
                l0 += p0 + p1; l1 += p2 + p3;
                of[ni][0] *= cr0; of[ni][1] *= cr0; of[ni][2] *= cr1; of[ni][3] *= cr1;
            }

#pragma unroll
            for (int ks2 = 0; ks2 < 4; ks2++) {
                int n0b = 2 * ks2, n1b = n0b + 1;
                uint32_t pah[4], pal[4];
                pah[0] = pack2bf(sf[n0b][0], sf[n0b][1]);
                pah[1] = pack2bf(sf[n0b][2], sf[n0b][3]);
                pah[2] = pack2bf(sf[n1b][0], sf[n1b][1]);
                pah[3] = pack2bf(sf[n1b][2], sf[n1b][3]);
                pal[0] = packlo2(sf[n0b][0], sf[n0b][1]);
                pal[1] = packlo2(sf[n0b][2], sf[n0b][3]);
                pal[2] = packlo2(sf[n1b][0], sf[n1b][1]);
                pal[3] = packlo2(sf[n1b][2], sf[n1b][3]);
                uint32_t vh[4][4], vl[4][4];
#pragma unroll
                for (int p = 0; p < 4; p++) {
                    uint32_t off = (uint32_t)((ks2 * 16) * PADB + p * 32) + a_off;
                    ldm4t(vh[p], base + 2 * KVTILE + off);
                    ldm4t(vl[p], base + 3 * KVTILE + off);
                }
#pragma unroll
                for (int ni = 0; ni < 8; ni++)
                    mma_bf16(of[ni], pah, &vh[ni >> 1][(ni & 1) * 2]);
#pragma unroll
                for (int ni = 0; ni < 8; ni++)
                    mma_bf16(of[ni], pah, &vl[ni >> 1][(ni & 1) * 2]);
#pragma unroll
                for (int ni = 0; ni < 8; ni++)
                    mma_bf16(of[ni], pal, &vh[ni >> 1][(ni & 1) * 2]);
            }
        }
        __syncthreads();
    }
#undef LOAD_TILE

    l0 += __shfl_xor_sync(0xffffffffu, l0, 1);
    l0 += __shfl_xor_sync(0xffffffffu, l0, 2);
    l1 += __shfl_xor_sync(0xffffffffu, l1, 1);
    l1 += __shfl_xor_sync(0xffffffffu, l1, 2);
    float inv0 = ASCALE / l0, inv1 = ASCALE / l1;   // fold x256 A-scale into normalize

    int row0 = q0 + wm * 16 + t4;
#pragma unroll
    for (int ni = 0; ni < 8; ni++) {
        int col = h * HS + ni * 8 + t2 * 2;
        float s0 = of[ni][0] * inv0, s1 = of[ni][1] * inv0;
        float s2 = of[ni][2] * inv1, s3 = of[ni][3] * inv1;
        size_t o0 = ((size_t)(b * CTX) + row0) * DM + col;
        size_t o1 = o0 + (size_t)8 * DM;
        *(uint32_t*)(g_a16h + o0) = pack2h(s0, s1);
        *(uint32_t*)(g_a16h + o1) = pack2h(s2, s3);
    }
}

// ================= launch =================
extern "C" void kernel_launch(void* const* d_in, const int* in_sizes, int n_in,
                              void* d_out, int out_size)
{
    const float* x  = (const float*)d_in[0];
    const float* Wq = (const float*)d_in[1];
    const float* Wk = (const float*)d_in[2];
    const float* Wv = (const float*)d_in[3];
    const float* W1 = (const float*)d_in[4];
    const float* b1 = (const float*)d_in[5];
    const float* W2 = (const float*)d_in[6];
    const float* b2 = (const float*)d_in[7];
    float* out = (float*)d_out;

    bf16 *qhi, *qlo, *khi, *klo, *vhi, *vlo;
    f16 *x16h, *a16h, *h16h, *bq16, *w116, *w216;
    cudaGetSymbolAddress((void**)&qhi, g_qhi);
    cudaGetSymbolAddress((void**)&qlo, g_qlo);
    cudaGetSymbolAddress((void**)&khi, g_khi);
    cudaGetSymbolAddress((void**)&klo, g_klo);
    cudaGetSymbolAddress((void**)&vhi, g_vhi);
    cudaGetSymbolAddress((void**)&vlo, g_vlo);
    cudaGetSymbolAddress((void**)&x16h, g_x16h);
    cudaGetSymbolAddress((void**)&a16h, g_a16h);
    cudaGetSymbolAddress((void**)&h16h, g_h16h);
    cudaGetSymbolAddress((void**)&bq16, g_bq16);
    cudaGetSymbolAddress((void**)&w116, g_w116);
    cudaGetSymbolAddress((void**)&w216, g_w216);

    cudaFuncSetAttribute((const void*)gemm_f16<0>, cudaFuncAttributeMaxDynamicSharedMemorySize, GEMM_SMEM);
    cudaFuncSetAttribute((const void*)gemm_f16<1>, cudaFuncAttributeMaxDynamicSharedMemorySize, GEMM_SMEM);
    cudaFuncSetAttribute((const void*)gemm_f16<2>, cudaFuncAttributeMaxDynamicSharedMemorySize, GEMM_SMEM);
    cudaFuncSetAttribute(attn_mma, cudaFuncAttributeMaxDynamicSharedMemorySize, ATTN_SMEM);

    // input conversions
    conv_x_kernel<<<(size_t)MTOT * NEMB / 1024, 256>>>(x, x16h);
    qkv_transpose_h<<<dim3(NEMB / 32, HS / 32, 48), dim3(32, 8)>>>(Wq, Wk, Wv, bq16);
    transpose_h<<<dim3(FF / 32, DM / 32), dim3(32, 8)>>>(W1, w116, DM, FF);
    transpose_h<<<dim3(DM / 32, FF / 32), dim3(32, 8)>>>(W2, w216, FF, DM);

    // QKV: [8192,1024] @ [1024,3072] -> split bf16 q/k/v [B,H,T,D]
    gemm_f16<0><<<dim3(3 * DM / 256, MTOT / 128), 256, GEMM_SMEM>>>(
        x16h, bq16, nullptr,
        nullptr, nullptr,
        qhi, qlo, khi, klo, vhi, vlo, 3 * DM, NEMB);

    // attention -> att fp16 x256 (single)
    attn_mma<<<dim3(CTX / 128, NH, BATCH), 256, ATTN_SMEM>>>();

    // FFN1: [8192,1024] @ [1024,4096] + b1 -> h fp16 x256
    gemm_f16<1><<<dim3(FF / 256, MTOT / 128), 256, GEMM_SMEM>>>(
        a16h, w116, b1,
        nullptr, h16h,
        nullptr, nullptr, nullptr, nullptr, nullptr, nullptr, FF, DM);

    // FFN2: [8192,4096] @ [4096,1024] + b2, relu -> out
    gemm_f16<2><<<dim3(DM / 256, MTOT / 128), 256, GEMM_SMEM>>>(
        h16h, w216, b2,
        out, nullptr,
        nullptr, nullptr, nullptr, nullptr, nullptr, nullptr, DM, FF);
}

// round 12
// speedup vs baseline: 2.8902x; 1.1651x over previous
#include <cuda_runtime.h>
#include <cuda_bf16.h>
#include <cuda_fp16.h>
#include <cstdint>

#define BATCH 4
#define CTX   2048
#define NEMB  1024
#define NH    16
#define HS    64
#define DM    1024
#define FF    4096
#define MTOT  (BATCH*CTX)   // 8192

typedef __nv_bfloat16 bf16;
typedef __half f16;

// ================= scratch =================
// attention operands: Q split fp16 hi/lo, K/V single fp16
__device__ f16 g_q16a[(size_t)BATCH*NH*CTX*HS], g_q16b[(size_t)BATCH*NH*CTX*HS];
__device__ f16 g_k16[(size_t)BATCH*NH*CTX*HS];
__device__ f16 g_v16[(size_t)BATCH*NH*CTX*HS];
// GEMM activations: single fp16, pre-scaled x256
__device__ f16 g_x16h[(size_t)MTOT*NEMB];
__device__ f16 g_a16h[(size_t)MTOT*DM];
__device__ f16 g_h16h[(size_t)MTOT*FF];
// GEMM weights: single fp16, [N,K]
__device__ f16 g_bq16[(size_t)3*DM*NEMB];
__device__ f16 g_w116[(size_t)FF*DM];
__device__ f16 g_w216[(size_t)DM*FF];

#define ASCALE 256.f
#define INVASC (1.f/256.f)

__device__ __forceinline__ uint32_t pack2h(float a, float b) {
    __half2 p = __floats2half2_rn(a, b);
    return *reinterpret_cast<uint32_t*>(&p);
}
__device__ __forceinline__ uint32_t packlo2h(float a, float b) {
    float ra = __half2float(__float2half_rn(a));
    float rb = __half2float(__float2half_rn(b));
    return pack2h(a - ra, b - rb);
}
__device__ __forceinline__ uint32_t smem_u32(const void* p) {
    uint32_t a;
    asm("{ .reg .u64 t; cvta.to.shared.u64 t, %1; cvt.u32.u64 %0, t; }" : "=r"(a) : "l"(p));
    return a;
}
__device__ __forceinline__ void cp16(uint32_t dst, const void* src) {
    asm volatile("cp.async.cg.shared.global [%0], [%1], 16;" :: "r"(dst), "l"(src));
}
#define CP_COMMIT() asm volatile("cp.async.commit_group;" ::: "memory")
#define CP_WAIT(n)  asm volatile("cp.async.wait_group %0;" :: "n"(n) : "memory")

__device__ __forceinline__ void ldm4(uint32_t* r, uint32_t addr) {
    asm volatile("ldmatrix.sync.aligned.m8n8.x4.shared.b16 {%0,%1,%2,%3}, [%4];"
        : "=r"(r[0]), "=r"(r[1]), "=r"(r[2]), "=r"(r[3]) : "r"(addr));
}
__device__ __forceinline__ void ldm4t(uint32_t* r, uint32_t addr) {
    asm volatile("ldmatrix.sync.aligned.m8n8.x4.trans.shared.b16 {%0,%1,%2,%3}, [%4];"
        : "=r"(r[0]), "=r"(r[1]), "=r"(r[2]), "=r"(r[3]) : "r"(addr));
}
__device__ __forceinline__ void mma_f16(float* d, const uint32_t* a, const uint32_t* b) {
    asm volatile("mma.sync.aligned.m16n8k16.row.col.f32.f16.f16.f32 "
        "{%0,%1,%2,%3}, {%4,%5,%6,%7}, {%8,%9}, {%0,%1,%2,%3};"
        : "+f"(d[0]), "+f"(d[1]), "+f"(d[2]), "+f"(d[3])
        : "r"(a[0]), "r"(a[1]), "r"(a[2]), "r"(a[3]), "r"(b[0]), "r"(b[1]));
}

// ================= convert / transpose kernels =================
// x -> fp16, scaled x256
__global__ __launch_bounds__(256) void conv_x_kernel(const float* __restrict__ x,
                                                     f16* __restrict__ hi)
{
    size_t i = (size_t)blockIdx.x * 256 + threadIdx.x;
    float4 v = ((const float4*)x)[i];
    ((uint2*)hi)[i] = make_uint2(pack2h(v.x * ASCALE, v.y * ASCALE),
                                 pack2h(v.z * ASCALE, v.w * ASCALE));
}

// W [K,N] row-major -> out [N,K] single fp16
__global__ __launch_bounds__(256) void transpose_h(const float* __restrict__ W,
                                                   f16* __restrict__ out, int K, int N)
{
    __shared__ float t[32][33];
    int n0 = blockIdx.x * 32, k0 = blockIdx.y * 32;
    int tx = threadIdx.x, ty = threadIdx.y;
#pragma unroll
    for (int i = ty; i < 32; i += 8)
        t[i][tx] = W[(size_t)(k0 + i) * N + n0 + tx];
    __syncthreads();
#pragma unroll
    for (int i = ty; i < 32; i += 8)
        out[(size_t)(n0 + i) * K + k0 + tx] = __float2half_rn(t[tx][i]);
}

// Wq/Wk/Wv [H,C,D] -> bqkv[n = sel*1024 + h*64 + d][k = c], single fp16
__global__ __launch_bounds__(256) void qkv_transpose_h(const float* __restrict__ Wq,
                                                       const float* __restrict__ Wk,
                                                       const float* __restrict__ Wv,
                                                       f16* __restrict__ out)
{
    __shared__ float t[32][33];
    int sel = blockIdx.z >> 4, h = blockIdx.z & 15;
    const float* W = (sel == 0 ? Wq : sel == 1 ? Wk : Wv) + (size_t)h * NEMB * HS;
    int c0 = blockIdx.x * 32, d0 = blockIdx.y * 32;
    int tx = threadIdx.x, ty = threadIdx.y;
#pragma unroll
    for (int i = ty; i < 32; i += 8)
        t[i][tx] = W[(size_t)(c0 + i) * HS + d0 + tx];
    __syncthreads();
    int nbase = sel * DM + h * HS + d0;
#pragma unroll
    for (int i = ty; i < 32; i += 8)
        out[(size_t)(nbase + i) * NEMB + c0 + tx] = __float2half_rn(t[tx][i]);
}

// ================= single-fp16 GEMM, 128x256 CTA tile, 5-stage =================
// D = Ah * Bh, A pre-scaled x256, rescale 1/256 in epilogue.
// MODE 0: scatter -> q split fp16 hi/lo, k/v single fp16, [B,H,T,D]
// MODE 1: +bias, write fp16 x256 (FFN1 -> h)
// MODE 2: +bias, relu, write fp32 (FFN2 -> out)
#define ROWB    80
#define TA      (128*ROWB)   // 10240
#define TBL     (256*ROWB)   // 20480
#define OFF_BH  (TA)
#define STAGE_B (TA + TBL)       // 30720
#define NSTAGE  5
#define GEMM_SMEM (NSTAGE*STAGE_B)   // 153600

template <int MODE>
__global__ __launch_bounds__(256, 1)
void gemm_f16(const f16* __restrict__ Ahi,
              const f16* __restrict__ Bh,
              const float* __restrict__ bias,
              float* __restrict__ out_f, f16* __restrict__ out_hi,
              f16* __restrict__ qa, f16* __restrict__ qb,
              f16* __restrict__ kk, f16* __restrict__ vv,
              int N, int K)
{
    extern __shared__ char smem[];
    uint32_t sb = smem_u32(smem);

    int tid = threadIdx.x, wid = tid >> 5, lid = tid & 31;
    int wm = wid >> 2, wn = wid & 3;          // warp tile 64(M) x 64(N)
    int bx = blockIdx.x, by = blockIdx.y;

    const f16* aH = Ahi + (size_t)by * 128 * K;
    const f16* bH = Bh + (size_t)bx * 256 * K;

    float acc[4][8][4];
#pragma unroll
    for (int i = 0; i < 4; i++)
#pragma unroll
        for (int j = 0; j < 8; j++)
#pragma unroll
            for (int l = 0; l < 4; l++) acc[i][j][l] = 0.f;

    int ITERS = K >> 5;

#define ISSUE(st, k0) do {                                                         \
        uint32_t _b = sb + (st) * STAGE_B;                                         \
        _Pragma("unroll")                                                          \
        for (int _i = 0; _i < 2; _i++) {                                           \
            int _c = tid + _i * 256; int _r = _c >> 2, _q = _c & 3;                \
            uint32_t _so = (uint32_t)(_r * ROWB + _q * 16);                        \
            size_t _g = (size_t)_r * K + (k0) + _q * 8;                            \
            cp16(_b + _so, aH + _g);                                               \
        }                                                                          \
        _Pragma("unroll")                                                          \
        for (int _i = 0; _i < 4; _i++) {                                           \
            int _c = tid + _i * 256; int _r = _c >> 2, _q = _c & 3;                \
            uint32_t _so = (uint32_t)(_r * ROWB + _q * 16);                        \
            size_t _g = (size_t)_r * K + (k0) + _q * 8;                            \
            cp16(_b + OFF_BH + _so, bH + _g);                                      \
        }                                                                          \
    } while (0)

#pragma unroll
    for (int s = 0; s < NSTAGE - 1; s++) { ISSUE(s, s * 32); CP_COMMIT(); }

    int g = lid >> 3, rr = lid & 7;
    uint32_t a_row_off = (uint32_t)(((g & 1) * 8 + rr) * ROWB + (g >> 1) * 16);
    uint32_t b_row_off = (uint32_t)(((g >> 1) * 8 + rr) * ROWB + (g & 1) * 16);

    for (int it = 0; it < ITERS; it++) {
        CP_WAIT(NSTAGE - 2);        // stage it resident
        __syncthreads();            // all warps done with stage it-1 (aliased by it+NSTAGE-1)
        int pre = it + NSTAGE - 1;
        if (pre < ITERS) { ISSUE(pre % NSTAGE, pre * 32); }
        CP_COMMIT();

        uint32_t base = sb + (it % NSTAGE) * STAGE_B;
#pragma unroll
        for (int ks = 0; ks < 2; ks++) {
            uint32_t ah[4][4], bh[4][4];
#pragma unroll
            for (int mi = 0; mi < 4; mi++)
                ldm4(ah[mi], base + (uint32_t)((wm * 64 + mi * 16) * ROWB + ks * 32) + a_row_off);
#pragma unroll
            for (int p = 0; p < 4; p++)
                ldm4(bh[p], base + OFF_BH + (uint32_t)((wn * 64 + p * 16) * ROWB + ks * 32) + b_row_off);
#pragma unroll
            for (int mi = 0; mi < 4; mi++)
#pragma unroll
                for (int ni = 0; ni < 8; ni++)
                    mma_f16(acc[mi][ni], ah[mi], &bh[ni >> 1][(ni & 1) * 2]);
        }
    }
#undef ISSUE

    // ---------------- epilogue (rescale 1/256) ----------------
    int t4 = lid >> 2, t2 = (lid & 3) * 2;
#pragma unroll
    for (int mi = 0; mi < 4; mi++) {
#pragma unroll
        for (int ni = 0; ni < 8; ni++) {
            int n = bx * 256 + wn * 64 + ni * 8 + t2;
            int m0 = by * 128 + wm * 64 + mi * 16 + t4;
            float bn0 = 0.f, bn1 = 0.f;
            if (MODE != 0) { bn0 = bias[n]; bn1 = bias[n + 1]; }
#pragma unroll
            for (int half = 0; half < 2; half++) {
                int m = m0 + half * 8;
                float v0 = acc[mi][ni][half * 2]     * INVASC;
                float v1 = acc[mi][ni][half * 2 + 1] * INVASC;
                if (MODE == 0) {
                    int b = m >> 11, t = m & (CTX - 1);
                    int sel = n >> 10, hh = (n & 1023) >> 6, d0 = n & 63;
                    size_t o = ((size_t)(b * NH + hh) * CTX + t) * HS + d0;
                    if (sel == 0) {
                        *(uint32_t*)(qa + o) = pack2h(v0, v1);
                        *(uint32_t*)(qb + o) = packlo2h(v0, v1);
                    } else if (sel == 1) {
                        *(uint32_t*)(kk + o) = pack2h(v0, v1);
                    } else {
                        *(uint32_t*)(vv + o) = pack2h(v0, v1);
                    }
                } else if (MODE == 1) {
                    float s0 = (v0 + bn0) * ASCALE;
                    float s1 = (v1 + bn1) * ASCALE;
                    size_t o = (size_t)m * N + n;
                    *(uint32_t*)(out_hi + o) = pack2h(s0, s1);
                } else {
                    v0 = fmaxf(v0 + bn0, 0.f);
                    v1 = fmaxf(v1 + bn1, 0.f);
                    *(float2*)(out_f + (size_t)m * N + n) = make_float2(v0, v1);
                }
            }
        }
    }
}

// ================= mma.sync causal flash attention (fp16) =================
// QK: (Qhi + Qlo) * K (2 MMAs); PV: P * V (1 MMA). All fp16, fp32 accum.
// 128 queries/CTA, 8 warps x 16 rows; Bc=64 key tile; double-buffered K/V.
// V stored [T,D]; PV B-fragments via ldmatrix.trans.
// Epilogue writes fp16 x256 for FFN1's A operand.
#define PADB   144
#define QTILE  (128*PADB)       // 18432
#define KVTILE (64*PADB)        // 9216
#define ASTAGE (2*KVTILE)       // 18432
#define ATTN_SMEM (2*QTILE + 2*ASTAGE)   // 73728

__global__ __launch_bounds__(256, 1)
void attn_mma()
{
    extern __shared__ char smem[];
    uint32_t sb = smem_u32(smem);
    int tid = threadIdx.x, wid = tid >> 5, lid = tid & 31;
    int qt = blockIdx.x, h = blockIdx.y, b = blockIdx.z;
    int q0 = qt * 128;
    int wm = wid;
    int g = lid >> 3, rr = lid & 7;
    uint32_t a_off = (uint32_t)(((g & 1) * 8 + rr) * PADB + (g >> 1) * 16);
    uint32_t b_off = (uint32_t)(((g >> 1) * 8 + rr) * PADB + (g & 1) * 16);
    int t4 = lid >> 2, t2 = lid & 3;

    size_t hb = (size_t)(b * NH + h);
    const f16* qaB = g_q16a + hb * CTX * HS;
    const f16* qbB = g_q16b + hb * CTX * HS;
    const f16* kB  = g_k16  + hb * CTX * HS;
    const f16* vB  = g_v16  + hb * CTX * HS;

    // Q tile (128 x 64) hi/lo
#pragma unroll
    for (int i = 0; i < 4; i++) {
        int idx = tid + i * 256;
        int r = idx >> 3, ch = idx & 7;
        uint32_t so = (uint32_t)(r * PADB + ch * 16);
        size_t gg = (size_t)(q0 + r) * HS + ch * 8;
        cp16(sb + so, qaB + gg);
        cp16(sb + QTILE + so, qbB + gg);
    }
    CP_COMMIT();

#define LOAD_TILE(st, kb_) do {                                            \
        uint32_t bs = sb + 2 * QTILE + (st) * ASTAGE;                      \
        for (int i_ = 0; i_ < 2; i_++) {                                   \
            int idx_ = tid + i_ * 256;                                     \
            int r_ = idx_ >> 3, ch_ = idx_ & 7;                            \
            uint32_t so_ = (uint32_t)(r_ * PADB + ch_ * 16);               \
            size_t kg_ = (size_t)((kb_) + r_) * HS + ch_ * 8;              \
            cp16(bs + so_, kB + kg_);                                      \
            cp16(bs + KVTILE + so_, vB + kg_);                             \
        } } while (0)

    LOAD_TILE(0, 0);
    CP_COMMIT();

    uint32_t qfh[4][4], qfl[4][4];
    float of[8][4];
#pragma unroll
    for (int i = 0; i < 8; i++)
#pragma unroll
        for (int j = 0; j < 4; j++) of[i][j] = 0.f;
    float m0 = -1e30f, m1 = -1e30f, l0 = 0.f, l1 = 0.f;
    bool qload = false;

    int nkt = 2 * qt + 2;
    for (int kt = 0; kt < nkt; kt++) {
        int kb = kt * 64;
        if (kt + 1 < nkt) { LOAD_TILE((kt + 1) & 1, kb + 64); CP_COMMIT(); CP_WAIT(1); }
        else { CP_WAIT(0); }
        __syncthreads();
        if (!qload) {
#pragma unroll
            for (int ks = 0; ks < 4; ks++) {
                uint32_t qo = (uint32_t)((wm * 16) * PADB + ks * 32) + a_off;
                ldm4(qfh[ks], sb + qo);
                ldm4(qfl[ks], sb + QTILE + qo);
            }
            qload = true;
        }
        if (q0 + wm * 16 + 15 >= kb) {
            uint32_t base = sb + 2 * QTILE + (kt & 1) * ASTAGE;
            float sf[8][4];
#pragma unroll
            for (int i = 0; i < 8; i++)
#pragma unroll
                for (int j = 0; j < 4; j++) sf[i][j] = 0.f;

#pragma unroll
            for (int ks = 0; ks < 4; ks++) {
                uint32_t bh[4][4];
#pragma unroll
                for (int p = 0; p < 4; p++)
                    ldm4(bh[p], base + (uint32_t)((p * 16) * PADB + ks * 32) + b_off);
#pragma unroll
                for (int ni = 0; ni < 8; ni++)
                    mma_f16(sf[ni], qfh[ks], &bh[ni >> 1][(ni & 1) * 2]);
#pragma unroll
                for (int ni = 0; ni < 8; ni++)
                    mma_f16(sf[ni], qfl[ks], &bh[ni >> 1][(ni & 1) * 2]);
            }

            int row0 = q0 + wm * 16 + t4, row1 = row0 + 8;
            bool needm = (kb + 63 > q0 + wm * 16);
            float mx0 = -1e30f, mx1 = -1e30f;
#pragma unroll
            for (int ni = 0; ni < 8; ni++) {
                int c = kb + ni * 8 + t2 * 2;
                float s0 = sf[ni][0] * 0.125f, s1 = sf[ni][1] * 0.125f;
                float s2 = sf[ni][2] * 0.125f, s3 = sf[ni][3] * 0.125f;
                if (needm) {
                    if (c > row0)     s0 = -1e30f;
                    if (c + 1 > row0) s1 = -1e30f;
                    if (c > row1)     s2 = -1e30f;
                    if (c + 1 > row1) s3 = -1e30f;
                }
                sf[ni][0] = s0; sf[ni][1] = s1; sf[ni][2] = s2; sf[ni][3] = s3;
                mx0 = fmaxf(mx0, fmaxf(s0, s1));
                mx1 = fmaxf(mx1, fmaxf(s2, s3));
            }
            mx0 = fmaxf(mx0, __shfl_xor_sync(0xffffffffu, mx0, 1));
            mx0 = fmaxf(mx0, __shfl_xor_sync(0xffffffffu, mx0, 2));
            mx1 = fmaxf(mx1, __shfl_xor_sync(0xffffffffu, mx1, 1));
            mx1 = fmaxf(mx1, __shfl_xor_sync(0xffffffffu, mx1, 2));
            float nm0 = fmaxf(m0, mx0), nm1 = fmaxf(m1, mx1);
            float cr0 = __expf(m0 - nm0), cr1 = __expf(m1 - nm1);
            m0 = nm0; m1 = nm1;
            l0 *= cr0; l1 *= cr1;
#pragma unroll
            for (int ni = 0; ni < 8; ni++) {
                float p0 = __expf(sf[ni][0] - m0), p1 = __expf(sf[ni][1] - m0);
                float p2 = __expf(sf[ni][2] - m1), p3 = __expf(sf[ni][3] - m1);
                sf[ni][0] = p0; sf[ni][1] = p1; sf[ni][2] = p2; sf[ni][3] = p3;
                l0 += p0 + p1; l1 += p2 + p3;
                of[ni][0] *= cr0; of[ni][1] *= cr0; of[ni][2] *= cr1; of[ni][3] *= cr1;
            }

#pragma unroll
            for (int ks2 = 0; ks2 < 4; ks2++) {
                int n0b = 2 * ks2, n1b = n0b + 1;
                uint32_t pah[4];
                pah[0] = pack2h(sf[n0b][0], sf[n0b][1]);
                pah[1] = pack2h(sf[n0b][2], sf[n0b][3]);
                pah[2] = pack2h(sf[n1b][0], sf[n1b][1]);
                pah[3] = pack2h(sf[n1b][2], sf[n1b][3]);
                uint32_t vh[4][4];
#pragma unroll
                for (int p = 0; p < 4; p++)
                    ldm4t(vh[p], base + KVTILE + (uint32_t)((ks2 * 16) * PADB + p * 32) + a_off);
#pragma unroll
                for (int ni = 0; ni < 8; ni++)
                    mma_f16(of[ni], pah, &vh[ni >> 1][(ni & 1) * 2]);
            }
        }
        __syncthreads();
    }
#undef LOAD_TILE

    l0 += __shfl_xor_sync(0xffffffffu, l0, 1);
    l0 += __shfl_xor_sync(0xffffffffu, l0, 2);
    l1 += __shfl_xor_sync(0xffffffffu, l1, 1);
    l1 += __shfl_xor_sync(0xffffffffu, l1, 2);
    float inv0 = ASCALE / l0, inv1 = ASCALE / l1;   // fold x256 A-scale into normalize

    int row0 = q0 + wm * 16 + t4;
#pragma unroll
    for (int ni = 0; ni < 8; ni++) {
        int col = h * HS + ni * 8 + t2 * 2;
        float s0 = of[ni][0] * inv0, s1 = of[ni][1] * inv0;
        float s2 = of[ni][2] * inv1, s3 = of[ni][3] * inv1;
        size_t o0 = ((size_t)(b * CTX) + row0) * DM + col;
        size_t o1 = o0 + (size_t)8 * DM;
        *(uint32_t*)(g_a16h + o0) = pack2h(s0, s1);
        *(uint32_t*)(g_a16h + o1) = pack2h(s2, s3);
    }
}

// ================= launch =================
extern "C" void kernel_launch(void* const* d_in, const int* in_sizes, int n_in,
                              void* d_out, int out_size)
{
    const float* x  = (const float*)d_in[0];
    const float* Wq = (const float*)d_in[1];
    const float* Wk = (const float*)d_in[2];
    const float* Wv = (const float*)d_in[3];
    const float* W1 = (const float*)d_in[4];
    const float* b1 = (const float*)d_in[5];
    const float* W2 = (const float*)d_in[6];
    const float* b2 = (const float*)d_in[7];
    float* out = (float*)d_out;

    f16 *qa, *qb, *k16, *v16;
    f16 *x16h, *a16h, *h16h, *bq16, *w116, *w216;
    cudaGetSymbolAddress((void**)&qa, g_q16a);
    cudaGetSymbolAddress((void**)&qb, g_q16b);
    cudaGetSymbolAddress((void**)&k16, g_k16);
    cudaGetSymbolAddress((void**)&v16, g_v16);
    cudaGetSymbolAddress((void**)&x16h, g_x16h);
    cudaGetSymbolAddress((void**)&a16h, g_a16h);
    cudaGetSymbolAddress((void**)&h16h, g_h16h);
    cudaGetSymbolAddress((void**)&bq16, g_bq16);
    cudaGetSymbolAddress((void**)&w116, g_w116);
    cudaGetSymbolAddress((void**)&w216, g_w216);

    cudaFuncSetAttribute((const void*)gemm_f16<0>, cudaFuncAttributeMaxDynamicSharedMemorySize, GEMM_SMEM);
    cudaFuncSetAttribute((const void*)gemm_f16<1>, cudaFuncAttributeMaxDynamicSharedMemorySize, GEMM_SMEM);
    cudaFuncSetAttribute((const void*)gemm_f16<2>, cudaFuncAttributeMaxDynamicSharedMemorySize, GEMM_SMEM);
    cudaFuncSetAttribute(attn_mma, cudaFuncAttributeMaxDynamicSharedMemorySize, ATTN_SMEM);

    // input conversions
    conv_x_kernel<<<(size_t)MTOT * NEMB / 1024, 256>>>(x, x16h);
    qkv_transpose_h<<<dim3(NEMB / 32, HS / 32, 48), dim3(32, 8)>>>(Wq, Wk, Wv, bq16);
    transpose_h<<<dim3(FF / 32, DM / 32), dim3(32, 8)>>>(W1, w116, DM, FF);
    transpose_h<<<dim3(DM / 32, FF / 32), dim3(32, 8)>>>(W2, w216, FF, DM);

    // QKV: [8192,1024] @ [1024,3072] -> q fp16 hi/lo, k/v fp16, [B,H,T,D]
    gemm_f16<0><<<dim3(3 * DM / 256, MTOT / 128), 256, GEMM_SMEM>>>(
        x16h, bq16, nullptr,
        nullptr, nullptr,
        qa, qb, k16, v16, 3 * DM, NEMB);

    // attention -> att fp16 x256
    attn_mma<<<dim3(CTX / 128, NH, BATCH), 256, ATTN_SMEM>>>();

    // FFN1: [8192,1024] @ [1024,4096] + b1 -> h fp16 x256
    gemm_f16<1><<<dim3(FF / 256, MTOT / 128), 256, GEMM_SMEM>>>(
        a16h, w116, b1,
        nullptr, h16h,
        nullptr, nullptr, nullptr, nullptr, FF, DM);

    // FFN2: [8192,4096] @ [4096,1024] + b2, relu -> out
    gemm_f16<2><<<dim3(DM / 256, MTOT / 128), 256, GEMM_SMEM>>>(
        h16h, w216, b2,
        out, nullptr,
        nullptr, nullptr, nullptr, nullptr, DM, FF);
}

// round 13
// speedup vs baseline: 3.0540x; 1.0567x over previous
#include <cuda_runtime.h>
#include <cuda_bf16.h>
#include <cuda_fp16.h>
#include <cstdint>

#define BATCH 4
#define CTX   2048
#define NEMB  1024
#define NH    16
#define HS    64
#define DM    1024
#define FF    4096
#define MTOT  (BATCH*CTX)   // 8192

typedef __half f16;

// ================= scratch =================
// attention operands: single fp16
__device__ f16 g_q16[(size_t)BATCH*NH*CTX*HS];
__device__ f16 g_k16[(size_t)BATCH*NH*CTX*HS];
__device__ f16 g_v16[(size_t)BATCH*NH*CTX*HS];
// GEMM activations: single fp16, pre-scaled x256
__device__ f16 g_x16h[(size_t)MTOT*NEMB];
__device__ f16 g_a16h[(size_t)MTOT*DM];
__device__ f16 g_h16h[(size_t)MTOT*FF];
// GEMM weights: single fp16, [N,K]
__device__ f16 g_bq16[(size_t)3*DM*NEMB];
__device__ f16 g_w116[(size_t)FF*DM];
__device__ f16 g_w216[(size_t)DM*FF];

#define ASCALE 256.f
#define INVASC (1.f/256.f)

__device__ __forceinline__ uint32_t pack2h(float a, float b) {
    __half2 p = __floats2half2_rn(a, b);
    return *reinterpret_cast<uint32_t*>(&p);
}
__device__ __forceinline__ uint32_t smem_u32(const void* p) {
    uint32_t a;
    asm("{ .reg .u64 t; cvta.to.shared.u64 t, %1; cvt.u32.u64 %0, t; }" : "=r"(a) : "l"(p));
    return a;
}
__device__ __forceinline__ void cp16(uint32_t dst, const void* src) {
    asm volatile("cp.async.cg.shared.global [%0], [%1], 16;" :: "r"(dst), "l"(src));
}
#define CP_COMMIT() asm volatile("cp.async.commit_group;" ::: "memory")
#define CP_WAIT(n)  asm volatile("cp.async.wait_group %0;" :: "n"(n) : "memory")

__device__ __forceinline__ void ldm4(uint32_t* r, uint32_t addr) {
    asm volatile("ldmatrix.sync.aligned.m8n8.x4.shared.b16 {%0,%1,%2,%3}, [%4];"
        : "=r"(r[0]), "=r"(r[1]), "=r"(r[2]), "=r"(r[3]) : "r"(addr));
}
__device__ __forceinline__ void ldm4t(uint32_t* r, uint32_t addr) {
    asm volatile("ldmatrix.sync.aligned.m8n8.x4.trans.shared.b16 {%0,%1,%2,%3}, [%4];"
        : "=r"(r[0]), "=r"(r[1]), "=r"(r[2]), "=r"(r[3]) : "r"(addr));
}
__device__ __forceinline__ void mma_f16(float* d, const uint32_t* a, const uint32_t* b) {
    asm volatile("mma.sync.aligned.m16n8k16.row.col.f32.f16.f16.f32 "
        "{%0,%1,%2,%3}, {%4,%5,%6,%7}, {%8,%9}, {%0,%1,%2,%3};"
        : "+f"(d[0]), "+f"(d[1]), "+f"(d[2]), "+f"(d[3])
        : "r"(a[0]), "r"(a[1]), "r"(a[2]), "r"(a[3]), "r"(b[0]), "r"(b[1]));
}

// ================= convert / transpose kernels =================
// x -> fp16, scaled x256
__global__ __launch_bounds__(256) void conv_x_kernel(const float* __restrict__ x,
                                                     f16* __restrict__ hi)
{
    size_t i = (size_t)blockIdx.x * 256 + threadIdx.x;
    float4 v = ((const float4*)x)[i];
    ((uint2*)hi)[i] = make_uint2(pack2h(v.x * ASCALE, v.y * ASCALE),
                                 pack2h(v.z * ASCALE, v.w * ASCALE));
}

// W [K,N] row-major -> out [N,K] single fp16
__global__ __launch_bounds__(256) void transpose_h(const float* __restrict__ W,
                                                   f16* __restrict__ out, int K, int N)
{
    __shared__ float t[32][33];
    int n0 = blockIdx.x * 32, k0 = blockIdx.y * 32;
    int tx = threadIdx.x, ty = threadIdx.y;
#pragma unroll
    for (int i = ty; i < 32; i += 8)
        t[i][tx] = W[(size_t)(k0 + i) * N + n0 + tx];
    __syncthreads();
#pragma unroll
    for (int i = ty; i < 32; i += 8)
        out[(size_t)(n0 + i) * K + k0 + tx] = __float2half_rn(t[tx][i]);
}

// Wq/Wk/Wv [H,C,D] -> bqkv[n = sel*1024 + h*64 + d][k = c], single fp16
__global__ __launch_bounds__(256) void qkv_transpose_h(const float* __restrict__ Wq,
                                                       const float* __restrict__ Wk,
                                                       const float* __restrict__ Wv,
                                                       f16* __restrict__ out)
{
    __shared__ float t[32][33];
    int sel = blockIdx.z >> 4, h = blockIdx.z & 15;
    const float* W = (sel == 0 ? Wq : sel == 1 ? Wk : Wv) + (size_t)h * NEMB * HS;
    int c0 = blockIdx.x * 32, d0 = blockIdx.y * 32;
    int tx = threadIdx.x, ty = threadIdx.y;
#pragma unroll
    for (int i = ty; i < 32; i += 8)
        t[i][tx] = W[(size_t)(c0 + i) * HS + d0 + tx];
    __syncthreads();
    int nbase = sel * DM + h * HS + d0;
#pragma unroll
    for (int i = ty; i < 32; i += 8)
        out[(size_t)(nbase + i) * NEMB + c0 + tx] = __float2half_rn(t[tx][i]);
}

// ================= single-fp16 GEMM, 128x256 CTA tile, 5-stage =================
// D = Ah * Bh, A pre-scaled x256, rescale 1/256 in epilogue.
// MODE 0: scatter -> q/k/v single fp16, [B,H,T,D]
// MODE 1: +bias, write fp16 x256 (FFN1 -> h)
// MODE 2: +bias, relu, write fp32 (FFN2 -> out)
#define ROWB    80
#define TA      (128*ROWB)   // 10240
#define TBL     (256*ROWB)   // 20480
#define OFF_BH  (TA)
#define STAGE_B (TA + TBL)       // 30720
#define NSTAGE  5
#define GEMM_SMEM (NSTAGE*STAGE_B)   // 153600

template <int MODE>
__global__ __launch_bounds__(256, 1)
void gemm_f16(const f16* __restrict__ Ahi,
              const f16* __restrict__ Bh,
              const float* __restrict__ bias,
              float* __restrict__ out_f, f16* __restrict__ out_hi,
              f16* __restrict__ qq, f16* __restrict__ kk, f16* __restrict__ vv,
              int N, int K)
{
    extern __shared__ char smem[];
    uint32_t sb = smem_u32(smem);

    int tid = threadIdx.x, wid = tid >> 5, lid = tid & 31;
    int wm = wid >> 2, wn = wid & 3;          // warp tile 64(M) x 64(N)
    int bx = blockIdx.x, by = blockIdx.y;

    const f16* aH = Ahi + (size_t)by * 128 * K;
    const f16* bH = Bh + (size_t)bx * 256 * K;

    float acc[4][8][4];
#pragma unroll
    for (int i = 0; i < 4; i++)
#pragma unroll
        for (int j = 0; j < 8; j++)
#pragma unroll
            for (int l = 0; l < 4; l++) acc[i][j][l] = 0.f;

    int ITERS = K >> 5;

#define ISSUE(st, k0) do {                                                         \
        uint32_t _b = sb + (st) * STAGE_B;                                         \
        _Pragma("unroll")                                                          \
        for (int _i = 0; _i < 2; _i++) {                                           \
            int _c = tid + _i * 256; int _r = _c >> 2, _q = _c & 3;                \
            uint32_t _so = (uint32_t)(_r * ROWB + _q * 16);                        \
            size_t _g = (size_t)_r * K + (k0) + _q * 8;                            \
            cp16(_b + _so, aH + _g);                                               \
        }                                                                          \
        _Pragma("unroll")                                                          \
        for (int _i = 0; _i < 4; _i++) {                                           \
            int _c = tid + _i * 256; int _r = _c >> 2, _q = _c & 3;                \
            uint32_t _so = (uint32_t)(_r * ROWB + _q * 16);                        \
            size_t _g = (size_t)_r * K + (k0) + _q * 8;                            \
            cp16(_b + OFF_BH + _so, bH + _g);                                      \
        }                                                                          \
    } while (0)

#pragma unroll
    for (int s = 0; s < NSTAGE - 1; s++) { ISSUE(s, s * 32); CP_COMMIT(); }

    int g = lid >> 3, rr = lid & 7;
    uint32_t a_row_off = (uint32_t)(((g & 1) * 8 + rr) * ROWB + (g >> 1) * 16);
    uint32_t b_row_off = (uint32_t)(((g >> 1) * 8 + rr) * ROWB + (g & 1) * 16);

    for (int it = 0; it < ITERS; it++) {
        CP_WAIT(NSTAGE - 2);        // stage it resident
        __syncthreads();            // all warps done with stage it-1 (aliased by it+NSTAGE-1)
        int pre = it + NSTAGE - 1;
        if (pre < ITERS) { ISSUE(pre % NSTAGE, pre * 32); }
        CP_COMMIT();

        uint32_t base = sb + (it % NSTAGE) * STAGE_B;
#pragma unroll
        for (int ks = 0; ks < 2; ks++) {
            uint32_t ah[4][4], bh[4][4];
#pragma unroll
            for (int mi = 0; mi < 4; mi++)
                ldm4(ah[mi], base + (uint32_t)((wm * 64 + mi * 16) * ROWB + ks * 32) + a_row_off);
#pragma unroll
            for (int p = 0; p < 4; p++)
                ldm4(bh[p], base + OFF_BH + (uint32_t)((wn * 64 + p * 16) * ROWB + ks * 32) + b_row_off);
#pragma unroll
            for (int mi = 0; mi < 4; mi++)
#pragma unroll
                for (int ni = 0; ni < 8; ni++)
                    mma_f16(acc[mi][ni], ah[mi], &bh[ni >> 1][(ni & 1) * 2]);
        }
    }
#undef ISSUE

    // ---------------- epilogue (rescale 1/256) ----------------
    int t4 = lid >> 2, t2 = (lid & 3) * 2;
#pragma unroll
    for (int mi = 0; mi < 4; mi++) {
#pragma unroll
        for (int ni = 0; ni < 8; ni++) {
            int n = bx * 256 + wn * 64 + ni * 8 + t2;
            int m0 = by * 128 + wm * 64 + mi * 16 + t4;
            float bn0 = 0.f, bn1 = 0.f;
            if (MODE != 0) { bn0 = bias[n]; bn1 = bias[n + 1]; }
#pragma unroll
            for (int half = 0; half < 2; half++) {
                int m = m0 + half * 8;
                float v0 = acc[mi][ni][half * 2]     * INVASC;
                float v1 = acc[mi][ni][half * 2 + 1] * INVASC;
                if (MODE == 0) {
                    int b = m >> 11, t = m & (CTX - 1);
                    int sel = n >> 10, hh = (n & 1023) >> 6, d0 = n & 63;
                    f16* dst = (sel == 0) ? qq : (sel == 1 ? kk : vv);
                    size_t o = ((size_t)(b * NH + hh) * CTX + t) * HS + d0;
                    *(uint32_t*)(dst + o) = pack2h(v0, v1);
                } else if (MODE == 1) {
                    float s0 = (v0 + bn0) * ASCALE;
                    float s1 = (v1 + bn1) * ASCALE;
                    size_t o = (size_t)m * N + n;
                    *(uint32_t*)(out_hi + o) = pack2h(s0, s1);
                } else {
                    v0 = fmaxf(v0 + bn0, 0.f);
                    v1 = fmaxf(v1 + bn1, 0.f);
                    *(float2*)(out_f + (size_t)m * N + n) = make_float2(v0, v1);
                }
            }
        }
    }
}

// ================= mma.sync causal flash attention (single fp16) =================
// QK: Q * K (1 MMA pass); PV: P * V (1 MMA pass). fp32 accum.
// 128 queries/CTA, 8 warps x 16 rows; Bc=64 key tile; double-buffered K/V.
// V stored [T,D]; PV B-fragments via ldmatrix.trans.
// Epilogue writes fp16 x256 for FFN1's A operand.  Occupancy 2.
#define PADB   144
#define QTILE  (128*PADB)       // 18432
#define KVTILE (64*PADB)        // 9216
#define ASTAGE (2*KVTILE)       // 18432
#define ATTN_SMEM (QTILE + 2*ASTAGE)   // 55296

__global__ __launch_bounds__(256, 2)
void attn_mma()
{
    extern __shared__ char smem[];
    uint32_t sb = smem_u32(smem);
    int tid = threadIdx.x, wid = tid >> 5, lid = tid & 31;
    int qt = blockIdx.x, h = blockIdx.y, b = blockIdx.z;
    int q0 = qt * 128;
    int wm = wid;
    int g = lid >> 3, rr = lid & 7;
    uint32_t a_off = (uint32_t)(((g & 1) * 8 + rr) * PADB + (g >> 1) * 16);
    uint32_t b_off = (uint32_t)(((g >> 1) * 8 + rr) * PADB + (g & 1) * 16);
    int t4 = lid >> 2, t2 = lid & 3;

    size_t hb = (size_t)(b * NH + h);
    const f16* qB = g_q16 + hb * CTX * HS;
    const f16* kB = g_k16 + hb * CTX * HS;
    const f16* vB = g_v16 + hb * CTX * HS;

    // Q tile (128 x 64)
#pragma unroll
    for (int i = 0; i < 4; i++) {
        int idx = tid + i * 256;
        int r = idx >> 3, ch = idx & 7;
        cp16(sb + (uint32_t)(r * PADB + ch * 16), qB + (size_t)(q0 + r) * HS + ch * 8);
    }
    CP_COMMIT();

#define LOAD_TILE(st, kb_) do {                                            \
        uint32_t bs = sb + QTILE + (st) * ASTAGE;                          \
        for (int i_ = 0; i_ < 2; i_++) {                                   \
            int idx_ = tid + i_ * 256;                                     \
            int r_ = idx_ >> 3, ch_ = idx_ & 7;                            \
            uint32_t so_ = (uint32_t)(r_ * PADB + ch_ * 16);               \
            size_t kg_ = (size_t)((kb_) + r_) * HS + ch_ * 8;              \
            cp16(bs + so_, kB + kg_);                                      \
            cp16(bs + KVTILE + so_, vB + kg_);                             \
        } } while (0)

    LOAD_TILE(0, 0);
    CP_COMMIT();

    uint32_t qf[4][4];
    float of[8][4];
#pragma unroll
    for (int i = 0; i < 8; i++)
#pragma unroll
        for (int j = 0; j < 4; j++) of[i][j] = 0.f;
    float m0 = -1e30f, m1 = -1e30f, l0 = 0.f, l1 = 0.f;
    bool qload = false;

    int nkt = 2 * qt + 2;
    for (int kt = 0; kt < nkt; kt++) {
        int kb = kt * 64;
        if (kt + 1 < nkt) { LOAD_TILE((kt + 1) & 1, kb + 64); CP_COMMIT(); CP_WAIT(1); }
        else { CP_WAIT(0); }
        __syncthreads();
        if (!qload) {
#pragma unroll
            for (int ks = 0; ks < 4; ks++)
                ldm4(qf[ks], sb + (uint32_t)((wm * 16) * PADB + ks * 32) + a_off);
            qload = true;
        }
        if (q0 + wm * 16 + 15 >= kb) {
            uint32_t base = sb + QTILE + (kt & 1) * ASTAGE;
            float sf[8][4];
#pragma unroll
            for (int i = 0; i < 8; i++)
#pragma unroll
                for (int j = 0; j < 4; j++) sf[i][j] = 0.f;

#pragma unroll
            for (int ks = 0; ks < 4; ks++) {
                uint32_t bh[4][4];
#pragma unroll
                for (int p = 0; p < 4; p++)
                    ldm4(bh[p], base + (uint32_t)((p * 16) * PADB + ks * 32) + b_off);
#pragma unroll
                for (int ni = 0; ni < 8; ni++)
                    mma_f16(sf[ni], qf[ks], &bh[ni >> 1][(ni & 1) * 2]);
            }

            int row0 = q0 + wm * 16 + t4, row1 = row0 + 8;
            bool needm = (kb + 63 > q0 + wm * 16);
            float mx0 = -1e30f, mx1 = -1e30f;
#pragma unroll
            for (int ni = 0; ni < 8; ni++) {
                int c = kb + ni * 8 + t2 * 2;
                float s0 = sf[ni][0] * 0.125f, s1 = sf[ni][1] * 0.125f;
                float s2 = sf[ni][2] * 0.125f, s3 = sf[ni][3] * 0.125f;
                if (needm) {
                    if (c > row0)     s0 = -1e30f;
                    if (c + 1 > row0) s1 = -1e30f;
                    if (c > row1)     s2 = -1e30f;
                    if (c + 1 > row1) s3 = -1e30f;
                }
                sf[ni][0] = s0; sf[ni][1] = s1; sf[ni][2] = s2; sf[ni][3] = s3;
                mx0 = fmaxf(mx0, fmaxf(s0, s1));
                mx1 = fmaxf(mx1, fmaxf(s2, s3));
            }
            mx0 = fmaxf(mx0, __shfl_xor_sync(0xffffffffu, mx0, 1));
            mx0 = fmaxf(mx0, __shfl_xor_sync(0xffffffffu, mx0, 2));
            mx1 = fmaxf(mx1, __shfl_xor_sync(0xffffffffu, mx1, 1));
            mx1 = fmaxf(mx1, __shfl_xor_sync(0xffffffffu, mx1, 2));
            float nm0 = fmaxf(m0, mx0), nm1 = fmaxf(m1, mx1);
            float cr0 = __expf(m0 - nm0), cr1 = __expf(m1 - nm1);
            m0 = nm0; m1 = nm1;
            l0 *= cr0; l1 *= cr1;
#pragma unroll
            for (int ni = 0; ni < 8; ni++) {
                float p0 = __expf(sf[ni][0] - m0), p1 = __expf(sf[ni][1] - m0);
                float p2 = __expf(sf[ni][2] - m1), p3 = __expf(sf[ni][3] - m1);
                sf[ni][0] = p0; sf[ni][1] = p1; sf[ni][2] = p2; sf[ni][3] = p3;
                l0 += p0 + p1; l1 += p2 + p3;
                of[ni][0] *= cr0; of[ni][1] *= cr0; of[ni][2] *= cr1; of[ni][3] *= cr1;
            }

#pragma unroll
            for (int ks2 = 0; ks2 < 4; ks2++) {
                int n0b = 2 * ks2, n1b = n0b + 1;
                uint32_t pah[4];
                pah[0] = pack2h(sf[n0b][0], sf[n0b][1]);
                pah[1] = pack2h(sf[n0b][2], sf[n0b][3]);
                pah[2] = pack2h(sf[n1b][0], sf[n1b][1]);
                pah[3] = pack2h(sf[n1b][2], sf[n1b][3]);
                uint32_t vh[4][4];
#pragma unroll
                for (int p = 0; p < 4; p++)
                    ldm4t(vh[p], base + KVTILE + (uint32_t)((ks2 * 16) * PADB + p * 32) + a_off);
#pragma unroll
                for (int ni = 0; ni < 8; ni++)
                    mma_f16(of[ni], pah, &vh[ni >> 1][(ni & 1) * 2]);
            }
        }
        __syncthreads();
    }
#undef LOAD_TILE

    l0 += __shfl_xor_sync(0xffffffffu, l0, 1);
    l0 += __shfl_xor_sync(0xffffffffu, l0, 2);
    l1 += __shfl_xor_sync(0xffffffffu, l1, 1);
    l1 += __shfl_xor_sync(0xffffffffu, l1, 2);
    float inv0 = ASCALE / l0, inv1 = ASCALE / l1;   // fold x256 A-scale into normalize

    int row0 = q0 + wm * 16 + t4;
#pragma unroll
    for (int ni = 0; ni < 8; ni++) {
        int col = h * HS + ni * 8 + t2 * 2;
        float s0 = of[ni][0] * inv0, s1 = of[ni][1] * inv0;
        float s2 = of[ni][2] * inv1, s3 = of[ni][3] * inv1;
        size_t o0 = ((size_t)(b * CTX) + row0) * DM + col;
        size_t o1 = o0 + (size_t)8 * DM;
        *(uint32_t*)(g_a16h + o0) = pack2h(s0, s1);
        *(uint32_t*)(g_a16h + o1) = pack2h(s2, s3);
    }
}

// ================= launch =================
extern "C" void kernel_launch(void* const* d_in, const int* in_sizes, int n_in,
                              void* d_out, int out_size)
{
    const float* x  = (const float*)d_in[0];
    const float* Wq = (const float*)d_in[1];
    const float* Wk = (const float*)d_in[2];
    const float* Wv = (const float*)d_in[3];
    const float* W1 = (const float*)d_in[4];
    const float* b1 = (const float*)d_in[5];
    const float* W2 = (const float*)d_in[6];
    const float* b2 = (const float*)d_in[7];
    float* out = (float*)d_out;

    f16 *q16, *k16, *v16;
    f16 *x16h, *a16h, *h16h, *bq16, *w116, *w216;
    cudaGetSymbolAddress((void**)&q16, g_q16);
    cudaGetSymbolAddress((void**)&k16, g_k16);
    cudaGetSymbolAddress((void**)&v16, g_v16);
    cudaGetSymbolAddress((void**)&x16h, g_x16h);
    cudaGetSymbolAddress((void**)&a16h, g_a16h);
    cudaGetSymbolAddress((void**)&h16h, g_h16h);
    cudaGetSymbolAddress((void**)&bq16, g_bq16);
    cudaGetSymbolAddress((void**)&w116, g_w116);
    cudaGetSymbolAddress((void**)&w216, g_w216);

    cudaFuncSetAttribute((const void*)gemm_f16<0>, cudaFuncAttributeMaxDynamicSharedMemorySize, GEMM_SMEM);
    cudaFuncSetAttribute((const void*)gemm_f16<1>, cudaFuncAttributeMaxDynamicSharedMemorySize, GEMM_SMEM);
    cudaFuncSetAttribute((const void*)gemm_f16<2>, cudaFuncAttributeMaxDynamicSharedMemorySize, GEMM_SMEM);
    cudaFuncSetAttribute(attn_mma, cudaFuncAttributeMaxDynamicSharedMemorySize, ATTN_SMEM);

    // input conversions
    conv_x_kernel<<<(size_t)MTOT * NEMB / 1024, 256>>>(x, x16h);
    qkv_transpose_h<<<dim3(NEMB / 32, HS / 32, 48), dim3(32, 8)>>>(Wq, Wk, Wv, bq16);
    transpose_h<<<dim3(FF / 32, DM / 32), dim3(32, 8)>>>(W1, w116, DM, FF);
    transpose_h<<<dim3(DM / 32, FF / 32), dim3(32, 8)>>>(W2, w216, FF, DM);

    // QKV: [8192,1024] @ [1024,3072] -> q/k/v single fp16 [B,H,T,D]
    gemm_f16<0><<<dim3(3 * DM / 256, MTOT / 128), 256, GEMM_SMEM>>>(
        x16h, bq16, nullptr,
        nullptr, nullptr,
        q16, k16, v16, 3 * DM, NEMB);

    // attention -> att fp16 x256
    attn_mma<<<dim3(CTX / 128, NH, BATCH), 256, ATTN_SMEM>>>();

    // FFN1: [8192,1024] @ [1024,4096] + b1 -> h fp16 x256
    gemm_f16<1><<<dim3(FF / 256, MTOT / 128), 256, GEMM_SMEM>>>(
        a16h, w116, b1,
        nullptr, h16h,
        nullptr, nullptr, nullptr, FF, DM);

    // FFN2: [8192,4096] @ [4096,1024] + b2, relu -> out
    gemm_f16<2><<<dim3(DM / 256, MTOT / 128), 256, GEMM_SMEM>>>(
        h16h, w216, b2,
        out, nullptr,
        nullptr, nullptr, nullptr, DM, FF);
}

// round 14
// speedup vs baseline: 3.5049x; 1.1476x over previous
#include <cuda_runtime.h>
#include <cuda_bf16.h>
#include <cuda_fp16.h>
#include <cstdint>

#define BATCH 4
#define CTX   2048
#define NEMB  1024
#define NH    16
#define HS    64
#define DM    1024
#define FF    4096
#define MTOT  (BATCH*CTX)   // 8192

typedef __half f16;

// ================= scratch =================
__device__ f16 g_q16[(size_t)BATCH*NH*CTX*HS];
__device__ f16 g_k16[(size_t)BATCH*NH*CTX*HS];
__device__ f16 g_v16[(size_t)BATCH*NH*CTX*HS];
__device__ f16 g_x16h[(size_t)MTOT*NEMB];
__device__ f16 g_a16h[(size_t)MTOT*DM];
__device__ f16 g_h16h[(size_t)MTOT*FF];
__device__ f16 g_bq16[(size_t)3*DM*NEMB];
__device__ f16 g_w116[(size_t)FF*DM];
__device__ f16 g_w216[(size_t)DM*FF];

#define ASCALE 256.f
#define INVASC (1.f/256.f)
#define SCLQK  0.180336884f   // 0.125 * log2(e)

__device__ __forceinline__ uint32_t pack2h(float a, float b) {
    __half2 p = __floats2half2_rn(a, b);
    return *reinterpret_cast<uint32_t*>(&p);
}
__device__ __forceinline__ uint32_t smem_u32(const void* p) {
    uint32_t a;
    asm("{ .reg .u64 t; cvta.to.shared.u64 t, %1; cvt.u32.u64 %0, t; }" : "=r"(a) : "l"(p));
    return a;
}
__device__ __forceinline__ void cp16(uint32_t dst, const void* src) {
    asm volatile("cp.async.cg.shared.global [%0], [%1], 16;" :: "r"(dst), "l"(src));
}
#define CP_COMMIT() asm volatile("cp.async.commit_group;" ::: "memory")
#define CP_WAIT(n)  asm volatile("cp.async.wait_group %0;" :: "n"(n) : "memory")

__device__ __forceinline__ void ldm4(uint32_t* r, uint32_t addr) {
    asm volatile("ldmatrix.sync.aligned.m8n8.x4.shared.b16 {%0,%1,%2,%3}, [%4];"
        : "=r"(r[0]), "=r"(r[1]), "=r"(r[2]), "=r"(r[3]) : "r"(addr));
}
__device__ __forceinline__ void ldm4t(uint32_t* r, uint32_t addr) {
    asm volatile("ldmatrix.sync.aligned.m8n8.x4.trans.shared.b16 {%0,%1,%2,%3}, [%4];"
        : "=r"(r[0]), "=r"(r[1]), "=r"(r[2]), "=r"(r[3]) : "r"(addr));
}
__device__ __forceinline__ void mma_f16(float* d, const uint32_t* a, const uint32_t* b) {
    asm volatile("mma.sync.aligned.m16n8k16.row.col.f32.f16.f16.f32 "
        "{%0,%1,%2,%3}, {%4,%5,%6,%7}, {%8,%9}, {%0,%1,%2,%3};"
        : "+f"(d[0]), "+f"(d[1]), "+f"(d[2]), "+f"(d[3])
        : "r"(a[0]), "r"(a[1]), "r"(a[2]), "r"(a[3]), "r"(b[0]), "r"(b[1]));
}

// ================= convert / transpose kernels =================
__global__ __launch_bounds__(256) void conv_x_kernel(const float* __restrict__ x,
                                                     f16* __restrict__ hi)
{
    size_t i = (size_t)blockIdx.x * 256 + threadIdx.x;
    float4 v = ((const float4*)x)[i];
    ((uint2*)hi)[i] = make_uint2(pack2h(v.x * ASCALE, v.y * ASCALE),
                                 pack2h(v.z * ASCALE, v.w * ASCALE));
}

__global__ __launch_bounds__(256) void transpose_h(const float* __restrict__ W,
                                                   f16* __restrict__ out, int K, int N)
{
    __shared__ float t[32][33];
    int n0 = blockIdx.x * 32, k0 = blockIdx.y * 32;
    int tx = threadIdx.x, ty = threadIdx.y;
#pragma unroll
    for (int i = ty; i < 32; i += 8)
        t[i][tx] = W[(size_t)(k0 + i) * N + n0 + tx];
    __syncthreads();
#pragma unroll
    for (int i = ty; i < 32; i += 8)
        out[(size_t)(n0 + i) * K + k0 + tx] = __float2half_rn(t[tx][i]);
}

__global__ __launch_bounds__(256) void qkv_transpose_h(const float* __restrict__ Wq,
                                                       const float* __restrict__ Wk,
                                                       const float* __restrict__ Wv,
                                                       f16* __restrict__ out)
{
    __shared__ float t[32][33];
    int sel = blockIdx.z >> 4, h = blockIdx.z & 15;
    const float* W = (sel == 0 ? Wq : sel == 1 ? Wk : Wv) + (size_t)h * NEMB * HS;
    int c0 = blockIdx.x * 32, d0 = blockIdx.y * 32;
    int tx = threadIdx.x, ty = threadIdx.y;
#pragma unroll
    for (int i = ty; i < 32; i += 8)
        t[i][tx] = W[(size_t)(c0 + i) * HS + d0 + tx];
    __syncthreads();
    int nbase = sel * DM + h * HS + d0;
#pragma unroll
    for (int i = ty; i < 32; i += 8)
        out[(size_t)(nbase + i) * NEMB + c0 + tx] = __float2half_rn(t[tx][i]);
}

// ================= single-fp16 GEMM, 128x256 CTA tile, BK=64, 3-stage =================
// D = Ah * Bh, A pre-scaled x256, rescale 1/256 in epilogue.
// MODE 0: scatter -> q/k/v single fp16, [B,H,T,D]
// MODE 1: +bias, write fp16 x256 (FFN1 -> h)
// MODE 2: +bias, relu, write fp32 (FFN2 -> out)
#define ROWB    144           // 64 fp16 = 128B + 16B pad (conflict-free ldmatrix)
#define TA      (128*ROWB)    // 18432
#define TBL     (256*ROWB)    // 36864
#define OFF_BH  (TA)
#define STAGE_B (TA + TBL)    // 55296
#define NSTAGE  3
#define GEMM_SMEM (NSTAGE*STAGE_B)   // 165888

template <int MODE>
__global__ __launch_bounds__(256, 1)
void gemm_f16(const f16* __restrict__ Ahi,
              const f16* __restrict__ Bh,
              const float* __restrict__ bias,
              float* __restrict__ out_f, f16* __restrict__ out_hi,
              f16* __restrict__ qq, f16* __restrict__ kk, f16* __restrict__ vv,
              int N, int K)
{
    extern __shared__ char smem[];
    uint32_t sb = smem_u32(smem);

    int tid = threadIdx.x, wid = tid >> 5, lid = tid & 31;
    int wm = wid >> 2, wn = wid & 3;          // warp tile 64(M) x 64(N)
    int bx = blockIdx.x, by = blockIdx.y;

    const f16* aH = Ahi + (size_t)by * 128 * K;
    const f16* bH = Bh + (size_t)bx * 256 * K;

    float acc[4][8][4];
#pragma unroll
    for (int i = 0; i < 4; i++)
#pragma unroll
        for (int j = 0; j < 8; j++)
#pragma unroll
            for (int l = 0; l < 4; l++) acc[i][j][l] = 0.f;

    int ITERS = K >> 6;

#define ISSUE(st, k0) do {                                                         \
        uint32_t _b = sb + (st) * STAGE_B;                                         \
        _Pragma("unroll")                                                          \
        for (int _i = 0; _i < 4; _i++) {                                           \
            int _c = tid + _i * 256; int _r = _c >> 3, _q = _c & 7;                \
            cp16(_b + (uint32_t)(_r * ROWB + _q * 16),                             \
                 aH + (size_t)_r * K + (k0) + _q * 8);                             \
        }                                                                          \
        _Pragma("unroll")                                                          \
        for (int _i = 0; _i < 8; _i++) {                                           \
            int _c = tid + _i * 256; int _r = _c >> 3, _q = _c & 7;                \
            cp16(_b + OFF_BH + (uint32_t)(_r * ROWB + _q * 16),                    \
                 bH + (size_t)_r * K + (k0) + _q * 8);                             \
        }                                                                          \
    } while (0)

    ISSUE(0, 0);  CP_COMMIT();
    ISSUE(1, 64); CP_COMMIT();

    int g = lid >> 3, rr = lid & 7;
    uint32_t a_row_off = (uint32_t)(((g & 1) * 8 + rr) * ROWB + (g >> 1) * 16);
    uint32_t b_row_off = (uint32_t)(((g >> 1) * 8 + rr) * ROWB + (g & 1) * 16);

    for (int it = 0; it < ITERS; it++) {
        CP_WAIT(NSTAGE - 2);        // stage it resident
        __syncthreads();            // all warps done with stage it-1 (aliased by it+2)
        int pre = it + NSTAGE - 1;
        if (pre < ITERS) { ISSUE(pre % NSTAGE, pre * 64); }
        CP_COMMIT();

        uint32_t base = sb + (it % NSTAGE) * STAGE_B;
#pragma unroll
        for (int ks = 0; ks < 4; ks++) {
            uint32_t ah[4][4], bh[4][4];
#pragma unroll
            for (int mi = 0; mi < 4; mi++)
                ldm4(ah[mi], base + (uint32_t)((wm * 64 + mi * 16) * ROWB + ks * 32) + a_row_off);
#pragma unroll
            for (int p = 0; p < 4; p++)
                ldm4(bh[p], base + OFF_BH + (uint32_t)((wn * 64 + p * 16) * ROWB + ks * 32) + b_row_off);
#pragma unroll
            for (int mi = 0; mi < 4; mi++)
#pragma unroll
                for (int ni = 0; ni < 8; ni++)
                    mma_f16(acc[mi][ni], ah[mi], &bh[ni >> 1][(ni & 1) * 2]);
        }
    }
#undef ISSUE

    // ---------------- epilogue (rescale 1/256) ----------------
    int t4 = lid >> 2, t2 = (lid & 3) * 2;
#pragma unroll
    for (int mi = 0; mi < 4; mi++) {
#pragma unroll
        for (int ni = 0; ni < 8; ni++) {
            int n = bx * 256 + wn * 64 + ni * 8 + t2;
            int m0 = by * 128 + wm * 64 + mi * 16 + t4;
            float bn0 = 0.f, bn1 = 0.f;
            if (MODE != 0) { bn0 = bias[n]; bn1 = bias[n + 1]; }
#pragma unroll
            for (int half = 0; half < 2; half++) {
                int m = m0 + half * 8;
                float v0 = acc[mi][ni][half * 2]     * INVASC;
                float v1 = acc[mi][ni][half * 2 + 1] * INVASC;
                if (MODE == 0) {
                    int b = m >> 11, t = m & (CTX - 1);
                    int sel = n >> 10, hh = (n & 1023) >> 6, d0 = n & 63;
                    f16* dst = (sel == 0) ? qq : (sel == 1 ? kk : vv);
                    size_t o = ((size_t)(b * NH + hh) * CTX + t) * HS + d0;
                    *(uint32_t*)(dst + o) = pack2h(v0, v1);
                } else if (MODE == 1) {
                    float s0 = (v0 + bn0) * ASCALE;
                    float s1 = (v1 + bn1) * ASCALE;
                    size_t o = (size_t)m * N + n;
                    *(uint32_t*)(out_hi + o) = pack2h(s0, s1);
                } else {
                    v0 = fmaxf(v0 + bn0, 0.f);
                    v1 = fmaxf(v1 + bn1, 0.f);
                    *(float2*)(out_f + (size_t)m * N + n) = make_float2(v0, v1);
                }
            }
        }
    }
}

// ================= mma.sync causal flash attention (single fp16, exp2 softmax) =================
// QK: Q * K (1 MMA pass); PV: P * V (1 MMA pass). fp32 accum.
// 128 queries/CTA, 8 warps x 16 rows; Bc=64 key tile; double-buffered K/V.
// Single barrier per K-tile. V stored [T,D]; PV B-fragments via ldmatrix.trans.
// Epilogue writes fp16 x256 for FFN1's A operand. Occupancy 2.
#define PADB   144
#define QTILE  (128*PADB)       // 18432
#define KVTILE (64*PADB)        // 9216
#define ASTAGE (2*KVTILE)       // 18432
#define ATTN_SMEM (QTILE + 2*ASTAGE)   // 55296

__global__ __launch_bounds__(256, 2)
void attn_mma()
{
    extern __shared__ char smem[];
    uint32_t sb = smem_u32(smem);
    int tid = threadIdx.x, wid = tid >> 5, lid = tid & 31;
    int qt = blockIdx.x, h = blockIdx.y, b = blockIdx.z;
    int q0 = qt * 128;
    int wm = wid;
    int g = lid >> 3, rr = lid & 7;
    uint32_t a_off = (uint32_t)(((g & 1) * 8 + rr) * PADB + (g >> 1) * 16);
    uint32_t b_off = (uint32_t)(((g >> 1) * 8 + rr) * PADB + (g & 1) * 16);
    int t4 = lid >> 2, t2 = lid & 3;

    size_t hb = (size_t)(b * NH + h);
    const f16* qB = g_q16 + hb * CTX * HS;
    const f16* kB = g_k16 + hb * CTX * HS;
    const f16* vB = g_v16 + hb * CTX * HS;

    // Q tile (128 x 64)
#pragma unroll
    for (int i = 0; i < 4; i++) {
        int idx = tid + i * 256;
        int r = idx >> 3, ch = idx & 7;
        cp16(sb + (uint32_t)(r * PADB + ch * 16), qB + (size_t)(q0 + r) * HS + ch * 8);
    }
    CP_COMMIT();

#define LOAD_TILE(st, kb_) do {                                            \
        uint32_t bs = sb + QTILE + (st) * ASTAGE;                          \
        for (int i_ = 0; i_ < 2; i_++) {                                   \
            int idx_ = tid + i_ * 256;                                     \
            int r_ = idx_ >> 3, ch_ = idx_ & 7;                            \
            uint32_t so_ = (uint32_t)(r_ * PADB + ch_ * 16);               \
            size_t kg_ = (size_t)((kb_) + r_) * HS + ch_ * 8;              \
            cp16(bs + so_, kB + kg_);                                      \
            cp16(bs + KVTILE + so_, vB + kg_);                             \
        } } while (0)

    LOAD_TILE(0, 0);
    CP_COMMIT();

    uint32_t qf[4][4];
    float of[8][4];
#pragma unroll
    for (int i = 0; i < 8; i++)
#pragma unroll
        for (int j = 0; j < 4; j++) of[i][j] = 0.f;
    float m0 = -1e30f, m1 = -1e30f, l0 = 0.f, l1 = 0.f;
    bool qload = false;

    int nkt = 2 * qt + 2;
    for (int kt = 0; kt < nkt; kt++) {
        int kb = kt * 64;
        CP_WAIT(0);                 // Q + tile kt resident
        __syncthreads();            // all warps done with stage kt-1 (aliased by kt+1)
        if (kt + 1 < nkt) { LOAD_TILE((kt + 1) & 1, kb + 64); CP_COMMIT(); }
        if (!qload) {
#pragma unroll
            for (int ks = 0; ks < 4; ks++)
                ldm4(qf[ks], sb + (uint32_t)((wm * 16) * PADB + ks * 32) + a_off);
            qload = true;
        }
        if (q0 + wm * 16 + 15 >= kb) {
            uint32_t base = sb + QTILE + (kt & 1) * ASTAGE;
            float sf[8][4];
#pragma unroll
            for (int i = 0; i < 8; i++)
#pragma unroll
                for (int j = 0; j < 4; j++) sf[i][j] = 0.f;

#pragma unroll
            for (int ks = 0; ks < 4; ks++) {
                uint32_t bh[4][4];
#pragma unroll
                for (int p = 0; p < 4; p++)
                    ldm4(bh[p], base + (uint32_t)((p * 16) * PADB + ks * 32) + b_off);
#pragma unroll
                for (int ni = 0; ni < 8; ni++)
                    mma_f16(sf[ni], qf[ks], &bh[ni >> 1][(ni & 1) * 2]);
            }

            int row0 = q0 + wm * 16 + t4, row1 = row0 + 8;
            bool needm = (kb + 63 > q0 + wm * 16);
            float mx0 = -1e30f, mx1 = -1e30f;
#pragma unroll
            for (int ni = 0; ni < 8; ni++) {
                int c = kb + ni * 8 + t2 * 2;
                float s0 = sf[ni][0] * SCLQK, s1 = sf[ni][1] * SCLQK;
                float s2 = sf[ni][2] * SCLQK, s3 = sf[ni][3] * SCLQK;
                if (needm) {
                    if (c > row0)     s0 = -1e30f;
                    if (c + 1 > row0) s1 = -1e30f;
                    if (c > row1)     s2 = -1e30f;
                    if (c + 1 > row1) s3 = -1e30f;
                }
                sf[ni][0] = s0; sf[ni][1] = s1; sf[ni][2] = s2; sf[ni][3] = s3;
                mx0 = fmaxf(mx0, fmaxf(s0, s1));
                mx1 = fmaxf(mx1, fmaxf(s2, s3));
            }
            mx0 = fmaxf(mx0, __shfl_xor_sync(0xffffffffu, mx0, 1));
            mx0 = fmaxf(mx0, __shfl_xor_sync(0xffffffffu, mx0, 2));
            mx1 = fmaxf(mx1, __shfl_xor_sync(0xffffffffu, mx1, 1));
            mx1 = fmaxf(mx1, __shfl_xor_sync(0xffffffffu, mx1, 2));
            float nm0 = fmaxf(m0, mx0), nm1 = fmaxf(m1, mx1);
            float cr0 = exp2f(m0 - nm0), cr1 = exp2f(m1 - nm1);
            m0 = nm0; m1 = nm1;
            l0 *= cr0; l1 *= cr1;
#pragma unroll
            for (int ni = 0; ni < 8; ni++) {
                float p0 = exp2f(sf[ni][0] - m0), p1 = exp2f(sf[ni][1] - m0);
                float p2 = exp2f(sf[ni][2] - m1), p3 = exp2f(sf[ni][3] - m1);
                sf[ni][0] = p0; sf[ni][1] = p1; sf[ni][2] = p2; sf[ni][3] = p3;
                l0 += p0 + p1; l1 += p2 + p3;
                of[ni][0] *= cr0; of[ni][1] *= cr0; of[ni][2] *= cr1; of[ni][3] *= cr1;
            }

#pragma unroll
            for (int ks2 = 0; ks2 < 4; ks2++) {
                int n0b = 2 * ks2, n1b = n0b + 1;
                uint32_t pah[4];
                pah[0] = pack2h(sf[n0b][0], sf[n0b][1]);
                pah[1] = pack2h(sf[n0b][2], sf[n0b][3]);
                pah[2] = pack2h(sf[n1b][0], sf[n1b][1]);
                pah[3] = pack2h(sf[n1b][2], sf[n1b][3]);
                uint32_t vh[4][4];
#pragma unroll
                for (int p = 0; p < 4; p++)
                    ldm4t(vh[p], base + KVTILE + (uint32_t)((ks2 * 16) * PADB + p * 32) + a_off);
#pragma unroll
                for (int ni = 0; ni < 8; ni++)
                    mma_f16(of[ni], pah, &vh[ni >> 1][(ni & 1) * 2]);
            }
        }
    }
#undef LOAD_TILE

    l0 += __shfl_xor_sync(0xffffffffu, l0, 1);
    l0 += __shfl_xor_sync(0xffffffffu, l0, 2);
    l1 += __shfl_xor_sync(0xffffffffu, l1, 1);
    l1 += __shfl_xor_sync(0xffffffffu, l1, 2);
    float inv0 = ASCALE / l0, inv1 = ASCALE / l1;   // fold x256 A-scale into normalize

    int row0 = q0 + wm * 16 + t4;
#pragma unroll
    for (int ni = 0; ni < 8; ni++) {
        int col = h * HS + ni * 8 + t2 * 2;
        float s0 = of[ni][0] * inv0, s1 = of[ni][1] * inv0;
        float s2 = of[ni][2] * inv1, s3 = of[ni][3] * inv1;
        size_t o0 = ((size_t)(b * CTX) + row0) * DM + col;
        size_t o1 = o0 + (size_t)8 * DM;
        *(uint32_t*)(g_a16h + o0) = pack2h(s0, s1);
        *(uint32_t*)(g_a16h + o1) = pack2h(s2, s3);
    }
}

// ================= launch =================
extern "C" void kernel_launch(void* const* d_in, const int* in_sizes, int n_in,
                              void* d_out, int out_size)
{
    const float* x  = (const float*)d_in[0];
    const float* Wq = (const float*)d_in[1];
    const float* Wk = (const float*)d_in[2];
    const float* Wv = (const float*)d_in[3];
    const float* W1 = (const float*)d_in[4];
    const float* b1 = (const float*)d_in[5];
    const float* W2 = (const float*)d_in[6];
    const float* b2 = (const float*)d_in[7];
    float* out = (float*)d_out;

    f16 *q16, *k16, *v16;
    f16 *x16h, *a16h, *h16h, *bq16, *w116, *w216;
    cudaGetSymbolAddress((void**)&q16, g_q16);
    cudaGetSymbolAddress((void**)&k16, g_k16);
    cudaGetSymbolAddress((void**)&v16, g_v16);
    cudaGetSymbolAddress((void**)&x16h, g_x16h);
    cudaGetSymbolAddress((void**)&a16h, g_a16h);
    cudaGetSymbolAddress((void**)&h16h, g_h16h);
    cudaGetSymbolAddress((void**)&bq16, g_bq16);
    cudaGetSymbolAddress((void**)&w116, g_w116);
    cudaGetSymbolAddress((void**)&w216, g_w216);

    cudaFuncSetAttribute((const void*)gemm_f16<0>, cudaFuncAttributeMaxDynamicSharedMemorySize, GEMM_SMEM);
    cudaFuncSetAttribute((const void*)gemm_f16<1>, cudaFuncAttributeMaxDynamicSharedMemorySize, GEMM_SMEM);
    cudaFuncSetAttribute((const void*)gemm_f16<2>, cudaFuncAttributeMaxDynamicSharedMemorySize, GEMM_SMEM);
    cudaFuncSetAttribute(attn_mma, cudaFuncAttributeMaxDynamicSharedMemorySize, ATTN_SMEM);

    // input conversions
    conv_x_kernel<<<(size_t)MTOT * NEMB / 1024, 256>>>(x, x16h);
    qkv_transpose_h<<<dim3(NEMB / 32, HS / 32, 48), dim3(32, 8)>>>(Wq, Wk, Wv, bq16);
    transpose_h<<<dim3(FF / 32, DM / 32), dim3(32, 8)>>>(W1, w116, DM, FF);
    transpose_h<<<dim3(DM / 32, FF / 32), dim3(32, 8)>>>(W2, w216, FF, DM);

    // QKV: [8192,1024] @ [1024,3072] -> q/k/v single fp16 [B,H,T,D]
    gemm_f16<0><<<dim3(3 * DM / 256, MTOT / 128), 256, GEMM_SMEM>>>(
        x16h, bq16, nullptr,
        nullptr, nullptr,
        q16, k16, v16, 3 * DM, NEMB);

    // attention -> att fp16 x256
    attn_mma<<<dim3(CTX / 128, NH, BATCH), 256, ATTN_SMEM>>>();

    // FFN1: [8192,1024] @ [1024,4096] + b1 -> h fp16 x256
    gemm_f16<1><<<dim3(FF / 256, MTOT / 128), 256, GEMM_SMEM>>>(
        a16h, w116, b1,
        nullptr, h16h,
        nullptr, nullptr, nullptr, FF, DM);

    // FFN2: [8192,4096] @ [4096,1024] + b2, relu -> out
    gemm_f16<2><<<dim3(DM / 256, MTOT / 128), 256, GEMM_SMEM>>>(
        h16h, w216, b2,
        out, nullptr,
        nullptr, nullptr, nullptr, DM, FF);
}

// round 15
// speedup vs baseline: 3.5281x; 1.0066x over previous
#include <cuda_runtime.h>
#include <cuda_bf16.h>
#include <cuda_fp16.h>
#include <cstdint>

#define BATCH 4
#define CTX   2048
#define NEMB  1024
#define NH    16
#define HS    64
#define DM    1024
#define FF    4096
#define MTOT  (BATCH*CTX)   // 8192

typedef __half f16;

// ================= scratch =================
__device__ f16 g_q16[(size_t)BATCH*NH*CTX*HS];
__device__ f16 g_k16[(size_t)BATCH*NH*CTX*HS];
__device__ f16 g_v16[(size_t)BATCH*NH*CTX*HS];
__device__ f16 g_x16h[(size_t)MTOT*NEMB];
__device__ f16 g_a16h[(size_t)MTOT*DM];
__device__ f16 g_h16h[(size_t)MTOT*FF];
__device__ f16 g_bq16[(size_t)3*DM*NEMB];
__device__ f16 g_w116[(size_t)FF*DM];
__device__ f16 g_w216[(size_t)DM*FF];

#define ASCALE 256.f
#define INVASC (1.f/256.f)
#define SCLQK  0.180336884f   // 0.125 * log2(e)

__device__ __forceinline__ uint32_t pack2h(float a, float b) {
    __half2 p = __floats2half2_rn(a, b);
    return *reinterpret_cast<uint32_t*>(&p);
}
__device__ __forceinline__ uint32_t smem_u32(const void* p) {
    uint32_t a;
    asm("{ .reg .u64 t; cvta.to.shared.u64 t, %1; cvt.u32.u64 %0, t; }" : "=r"(a) : "l"(p));
    return a;
}
__device__ __forceinline__ void cp16(uint32_t dst, const void* src) {
    asm volatile("cp.async.cg.shared.global [%0], [%1], 16;" :: "r"(dst), "l"(src));
}
#define CP_COMMIT() asm volatile("cp.async.commit_group;" ::: "memory")
#define CP_WAIT(n)  asm volatile("cp.async.wait_group %0;" :: "n"(n) : "memory")

__device__ __forceinline__ void ldm4(uint32_t* r, uint32_t addr) {
    asm volatile("ldmatrix.sync.aligned.m8n8.x4.shared.b16 {%0,%1,%2,%3}, [%4];"
        : "=r"(r[0]), "=r"(r[1]), "=r"(r[2]), "=r"(r[3]) : "r"(addr));
}
__device__ __forceinline__ void ldm4t(uint32_t* r, uint32_t addr) {
    asm volatile("ldmatrix.sync.aligned.m8n8.x4.trans.shared.b16 {%0,%1,%2,%3}, [%4];"
        : "=r"(r[0]), "=r"(r[1]), "=r"(r[2]), "=r"(r[3]) : "r"(addr));
}
__device__ __forceinline__ void mma_f16(float* d, const uint32_t* a, const uint32_t* b) {
    asm volatile("mma.sync.aligned.m16n8k16.row.col.f32.f16.f16.f32 "
        "{%0,%1,%2,%3}, {%4,%5,%6,%7}, {%8,%9}, {%0,%1,%2,%3};"
        : "+f"(d[0]), "+f"(d[1]), "+f"(d[2]), "+f"(d[3])
        : "r"(a[0]), "r"(a[1]), "r"(a[2]), "r"(a[3]), "r"(b[0]), "r"(b[1]));
}

// ================= convert / transpose kernels =================
__global__ __launch_bounds__(256) void conv_x_kernel(const float* __restrict__ x,
                                                     f16* __restrict__ hi)
{
    size_t i = (size_t)blockIdx.x * 256 + threadIdx.x;
    float4 v = ((const float4*)x)[i];
    ((uint2*)hi)[i] = make_uint2(pack2h(v.x * ASCALE, v.y * ASCALE),
                                 pack2h(v.z * ASCALE, v.w * ASCALE));
}

__global__ __launch_bounds__(256) void transpose_h(const float* __restrict__ W,
                                                   f16* __restrict__ out, int K, int N)
{
    __shared__ float t[32][33];
    int n0 = blockIdx.x * 32, k0 = blockIdx.y * 32;
    int tx = threadIdx.x, ty = threadIdx.y;
#pragma unroll
    for (int i = ty; i < 32; i += 8)
        t[i][tx] = W[(size_t)(k0 + i) * N + n0 + tx];
    __syncthreads();
#pragma unroll
    for (int i = ty; i < 32; i += 8)
        out[(size_t)(n0 + i) * K + k0 + tx] = __float2half_rn(t[tx][i]);
}

__global__ __launch_bounds__(256) void qkv_transpose_h(const float* __restrict__ Wq,
                                                       const float* __restrict__ Wk,
                                                       const float* __restrict__ Wv,
                                                       f16* __restrict__ out)
{
    __shared__ float t[32][33];
    int sel = blockIdx.z >> 4, h = blockIdx.z & 15;
    const float* W = (sel == 0 ? Wq : sel == 1 ? Wk : Wv) + (size_t)h * NEMB * HS;
    int c0 = blockIdx.x * 32, d0 = blockIdx.y * 32;
    int tx = threadIdx.x, ty = threadIdx.y;
#pragma unroll
    for (int i = ty; i < 32; i += 8)
        t[i][tx] = W[(size_t)(c0 + i) * HS + d0 + tx];
    __syncthreads();
    int nbase = sel * DM + h * HS + d0;
#pragma unroll
    for (int i = ty; i < 32; i += 8)
        out[(size_t)(nbase + i) * NEMB + c0 + tx] = __float2half_rn(t[tx][i]);
}

// ================= single-fp16 GEMM, 128x256 CTA tile, BK=128, 2-stage =================
// D = Ah * Bh, A pre-scaled x256, rescale 1/256 in epilogue.
// MODE 0: scatter -> q/k/v single fp16, [B,H,T,D]
// MODE 1: +bias, write fp16 x256 (FFN1 -> h)
// MODE 2: +bias, relu, write fp32 (FFN2 -> out)
#define ROWB    272           // 128 fp16 = 256B + 16B pad (stride 17 chunks, conflict-free)
#define TA      (128*ROWB)    // 34816
#define TBL     (256*ROWB)    // 69632
#define OFF_BH  (TA)
#define STAGE_B (TA + TBL)    // 104448
#define NSTAGE  2
#define GEMM_SMEM (NSTAGE*STAGE_B)   // 208896

template <int MODE>
__global__ __launch_bounds__(256, 1)
void gemm_f16(const f16* __restrict__ Ahi,
              const f16* __restrict__ Bh,
              const float* __restrict__ bias,
              float* __restrict__ out_f, f16* __restrict__ out_hi,
              f16* __restrict__ qq, f16* __restrict__ kk, f16* __restrict__ vv,
              int N, int K)
{
    extern __shared__ char smem[];
    uint32_t sb = smem_u32(smem);

    int tid = threadIdx.x, wid = tid >> 5, lid = tid & 31;
    int wm = wid >> 2, wn = wid & 3;          // warp tile 64(M) x 64(N)
    int bx = blockIdx.x, by = blockIdx.y;

    const f16* aH = Ahi + (size_t)by * 128 * K;
    const f16* bH = Bh + (size_t)bx * 256 * K;

    float acc[4][8][4];
#pragma unroll
    for (int i = 0; i < 4; i++)
#pragma unroll
        for (int j = 0; j < 8; j++)
#pragma unroll
            for (int l = 0; l < 4; l++) acc[i][j][l] = 0.f;

    int ITERS = K >> 7;

#define ISSUE(st, k0) do {                                                         \
        uint32_t _b = sb + (st) * STAGE_B;                                         \
        _Pragma("unroll")                                                          \
        for (int _i = 0; _i < 8; _i++) {                                           \
            int _c = tid + _i * 256; int _r = _c >> 4, _q = _c & 15;               \
            cp16(_b + (uint32_t)(_r * ROWB + _q * 16),                             \
                 aH + (size_t)_r * K + (k0) + _q * 8);                             \
        }                                                                          \
        _Pragma("unroll")                                                          \
        for (int _i = 0; _i < 16; _i++) {                                          \
            int _c = tid + _i * 256; int _r = _c >> 4, _q = _c & 15;               \
            cp16(_b + OFF_BH + (uint32_t)(_r * ROWB + _q * 16),                    \
                 bH + (size_t)_r * K + (k0) + _q * 8);                             \
        }                                                                          \
    } while (0)

    ISSUE(0, 0); CP_COMMIT();

    int g = lid >> 3, rr = lid & 7;
    uint32_t a_row_off = (uint32_t)(((g & 1) * 8 + rr) * ROWB + (g >> 1) * 16);
    uint32_t b_row_off = (uint32_t)(((g >> 1) * 8 + rr) * ROWB + (g & 1) * 16);

    for (int it = 0; it < ITERS; it++) {
        CP_WAIT(0);                 // stage it resident
        __syncthreads();            // all warps done with the other stage
        if (it + 1 < ITERS) { ISSUE((it + 1) & 1, (it + 1) * 128); CP_COMMIT(); }

        uint32_t base = sb + (it & 1) * STAGE_B;
#pragma unroll
        for (int ks = 0; ks < 8; ks++) {
            uint32_t ah[4][4], bh[4][4];
#pragma unroll
            for (int mi = 0; mi < 4; mi++)
                ldm4(ah[mi], base + (uint32_t)((wm * 64 + mi * 16) * ROWB + ks * 32) + a_row_off);
#pragma unroll
            for (int p = 0; p < 4; p++)
                ldm4(bh[p], base + OFF_BH + (uint32_t)((wn * 64 + p * 16) * ROWB + ks * 32) + b_row_off);
#pragma unroll
            for (int mi = 0; mi < 4; mi++)
#pragma unroll
                for (int ni = 0; ni < 8; ni++)
                    mma_f16(acc[mi][ni], ah[mi], &bh[ni >> 1][(ni & 1) * 2]);
        }
    }
#undef ISSUE

    // ---------------- epilogue (rescale 1/256) ----------------
    int t4 = lid >> 2, t2 = (lid & 3) * 2;
#pragma unroll
    for (int mi = 0; mi < 4; mi++) {
#pragma unroll
        for (int ni = 0; ni < 8; ni++) {
            int n = bx * 256 + wn * 64 + ni * 8 + t2;
            int m0 = by * 128 + wm * 64 + mi * 16 + t4;
            float bn0 = 0.f, bn1 = 0.f;
            if (MODE != 0) { bn0 = bias[n]; bn1 = bias[n + 1]; }
#pragma unroll
            for (int half = 0; half < 2; half++) {
                int m = m0 + half * 8;
                float v0 = acc[mi][ni][half * 2]     * INVASC;
                float v1 = acc[mi][ni][half * 2 + 1] * INVASC;
                if (MODE == 0) {
                    int b = m >> 11, t = m & (CTX - 1);
                    int sel = n >> 10, hh = (n & 1023) >> 6, d0 = n & 63;
                    f16* dst = (sel == 0) ? qq : (sel == 1 ? kk : vv);
                    size_t o = ((size_t)(b * NH + hh) * CTX + t) * HS + d0;
                    *(uint32_t*)(dst + o) = pack2h(v0, v1);
                } else if (MODE == 1) {
                    float s0 = (v0 + bn0) * ASCALE;
                    float s1 = (v1 + bn1) * ASCALE;
                    size_t o = (size_t)m * N + n;
                    *(uint32_t*)(out_hi + o) = pack2h(s0, s1);
                } else {
                    v0 = fmaxf(v0 + bn0, 0.f);
                    v1 = fmaxf(v1 + bn1, 0.f);
                    *(float2*)(out_f + (size_t)m * N + n) = make_float2(v0, v1);
                }
            }
        }
    }
}

// ================= mma.sync causal flash attention (single fp16, exp2 softmax) =================
// QK: Q * K (1 MMA pass); PV: P * V (1 MMA pass). fp32 accum.
// 128 queries/CTA, 8 warps x 16 rows; Bc=64 key tile; double-buffered K/V.
// Single barrier per K-tile. V stored [T,D]; PV B-fragments via ldmatrix.trans.
// Epilogue writes fp16 x256 for FFN1's A operand. Occupancy 2.
#define PADB   144
#define QTILE  (128*PADB)       // 18432
#define KVTILE (64*PADB)        // 9216
#define ASTAGE (2*KVTILE)       // 18432
#define ATTN_SMEM (QTILE + 2*ASTAGE)   // 55296

__global__ __launch_bounds__(256, 2)
void attn_mma()
{
    extern __shared__ char smem[];
    uint32_t sb = smem_u32(smem);
    int tid = threadIdx.x, wid = tid >> 5, lid = tid & 31;
    int qt = blockIdx.x, h = blockIdx.y, b = blockIdx.z;
    int q0 = qt * 128;
    int wm = wid;
    int g = lid >> 3, rr = lid & 7;
    uint32_t a_off = (uint32_t)(((g & 1) * 8 + rr) * PADB + (g >> 1) * 16);
    uint32_t b_off = (uint32_t)(((g >> 1) * 8 + rr) * PADB + (g & 1) * 16);
    int t4 = lid >> 2, t2 = lid & 3;

    size_t hb = (size_t)(b * NH + h);
    const f16* qB = g_q16 + hb * CTX * HS;
    const f16* kB = g_k16 + hb * CTX * HS;
    const f16* vB = g_v16 + hb * CTX * HS;

    // Q tile (128 x 64)
#pragma unroll
    for (int i = 0; i < 4; i++) {
        int idx = tid + i * 256;
        int r = idx >> 3, ch = idx & 7;
        cp16(sb + (uint32_t)(r * PADB + ch * 16), qB + (size_t)(q0 + r) * HS + ch * 8);
    }
    CP_COMMIT();

#define LOAD_TILE(st, kb_) do {                                            \
        uint32_t bs = sb + QTILE + (st) * ASTAGE;                          \
        for (int i_ = 0; i_ < 2; i_++) {                                   \
            int idx_ = tid + i_ * 256;                                     \
            int r_ = idx_ >> 3, ch_ = idx_ & 7;                            \
            uint32_t so_ = (uint32_t)(r_ * PADB + ch_ * 16);               \
            size_t kg_ = (size_t)((kb_) + r_) * HS + ch_ * 8;              \
            cp16(bs + so_, kB + kg_);                                      \
            cp16(bs + KVTILE + so_, vB + kg_);                             \
        } } while (0)

    LOAD_TILE(0, 0);
    CP_COMMIT();

    uint32_t qf[4][4];
    float of[8][4];
#pragma unroll
    for (int i = 0; i < 8; i++)
#pragma unroll
        for (int j = 0; j < 4; j++) of[i][j] = 0.f;
    float m0 = -1e30f, m1 = -1e30f, l0 = 0.f, l1 = 0.f;
    bool qload = false;

    int nkt = 2 * qt + 2;
    for (int kt = 0; kt < nkt; kt++) {
        int kb = kt * 64;
        CP_WAIT(0);                 // Q + tile kt resident
        __syncthreads();            // all warps done with stage kt-1 (aliased by kt+1)
        if (kt + 1 < nkt) { LOAD_TILE((kt + 1) & 1, kb + 64); CP_COMMIT(); }
        if (!qload) {
#pragma unroll
            for (int ks = 0; ks < 4; ks++)
                ldm4(qf[ks], sb + (uint32_t)((wm * 16) * PADB + ks * 32) + a_off);
            qload = true;
        }
        if (q0 + wm * 16 + 15 >= kb) {
            uint32_t base = sb + QTILE + (kt & 1) * ASTAGE;
            float sf[8][4];
#pragma unroll
            for (int i = 0; i < 8; i++)
#pragma unroll
                for (int j = 0; j < 4; j++) sf[i][j] = 0.f;

#pragma unroll
            for (int ks = 0; ks < 4; ks++) {
                uint32_t bh[4][4];
#pragma unroll
                for (int p = 0; p < 4; p++)
                    ldm4(bh[p], base + (uint32_t)((p * 16) * PADB + ks * 32) + b_off);
#pragma unroll
                for (int ni = 0; ni < 8; ni++)
                    mma_f16(sf[ni], qf[ks], &bh[ni >> 1][(ni & 1) * 2]);
            }

            int row0 = q0 + wm * 16 + t4, row1 = row0 + 8;
            bool needm = (kb + 63 > q0 + wm * 16);
            float mx0 = -1e30f, mx1 = -1e30f;
#pragma unroll
            for (int ni = 0; ni < 8; ni++) {
                int c = kb + ni * 8 + t2 * 2;
                float s0 = sf[ni][0] * SCLQK, s1 = sf[ni][1] * SCLQK;
                float s2 = sf[ni][2] * SCLQK, s3 = sf[ni][3] * SCLQK;
                if (needm) {
                    if (c > row0)     s0 = -1e30f;
                    if (c + 1 > row0) s1 = -1e30f;
                    if (c > row1)     s2 = -1e30f;
                    if (c + 1 > row1) s3 = -1e30f;
                }
                sf[ni][0] = s0; sf[ni][1] = s1; sf[ni][2] = s2; sf[ni][3] = s3;
                mx0 = fmaxf(mx0, fmaxf(s0, s1));
                mx1 = fmaxf(mx1, fmaxf(s2, s3));
            }
            mx0 = fmaxf(mx0, __shfl_xor_sync(0xffffffffu, mx0, 1));
            mx0 = fmaxf(mx0, __shfl_xor_sync(0xffffffffu, mx0, 2));
            mx1 = fmaxf(mx1, __shfl_xor_sync(0xffffffffu, mx1, 1));
            mx1 = fmaxf(mx1, __shfl_xor_sync(0xffffffffu, mx1, 2));
            float nm0 = fmaxf(m0, mx0), nm1 = fmaxf(m1, mx1);
            float cr0 = exp2f(m0 - nm0), cr1 = exp2f(m1 - nm1);
            m0 = nm0; m1 = nm1;
            l0 *= cr0; l1 *= cr1;
#pragma unroll
            for (int ni = 0; ni < 8; ni++) {
                float p0 = exp2f(sf[ni][0] - m0), p1 = exp2f(sf[ni][1] - m0);
                float p2 = exp2f(sf[ni][2] - m1), p3 = exp2f(sf[ni][3] - m1);
                sf[ni][0] = p0; sf[ni][1] = p1; sf[ni][2] = p2; sf[ni][3] = p3;
                l0 += p0 + p1; l1 += p2 + p3;
                of[ni][0] *= cr0; of[ni][1] *= cr0; of[ni][2] *= cr1; of[ni][3] *= cr1;
            }

#pragma unroll
            for (int ks2 = 0; ks2 < 4; ks2++) {
                int n0b = 2 * ks2, n1b = n0b + 1;
                uint32_t pah[4];
                pah[0] = pack2h(sf[n0b][0], sf[n0b][1]);
                pah[1] = pack2h(sf[n0b][2], sf[n0b][3]);
                pah[2] = pack2h(sf[n1b][0], sf[n1b][1]);
                pah[3] = pack2h(sf[n1b][2], sf[n1b][3]);
                uint32_t vh[4][4];
#pragma unroll
                for (int p = 0; p < 4; p++)
                    ldm4t(vh[p], base + KVTILE + (uint32_t)((ks2 * 16) * PADB + p * 32) + a_off);
#pragma unroll
                for (int ni = 0; ni < 8; ni++)
                    mma_f16(of[ni], pah, &vh[ni >> 1][(ni & 1) * 2]);
            }
        }
    }
#undef LOAD_TILE

    l0 += __shfl_xor_sync(0xffffffffu, l0, 1);
    l0 += __shfl_xor_sync(0xffffffffu, l0, 2);
    l1 += __shfl_xor_sync(0xffffffffu, l1, 1);
    l1 += __shfl_xor_sync(0xffffffffu, l1, 2);
    float inv0 = ASCALE / l0, inv1 = ASCALE / l1;   // fold x256 A-scale into normalize

    int row0 = q0 + wm * 16 + t4;
#pragma unroll
    for (int ni = 0; ni < 8; ni++) {
        int col = h * HS + ni * 8 + t2 * 2;
        float s0 = of[ni][0] * inv0, s1 = of[ni][1] * inv0;
        float s2 = of[ni][2] * inv1, s3 = of[ni][3] * inv1;
        size_t o0 = ((size_t)(b * CTX) + row0) * DM + col;
        size_t o1 = o0 + (size_t)8 * DM;
        *(uint32_t*)(g_a16h + o0) = pack2h(s0, s1);
        *(uint32_t*)(g_a16h + o1) = pack2h(s2, s3);
    }
}

// ================= launch =================
extern "C" void kernel_launch(void* const* d_in, const int* in_sizes, int n_in,
                              void* d_out, int out_size)
{
    const float* x  = (const float*)d_in[0];
    const float* Wq = (const float*)d_in[1];
    const float* Wk = (const float*)d_in[2];
    const float* Wv = (const float*)d_in[3];
    const float* W1 = (const float*)d_in[4];
    const float* b1 = (const float*)d_in[5];
    const float* W2 = (const float*)d_in[6];
    const float* b2 = (const float*)d_in[7];
    float* out = (float*)d_out;

    f16 *q16, *k16, *v16;
    f16 *x16h, *a16h, *h16h, *bq16, *w116, *w216;
    cudaGetSymbolAddress((void**)&q16, g_q16);
    cudaGetSymbolAddress((void**)&k16, g_k16);
    cudaGetSymbolAddress((void**)&v16, g_v16);
    cudaGetSymbolAddress((void**)&x16h, g_x16h);
    cudaGetSymbolAddress((void**)&a16h, g_a16h);
    cudaGetSymbolAddress((void**)&h16h, g_h16h);
    cudaGetSymbolAddress((void**)&bq16, g_bq16);
    cudaGetSymbolAddress((void**)&w116, g_w116);
    cudaGetSymbolAddress((void**)&w216, g_w216);

    cudaFuncSetAttribute((const void*)gemm_f16<0>, cudaFuncAttributeMaxDynamicSharedMemorySize, GEMM_SMEM);
    cudaFuncSetAttribute((const void*)gemm_f16<1>, cudaFuncAttributeMaxDynamicSharedMemorySize, GEMM_SMEM);
    cudaFuncSetAttribute((const void*)gemm_f16<2>, cudaFuncAttributeMaxDynamicSharedMemorySize, GEMM_SMEM);
    cudaFuncSetAttribute(attn_mma, cudaFuncAttributeMaxDynamicSharedMemorySize, ATTN_SMEM);

    // input conversions
    conv_x_kernel<<<(size_t)MTOT * NEMB / 1024, 256>>>(x, x16h);
    qkv_transpose_h<<<dim3(NEMB / 32, HS / 32, 48), dim3(32, 8)>>>(Wq, Wk, Wv, bq16);
    transpose_h<<<dim3(FF / 32, DM / 32), dim3(32, 8)>>>(W1, w116, DM, FF);
    transpose_h<<<dim3(DM / 32, FF / 32), dim3(32, 8)>>>(W2, w216, FF, DM);

    // QKV: [8192,1024] @ [1024,3072] -> q/k/v single fp16 [B,H,T,D]
    gemm_f16<0><<<dim3(3 * DM / 256, MTOT / 128), 256, GEMM_SMEM>>>(
        x16h, bq16, nullptr,
        nullptr, nullptr,
        q16, k16, v16, 3 * DM, NEMB);

    // attention -> att fp16 x256
    attn_mma<<<dim3(CTX / 128, NH, BATCH), 256, ATTN_SMEM>>>();

    // FFN1: [8192,1024] @ [1024,4096] + b1 -> h fp16 x256
    gemm_f16<1><<<dim3(FF / 256, MTOT / 128), 256, GEMM_SMEM>>>(
        a16h, w116, b1,
        nullptr, h16h,
        nullptr, nullptr, nullptr, FF, DM);

    // FFN2: [8192,4096] @ [4096,1024] + b2, relu -> out
    gemm_f16<2><<<dim3(DM / 256, MTOT / 128), 256, GEMM_SMEM>>>(
        h16h, w216, b2,
        out, nullptr,
        nullptr, nullptr, nullptr, DM, FF);
}